// round 5
// baseline (speedup 1.0000x reference)
#include <cuda_runtime.h>
#include <math.h>

// ---------------------------------------------------------------------------
// Mamba block forward. tf32 mma.sync GEMMs (software-pipelined, double-buffer)
// + chunked parallel selective scan.
//   B=2, L=2048, d_model=1024, d_inner=2048, d_state=16, d_conv=4, dt_rank=64
// NOTE: tcgen05 is unavailable — harness PTX target is compute_103 (no 'a'),
// which gates all tcgen05/TMEM instructions. mma.sync tf32 is the tensor path.
// ---------------------------------------------------------------------------

#define L_SEQ   2048
#define NB      2
#define DMODEL  1024
#define DINNER  2048
#define DSTATE  16
#define NROWS   (NB * L_SEQ)     // 4096
#define XPROJ_N 96
#define KSPLIT  8
#define CHUNK   128
#define NCHUNK  (L_SEQ / CHUNK)  // 16

__device__ float g_xz   [(size_t)NROWS * 2 * DINNER];
__device__ float g_uc   [(size_t)NROWS * DINNER];
__device__ float g_xpart[(size_t)KSPLIT * NROWS * XPROJ_N];
__device__ float g_xdbl [(size_t)NROWS * XPROJ_N];
__device__ float g_delta[(size_t)NROWS * DINNER];
__device__ float g_y    [(size_t)NROWS * DINNER];
__device__ float g_hfin [(size_t)NB * NCHUNK * DSTATE * DINNER];
__device__ float g_hini [(size_t)NB * NCHUNK * DSTATE * DINNER];
__device__ float g_sumd [(size_t)NB * NCHUNK * DINNER];

__device__ __forceinline__ float softplusf(float x) {
    return x > 20.f ? x : log1pf(__expf(x));
}
__device__ __forceinline__ unsigned f2tf32(float f) {
    unsigned u;
    asm("cvt.rna.tf32.f32 %0, %1;" : "=r"(u) : "f"(f));
    return u;
}
__device__ __forceinline__ unsigned smem_u32(const void* p) {
    return (unsigned)__cvta_generic_to_shared(p);
}

// ---------------------------------------------------------------------------
// C[M,N] = A[M,K] @ B[N,K]^T via mma.sync.m16n8k8.tf32.
// 128x128 block tile, BK=32, 256 threads = 8 warps (4m x 2n), warp = 32m x 64n.
// Software pipelined: LDG(t+1) -> regs || MMA(t) ; STS(t+1) ; one sync/iter.
// Dynamic smem: 2 stages x (As + Bs), 128*BST words each.
// ---------------------------------------------------------------------------
#define BK   32
#define BST  36   // BK + 4 pad (ldmatrix conflict-free)
#define MMA_STAGE_WORDS (128 * BST)
#define MMA_SMEM_BYTES  (4 * MMA_STAGE_WORDS * 4)   // 73728

__global__ __launch_bounds__(256)
void mma_tn(const float* __restrict__ A, const float* __restrict__ B,
            float* __restrict__ C, int M, int N, int K,
            int lda, int ldb, int ldc,
            const float* __restrict__ bias, int epi, int kPerSplit)
{
    extern __shared__ __align__(16) unsigned sh[];
    // layout: As0 | Bs0 | As1 | Bs1
    unsigned* const AsBuf[2] = { sh,                      sh + 2 * MMA_STAGE_WORDS };
    unsigned* const BsBuf[2] = { sh + MMA_STAGE_WORDS,    sh + 3 * MMA_STAGE_WORDS };

    const int tid  = threadIdx.x;
    const int lane = tid & 31;
    const int wid  = tid >> 5;
    const int wm0  = (wid >> 1) << 5;   // warp m offset: 0,32,64,96
    const int wn0  = (wid & 1) << 6;    // warp n offset: 0,64

    const int bm = blockIdx.y << 7;
    const int bn = blockIdx.x << 7;
    const int kbeg = blockIdx.z * kPerSplit;
    const int kend = kbeg + kPerSplit;
    C += (size_t)blockIdx.z * (size_t)M * (size_t)ldc;

    float acc[2][8][4];
#pragma unroll
    for (int mt = 0; mt < 2; ++mt)
#pragma unroll
        for (int nt = 0; nt < 8; ++nt)
#pragma unroll
            for (int r = 0; r < 4; ++r) acc[mt][nt][r] = 0.f;

    int a_off[2], b_off[4];
#pragma unroll
    for (int mt = 0; mt < 2; ++mt) {
        int row = wm0 + mt * 16 + ((lane >> 3) & 1) * 8 + (lane & 7);
        int col = (lane >> 4) * 4;
        a_off[mt] = row * BST + col;
    }
#pragma unroll
    for (int bt = 0; bt < 4; ++bt) {
        int row = wn0 + bt * 16 + (lane >> 4) * 8 + (lane & 7);
        int col = ((lane >> 3) & 1) * 4;
        b_off[bt] = row * BST + col;
    }
    const unsigned as_base[2] = { smem_u32(AsBuf[0]), smem_u32(AsBuf[1]) };
    const unsigned bs_base[2] = { smem_u32(BsBuf[0]), smem_u32(BsBuf[1]) };

    const int lrow = tid >> 3;          // 0..31
    const int lc4  = (tid & 7) << 2;    // 0..28

    float4 pa[4], pb[4];
    // ---- prologue: load k-block 0 into regs, store to stage 0 ----
#pragma unroll
    for (int i = 0; i < 4; ++i) {
        int r = lrow + (i << 5);
        pa[i] = *reinterpret_cast<const float4*>(
            A + (size_t)(bm + r) * lda + kbeg + lc4);
        pb[i] = make_float4(0.f, 0.f, 0.f, 0.f);
        if (bn + r < N)
            pb[i] = *reinterpret_cast<const float4*>(
                B + (size_t)(bn + r) * ldb + kbeg + lc4);
    }
#pragma unroll
    for (int i = 0; i < 4; ++i) {
        int r = lrow + (i << 5);
        unsigned* qa = &AsBuf[0][r * BST + lc4];
        qa[0] = f2tf32(pa[i].x); qa[1] = f2tf32(pa[i].y);
        qa[2] = f2tf32(pa[i].z); qa[3] = f2tf32(pa[i].w);
        unsigned* qb = &BsBuf[0][r * BST + lc4];
        qb[0] = f2tf32(pb[i].x); qb[1] = f2tf32(pb[i].y);
        qb[2] = f2tf32(pb[i].z); qb[3] = f2tf32(pb[i].w);
    }
    __syncthreads();

    const int nk = (kend - kbeg) >> 5;
    for (int t = 0; t < nk; ++t) {
        const int cur = t & 1;
        const bool more = (t + 1) < nk;
        // ---- prefetch next k-block into registers (hides DRAM latency) ----
        if (more) {
            const int kn = kbeg + (t + 1) * BK;
#pragma unroll
            for (int i = 0; i < 4; ++i) {
                int r = lrow + (i << 5);
                pa[i] = *reinterpret_cast<const float4*>(
                    A + (size_t)(bm + r) * lda + kn + lc4);
                pb[i] = make_float4(0.f, 0.f, 0.f, 0.f);
                if (bn + r < N)
                    pb[i] = *reinterpret_cast<const float4*>(
                        B + (size_t)(bn + r) * ldb + kn + lc4);
            }
        }
        // ---- compute current stage ----
#pragma unroll
        for (int kk = 0; kk < BK; kk += 8) {
            unsigned a[2][4], b[4][4];
#pragma unroll
            for (int mt = 0; mt < 2; ++mt) {
                unsigned addr = as_base[cur] + (unsigned)((a_off[mt] + kk) << 2);
                asm volatile(
                    "ldmatrix.sync.aligned.m8n8.x4.shared.b16 {%0,%1,%2,%3}, [%4];"
                    : "=r"(a[mt][0]), "=r"(a[mt][1]), "=r"(a[mt][2]), "=r"(a[mt][3])
                    : "r"(addr));
            }
#pragma unroll
            for (int bt = 0; bt < 4; ++bt) {
                unsigned addr = bs_base[cur] + (unsigned)((b_off[bt] + kk) << 2);
                asm volatile(
                    "ldmatrix.sync.aligned.m8n8.x4.shared.b16 {%0,%1,%2,%3}, [%4];"
                    : "=r"(b[bt][0]), "=r"(b[bt][1]), "=r"(b[bt][2]), "=r"(b[bt][3])
                    : "r"(addr));
            }
#pragma unroll
            for (int mt = 0; mt < 2; ++mt)
#pragma unroll
                for (int nt = 0; nt < 8; ++nt) {
                    unsigned b0 = b[nt >> 1][(nt & 1) * 2 + 0];
                    unsigned b1 = b[nt >> 1][(nt & 1) * 2 + 1];
                    asm volatile(
                        "mma.sync.aligned.m16n8k8.row.col.f32.tf32.tf32.f32 "
                        "{%0,%1,%2,%3}, {%4,%5,%6,%7}, {%8,%9}, {%0,%1,%2,%3};"
                        : "+f"(acc[mt][nt][0]), "+f"(acc[mt][nt][1]),
                          "+f"(acc[mt][nt][2]), "+f"(acc[mt][nt][3])
                        : "r"(a[mt][0]), "r"(a[mt][1]), "r"(a[mt][2]), "r"(a[mt][3]),
                          "r"(b0), "r"(b1));
                }
        }
        // ---- store prefetched regs into the other stage ----
        if (more) {
            const int nxt = cur ^ 1;
#pragma unroll
            for (int i = 0; i < 4; ++i) {
                int r = lrow + (i << 5);
                unsigned* qa = &AsBuf[nxt][r * BST + lc4];
                qa[0] = f2tf32(pa[i].x); qa[1] = f2tf32(pa[i].y);
                qa[2] = f2tf32(pa[i].z); qa[3] = f2tf32(pa[i].w);
                unsigned* qb = &BsBuf[nxt][r * BST + lc4];
                qb[0] = f2tf32(pb[i].x); qb[1] = f2tf32(pb[i].y);
                qb[2] = f2tf32(pb[i].z); qb[3] = f2tf32(pb[i].w);
            }
        }
        __syncthreads();
    }

    const int gid = lane >> 2;
    const int tig = lane & 3;
#pragma unroll
    for (int mt = 0; mt < 2; ++mt)
#pragma unroll
        for (int nt = 0; nt < 8; ++nt) {
            int m = bm + wm0 + mt * 16 + gid;
            int n = bn + wn0 + nt * 8 + tig * 2;
            if (n < N) {
                float v0 = acc[mt][nt][0], v1 = acc[mt][nt][1];
                float v2 = acc[mt][nt][2], v3 = acc[mt][nt][3];
                if (epi == 1) {
                    float b0v = bias[n], b1v = bias[n + 1];
                    v0 = softplusf(v0 + b0v); v1 = softplusf(v1 + b1v);
                    v2 = softplusf(v2 + b0v); v3 = softplusf(v3 + b1v);
                }
                *reinterpret_cast<float2*>(C + (size_t)m * ldc + n) =
                    make_float2(v0, v1);
                *reinterpret_cast<float2*>(C + (size_t)(m + 8) * ldc + n) =
                    make_float2(v2, v3);
            }
        }
}

// ---------------------------------------------------------------------------
__global__ __launch_bounds__(256)
void conv_silu_k(const float* __restrict__ xz, const float* __restrict__ w,
                 const float* __restrict__ cb, float* __restrict__ uc)
{
    int idx = blockIdx.x * blockDim.x + threadIdx.x;
    if (idx >= NROWS * DINNER) return;
    int d   = idx & (DINNER - 1);
    int row = idx >> 11;
    int l   = row & (L_SEQ - 1);
    int b   = row >> 11;

    const float4 wv = *reinterpret_cast<const float4*>(w + (size_t)d * 4);
    const float* up = xz + (size_t)b * L_SEQ * (2 * DINNER) + d;
    const size_t S = 2 * DINNER;

    float acc = cb[d] + wv.w * up[(size_t)l * S];
    if (l >= 1) acc += wv.z * up[(size_t)(l - 1) * S];
    if (l >= 2) acc += wv.y * up[(size_t)(l - 2) * S];
    if (l >= 3) acc += wv.x * up[(size_t)(l - 3) * S];

    uc[idx] = acc / (1.f + __expf(-acc));
}

__global__ void reduce_split(const float* __restrict__ part,
                             float* __restrict__ out, int n)
{
    int i = blockIdx.x * blockDim.x + threadIdx.x;
    if (i < n) {
        float s = 0.f;
#pragma unroll
        for (int z = 0; z < KSPLIT; ++z) s += part[(size_t)z * n + i];
        out[i] = s;
    }
}

// ---------------------------------------------------------------------------
// Chunked selective scan (3 phases).
// ---------------------------------------------------------------------------
__global__ __launch_bounds__(256)
void scan_p1(const float* __restrict__ delta, const float* __restrict__ xdbl,
             const float* __restrict__ uc, const float* __restrict__ A_log,
             float* __restrict__ hfin, float* __restrict__ sumd)
{
    const int b = blockIdx.z;
    const int c = blockIdx.y;
    const int d = blockIdx.x * 256 + threadIdx.x;

    float na[DSTATE];
#pragma unroll
    for (int s = 0; s < DSTATE; ++s)
        na[s] = -__expf(A_log[(size_t)d * DSTATE + s]);

    float h[DSTATE];
#pragma unroll
    for (int s = 0; s < DSTATE; ++s) h[s] = 0.f;
    float sd = 0.f;

    __shared__ float bs[32][DSTATE];

    const int lbeg = c * CHUNK;
    for (int l0 = lbeg; l0 < lbeg + CHUNK; l0 += 32) {
        __syncthreads();
        for (int t = threadIdx.x; t < 32 * DSTATE; t += 256) {
            int i = t >> 4, j = t & 15;
            bs[i][j] = xdbl[(size_t)(b * L_SEQ + l0 + i) * XPROJ_N + 64 + j];
        }
        __syncthreads();
#pragma unroll 4
        for (int i = 0; i < 32; ++i) {
            size_t row = (size_t)b * L_SEQ + l0 + i;
            float t  = delta[row * DINNER + d];
            float u  = uc[row * DINNER + d];
            float tu = t * u;
            sd += t;
#pragma unroll
            for (int s = 0; s < DSTATE; ++s) {
                float dA = __expf(t * na[s]);
                h[s] = fmaf(dA, h[s], tu * bs[i][s]);
            }
        }
    }

    const size_t base = ((size_t)(b * NCHUNK + c) * DSTATE) * DINNER + d;
#pragma unroll
    for (int s = 0; s < DSTATE; ++s)
        hfin[base + (size_t)s * DINNER] = h[s];
    sumd[(size_t)(b * NCHUNK + c) * DINNER + d] = sd;
}

__global__ __launch_bounds__(256)
void scan_combine(const float* __restrict__ hfin, const float* __restrict__ sumd,
                  const float* __restrict__ A_log, float* __restrict__ hini)
{
    const int b = blockIdx.y;
    const int d = blockIdx.x * 256 + threadIdx.x;

    float na[DSTATE];
#pragma unroll
    for (int s = 0; s < DSTATE; ++s)
        na[s] = -__expf(A_log[(size_t)d * DSTATE + s]);

    float h[DSTATE];
#pragma unroll
    for (int s = 0; s < DSTATE; ++s) h[s] = 0.f;

    for (int c = 0; c < NCHUNK; ++c) {
        const size_t base = ((size_t)(b * NCHUNK + c) * DSTATE) * DINNER + d;
#pragma unroll
        for (int s = 0; s < DSTATE; ++s)
            hini[base + (size_t)s * DINNER] = h[s];
        float sd = sumd[(size_t)(b * NCHUNK + c) * DINNER + d];
#pragma unroll
        for (int s = 0; s < DSTATE; ++s) {
            float pA = __expf(sd * na[s]);
            h[s] = fmaf(pA, h[s], hfin[base + (size_t)s * DINNER]);
        }
    }
}

__global__ __launch_bounds__(256)
void scan_p3(const float* __restrict__ delta, const float* __restrict__ xdbl,
             const float* __restrict__ uc, const float* __restrict__ xz,
             const float* __restrict__ A_log, const float* __restrict__ Dv,
             const float* __restrict__ hini, float* __restrict__ y)
{
    const int b = blockIdx.z;
    const int c = blockIdx.y;
    const int d = blockIdx.x * 256 + threadIdx.x;

    float na[DSTATE];
#pragma unroll
    for (int s = 0; s < DSTATE; ++s)
        na[s] = -__expf(A_log[(size_t)d * DSTATE + s]);

    float h[DSTATE];
    {
        const size_t base = ((size_t)(b * NCHUNK + c) * DSTATE) * DINNER + d;
#pragma unroll
        for (int s = 0; s < DSTATE; ++s)
            h[s] = hini[base + (size_t)s * DINNER];
    }

    const float Dd = Dv[d];
    __shared__ float bc[32][32];

    const int lbeg = c * CHUNK;
    for (int l0 = lbeg; l0 < lbeg + CHUNK; l0 += 32) {
        __syncthreads();
        for (int t = threadIdx.x; t < 1024; t += 256) {
            int i = t >> 5, j = t & 31;
            bc[i][j] = xdbl[(size_t)(b * L_SEQ + l0 + i) * XPROJ_N + 64 + j];
        }
        __syncthreads();
#pragma unroll 4
        for (int i = 0; i < 32; ++i) {
            size_t row = (size_t)b * L_SEQ + l0 + i;
            float t  = delta[row * DINNER + d];
            float u  = uc[row * DINNER + d];
            float tu = t * u;
            float yv = 0.f;
#pragma unroll
            for (int s = 0; s < DSTATE; ++s) {
                float dA = __expf(t * na[s]);
                h[s] = fmaf(dA, h[s], tu * bc[i][s]);
                yv   = fmaf(h[s], bc[i][16 + s], yv);
            }
            float zv = xz[row * (2 * DINNER) + DINNER + d];
            float g  = zv / (1.f + __expf(-zv));
            y[row * DINNER + d] = (yv + u * Dd) * g;
        }
    }
}

// ---------------------------------------------------------------------------
extern "C" void kernel_launch(void* const* d_in, const int* in_sizes, int n_in,
                              void* d_out, int out_size)
{
    const float* x        = (const float*)d_in[0];
    const float* W_in     = (const float*)d_in[1];
    const float* conv_w   = (const float*)d_in[2];
    const float* conv_b   = (const float*)d_in[3];
    const float* W_xproj  = (const float*)d_in[4];
    const float* W_dtproj = (const float*)d_in[5];
    const float* dt_bias  = (const float*)d_in[6];
    const float* A_log    = (const float*)d_in[7];
    const float* Dv       = (const float*)d_in[8];
    const float* W_out    = (const float*)d_in[9];
    float* out = (float*)d_out;

    float *xz, *uc, *xpart, *xdbl, *delta, *y, *hfin, *hini, *sumd;
    cudaGetSymbolAddress((void**)&xz,    g_xz);
    cudaGetSymbolAddress((void**)&uc,    g_uc);
    cudaGetSymbolAddress((void**)&xpart, g_xpart);
    cudaGetSymbolAddress((void**)&xdbl,  g_xdbl);
    cudaGetSymbolAddress((void**)&delta, g_delta);
    cudaGetSymbolAddress((void**)&y,     g_y);
    cudaGetSymbolAddress((void**)&hfin,  g_hfin);
    cudaGetSymbolAddress((void**)&hini,  g_hini);
    cudaGetSymbolAddress((void**)&sumd,  g_sumd);

    cudaFuncSetAttribute(mma_tn,
        cudaFuncAttributeMaxDynamicSharedMemorySize, MMA_SMEM_BYTES);

    dim3 blk(256);

    // 1. in_proj: xz[4096,4096] = x @ W_in^T  (K=1024)
    mma_tn<<<dim3(32, 32, 1), blk, MMA_SMEM_BYTES>>>(x, W_in, xz,
        NROWS, 2 * DINNER, DMODEL, DMODEL, DMODEL, 2 * DINNER,
        nullptr, 0, DMODEL);

    // 2. depthwise conv + silu
    conv_silu_k<<<(NROWS * DINNER) / 256, blk>>>(xz, conv_w, conv_b, uc);

    // 3. x_proj (split-K x8): x_dbl[4096,96] = u_c @ W_xproj^T (K=2048)
    mma_tn<<<dim3(1, 32, KSPLIT), blk, MMA_SMEM_BYTES>>>(uc, W_xproj, xpart,
        NROWS, XPROJ_N, DINNER, DINNER, DINNER, XPROJ_N,
        nullptr, 0, DINNER / KSPLIT);
    reduce_split<<<(NROWS * XPROJ_N + 255) / 256, blk>>>(
        xpart, xdbl, NROWS * XPROJ_N);

    // 4. dt_proj + softplus: delta[4096,2048] (K=64)
    mma_tn<<<dim3(16, 32, 1), blk, MMA_SMEM_BYTES>>>(xdbl, W_dtproj, delta,
        NROWS, DINNER, 64, XPROJ_N, 64, DINNER,
        dt_bias, 1, 64);

    // 5. chunked selective scan + skip + gate
    scan_p1<<<dim3(DINNER / 256, NCHUNK, NB), blk>>>(
        delta, xdbl, uc, A_log, hfin, sumd);
    scan_combine<<<dim3(DINNER / 256, NB), blk>>>(hfin, sumd, A_log, hini);
    scan_p3<<<dim3(DINNER / 256, NCHUNK, NB), blk>>>(
        delta, xdbl, uc, xz, A_log, Dv, hini, y);

    // 6. out_proj: out[4096,1024] = y @ W_out^T (K=2048)
    mma_tn<<<dim3(8, 32, 1), blk, MMA_SMEM_BYTES>>>(y, W_out, out,
        NROWS, DMODEL, DINNER, DINNER, DINNER, DMODEL,
        nullptr, 0, DINNER);
}

// round 6
// speedup vs baseline: 1.2334x; 1.2334x over previous
#include <cuda_runtime.h>
#include <math.h>

// ---------------------------------------------------------------------------
// Mamba block forward. tf32 mma.sync GEMMs (single smem buffer, occ=2,
// register prefetch of next K-block) + chunked parallel selective scan.
//   B=2, L=2048, d_model=1024, d_inner=2048, d_state=16, d_conv=4, dt_rank=64
// tcgen05 unavailable: harness PTX target is compute_103 (no 'a' suffix).
// ---------------------------------------------------------------------------

#define L_SEQ   2048
#define NB      2
#define DMODEL  1024
#define DINNER  2048
#define DSTATE  16
#define NROWS   (NB * L_SEQ)     // 4096
#define XPROJ_N 96
#define KSPLIT  8
#define CHUNK   128
#define NCHUNK  (L_SEQ / CHUNK)  // 16

__device__ float g_xz   [(size_t)NROWS * 2 * DINNER];
__device__ float g_uc   [(size_t)NROWS * DINNER];
__device__ float g_xpart[(size_t)KSPLIT * NROWS * XPROJ_N];
__device__ float g_xdbl [(size_t)NROWS * XPROJ_N];
__device__ float g_delta[(size_t)NROWS * DINNER];
__device__ float g_y    [(size_t)NROWS * DINNER];
__device__ float g_hfin [(size_t)NB * NCHUNK * DSTATE * DINNER];
__device__ float g_hini [(size_t)NB * NCHUNK * DSTATE * DINNER];
__device__ float g_sumd [(size_t)NB * NCHUNK * DINNER];

__device__ __forceinline__ float softplusf(float x) {
    return x > 20.f ? x : log1pf(__expf(x));
}
__device__ __forceinline__ unsigned f2tf32(float f) {
    unsigned u;
    asm("cvt.rna.tf32.f32 %0, %1;" : "=r"(u) : "f"(f));
    return u;
}
__device__ __forceinline__ unsigned smem_u32(const void* p) {
    return (unsigned)__cvta_generic_to_shared(p);
}

// ---------------------------------------------------------------------------
// C[M,N] = A[M,K] @ B[N,K]^T via mma.sync.m16n8k8.tf32.
// 128x128 tile, BK=32, 256 threads = 8 warps (4m x 2n), warp = 32m x 64n.
// Single smem stage (36.8KB -> 2 CTAs/SM); next K-block prefetched into regs
// before the MMA loop so the global-load latency hides under tensor issue.
// ---------------------------------------------------------------------------
#define BK   32
#define BST  36   // BK + 4 pad (ldmatrix conflict-free)

__global__ __launch_bounds__(256, 2)
void mma_tn(const float* __restrict__ A, const float* __restrict__ B,
            float* __restrict__ C, int M, int N, int K,
            int lda, int ldb, int ldc,
            const float* __restrict__ bias, int epi, int kPerSplit)
{
    __shared__ __align__(16) unsigned As[128 * BST];
    __shared__ __align__(16) unsigned Bs[128 * BST];

    const int tid  = threadIdx.x;
    const int lane = tid & 31;
    const int wid  = tid >> 5;
    const int wm0  = (wid >> 1) << 5;
    const int wn0  = (wid & 1) << 6;

    const int bm = blockIdx.y << 7;
    const int bn = blockIdx.x << 7;
    const int kbeg = blockIdx.z * kPerSplit;
    const int kend = kbeg + kPerSplit;
    C += (size_t)blockIdx.z * (size_t)M * (size_t)ldc;

    float acc[2][8][4];
#pragma unroll
    for (int mt = 0; mt < 2; ++mt)
#pragma unroll
        for (int nt = 0; nt < 8; ++nt)
#pragma unroll
            for (int r = 0; r < 4; ++r) acc[mt][nt][r] = 0.f;

    int a_off[2], b_off[4];
#pragma unroll
    for (int mt = 0; mt < 2; ++mt) {
        int row = wm0 + mt * 16 + ((lane >> 3) & 1) * 8 + (lane & 7);
        int col = (lane >> 4) * 4;
        a_off[mt] = row * BST + col;
    }
#pragma unroll
    for (int bt = 0; bt < 4; ++bt) {
        int row = wn0 + bt * 16 + (lane >> 4) * 8 + (lane & 7);
        int col = ((lane >> 3) & 1) * 4;
        b_off[bt] = row * BST + col;
    }
    const unsigned as_base = smem_u32(As);
    const unsigned bs_base = smem_u32(Bs);

    const int lrow = tid >> 3;          // 0..31
    const int lc4  = (tid & 7) << 2;    // 0..28

    float4 pa[4], pb[4];
    // prologue: load K-block 0 into registers
#pragma unroll
    for (int i = 0; i < 4; ++i) {
        int r = lrow + (i << 5);
        pa[i] = *reinterpret_cast<const float4*>(
            A + (size_t)(bm + r) * lda + kbeg + lc4);
        pb[i] = make_float4(0.f, 0.f, 0.f, 0.f);
        if (bn + r < N)
            pb[i] = *reinterpret_cast<const float4*>(
                B + (size_t)(bn + r) * ldb + kbeg + lc4);
    }

    const int nk = (kend - kbeg) >> 5;
    for (int t = 0; t < nk; ++t) {
        // stage current regs into smem
#pragma unroll
        for (int i = 0; i < 4; ++i) {
            int r = lrow + (i << 5);
            unsigned* qa = &As[r * BST + lc4];
            qa[0] = f2tf32(pa[i].x); qa[1] = f2tf32(pa[i].y);
            qa[2] = f2tf32(pa[i].z); qa[3] = f2tf32(pa[i].w);
            unsigned* qb = &Bs[r * BST + lc4];
            qb[0] = f2tf32(pb[i].x); qb[1] = f2tf32(pb[i].y);
            qb[2] = f2tf32(pb[i].z); qb[3] = f2tf32(pb[i].w);
        }
        __syncthreads();

        // prefetch next K-block into regs (latency hides under MMA below)
        if (t + 1 < nk) {
            const int kn = kbeg + (t + 1) * BK;
#pragma unroll
            for (int i = 0; i < 4; ++i) {
                int r = lrow + (i << 5);
                pa[i] = *reinterpret_cast<const float4*>(
                    A + (size_t)(bm + r) * lda + kn + lc4);
                pb[i] = make_float4(0.f, 0.f, 0.f, 0.f);
                if (bn + r < N)
                    pb[i] = *reinterpret_cast<const float4*>(
                        B + (size_t)(bn + r) * ldb + kn + lc4);
            }
        }

        // compute current block from smem
#pragma unroll
        for (int kk = 0; kk < BK; kk += 8) {
            unsigned a[2][4], b[4][4];
#pragma unroll
            for (int mt = 0; mt < 2; ++mt) {
                unsigned addr = as_base + (unsigned)((a_off[mt] + kk) << 2);
                asm volatile(
                    "ldmatrix.sync.aligned.m8n8.x4.shared.b16 {%0,%1,%2,%3}, [%4];"
                    : "=r"(a[mt][0]), "=r"(a[mt][1]), "=r"(a[mt][2]), "=r"(a[mt][3])
                    : "r"(addr));
            }
#pragma unroll
            for (int bt = 0; bt < 4; ++bt) {
                unsigned addr = bs_base + (unsigned)((b_off[bt] + kk) << 2);
                asm volatile(
                    "ldmatrix.sync.aligned.m8n8.x4.shared.b16 {%0,%1,%2,%3}, [%4];"
                    : "=r"(b[bt][0]), "=r"(b[bt][1]), "=r"(b[bt][2]), "=r"(b[bt][3])
                    : "r"(addr));
            }
#pragma unroll
            for (int mt = 0; mt < 2; ++mt)
#pragma unroll
                for (int nt = 0; nt < 8; ++nt) {
                    unsigned b0 = b[nt >> 1][(nt & 1) * 2 + 0];
                    unsigned b1 = b[nt >> 1][(nt & 1) * 2 + 1];
                    asm volatile(
                        "mma.sync.aligned.m16n8k8.row.col.f32.tf32.tf32.f32 "
                        "{%0,%1,%2,%3}, {%4,%5,%6,%7}, {%8,%9}, {%0,%1,%2,%3};"
                        : "+f"(acc[mt][nt][0]), "+f"(acc[mt][nt][1]),
                          "+f"(acc[mt][nt][2]), "+f"(acc[mt][nt][3])
                        : "r"(a[mt][0]), "r"(a[mt][1]), "r"(a[mt][2]), "r"(a[mt][3]),
                          "r"(b0), "r"(b1));
                }
        }
        __syncthreads();
    }

    const int gid = lane >> 2;
    const int tig = lane & 3;
#pragma unroll
    for (int mt = 0; mt < 2; ++mt)
#pragma unroll
        for (int nt = 0; nt < 8; ++nt) {
            int m = bm + wm0 + mt * 16 + gid;
            int n = bn + wn0 + nt * 8 + tig * 2;
            if (n < N) {
                float v0 = acc[mt][nt][0], v1 = acc[mt][nt][1];
                float v2 = acc[mt][nt][2], v3 = acc[mt][nt][3];
                if (epi == 1) {
                    float b0v = bias[n], b1v = bias[n + 1];
                    v0 = softplusf(v0 + b0v); v1 = softplusf(v1 + b1v);
                    v2 = softplusf(v2 + b0v); v3 = softplusf(v3 + b1v);
                }
                *reinterpret_cast<float2*>(C + (size_t)m * ldc + n) =
                    make_float2(v0, v1);
                *reinterpret_cast<float2*>(C + (size_t)(m + 8) * ldc + n) =
                    make_float2(v2, v3);
            }
        }
}

// ---------------------------------------------------------------------------
__global__ __launch_bounds__(256)
void conv_silu_k(const float* __restrict__ xz, const float* __restrict__ w,
                 const float* __restrict__ cb, float* __restrict__ uc)
{
    int idx = blockIdx.x * blockDim.x + threadIdx.x;
    if (idx >= NROWS * DINNER) return;
    int d   = idx & (DINNER - 1);
    int row = idx >> 11;
    int l   = row & (L_SEQ - 1);
    int b   = row >> 11;

    const float4 wv = *reinterpret_cast<const float4*>(w + (size_t)d * 4);
    const float* up = xz + (size_t)b * L_SEQ * (2 * DINNER) + d;
    const size_t S = 2 * DINNER;

    float acc = cb[d] + wv.w * up[(size_t)l * S];
    if (l >= 1) acc += wv.z * up[(size_t)(l - 1) * S];
    if (l >= 2) acc += wv.y * up[(size_t)(l - 2) * S];
    if (l >= 3) acc += wv.x * up[(size_t)(l - 3) * S];

    uc[idx] = acc / (1.f + __expf(-acc));
}

__global__ void reduce_split(const float* __restrict__ part,
                             float* __restrict__ out, int n)
{
    int i = blockIdx.x * blockDim.x + threadIdx.x;
    if (i < n) {
        float s = 0.f;
#pragma unroll
        for (int z = 0; z < KSPLIT; ++z) s += part[(size_t)z * n + i];
        out[i] = s;
    }
}

// ---------------------------------------------------------------------------
// Chunked selective scan (3 phases).
// ---------------------------------------------------------------------------
__global__ __launch_bounds__(256)
void scan_p1(const float* __restrict__ delta, const float* __restrict__ xdbl,
             const float* __restrict__ uc, const float* __restrict__ A_log,
             float* __restrict__ hfin, float* __restrict__ sumd)
{
    const int b = blockIdx.z;
    const int c = blockIdx.y;
    const int d = blockIdx.x * 256 + threadIdx.x;

    float na[DSTATE];
#pragma unroll
    for (int s = 0; s < DSTATE; ++s)
        na[s] = -__expf(A_log[(size_t)d * DSTATE + s]);

    float h[DSTATE];
#pragma unroll
    for (int s = 0; s < DSTATE; ++s) h[s] = 0.f;
    float sd = 0.f;

    __shared__ float bs[32][DSTATE];

    const int lbeg = c * CHUNK;
    for (int l0 = lbeg; l0 < lbeg + CHUNK; l0 += 32) {
        __syncthreads();
        for (int t = threadIdx.x; t < 32 * DSTATE; t += 256) {
            int i = t >> 4, j = t & 15;
            bs[i][j] = xdbl[(size_t)(b * L_SEQ + l0 + i) * XPROJ_N + 64 + j];
        }
        __syncthreads();
#pragma unroll 4
        for (int i = 0; i < 32; ++i) {
            size_t row = (size_t)b * L_SEQ + l0 + i;
            float t  = delta[row * DINNER + d];
            float u  = uc[row * DINNER + d];
            float tu = t * u;
            sd += t;
#pragma unroll
            for (int s = 0; s < DSTATE; ++s) {
                float dA = __expf(t * na[s]);
                h[s] = fmaf(dA, h[s], tu * bs[i][s]);
            }
        }
    }

    const size_t base = ((size_t)(b * NCHUNK + c) * DSTATE) * DINNER + d;
#pragma unroll
    for (int s = 0; s < DSTATE; ++s)
        hfin[base + (size_t)s * DINNER] = h[s];
    sumd[(size_t)(b * NCHUNK + c) * DINNER + d] = sd;
}

__global__ __launch_bounds__(256)
void scan_combine(const float* __restrict__ hfin, const float* __restrict__ sumd,
                  const float* __restrict__ A_log, float* __restrict__ hini)
{
    const int b = blockIdx.y;
    const int d = blockIdx.x * 256 + threadIdx.x;

    float na[DSTATE];
#pragma unroll
    for (int s = 0; s < DSTATE; ++s)
        na[s] = -__expf(A_log[(size_t)d * DSTATE + s]);

    float h[DSTATE];
#pragma unroll
    for (int s = 0; s < DSTATE; ++s) h[s] = 0.f;

    for (int c = 0; c < NCHUNK; ++c) {
        const size_t base = ((size_t)(b * NCHUNK + c) * DSTATE) * DINNER + d;
#pragma unroll
        for (int s = 0; s < DSTATE; ++s)
            hini[base + (size_t)s * DINNER] = h[s];
        float sd = sumd[(size_t)(b * NCHUNK + c) * DINNER + d];
#pragma unroll
        for (int s = 0; s < DSTATE; ++s) {
            float pA = __expf(sd * na[s]);
            h[s] = fmaf(pA, h[s], hfin[base + (size_t)s * DINNER]);
        }
    }
}

__global__ __launch_bounds__(256)
void scan_p3(const float* __restrict__ delta, const float* __restrict__ xdbl,
             const float* __restrict__ uc, const float* __restrict__ xz,
             const float* __restrict__ A_log, const float* __restrict__ Dv,
             const float* __restrict__ hini, float* __restrict__ y)
{
    const int b = blockIdx.z;
    const int c = blockIdx.y;
    const int d = blockIdx.x * 256 + threadIdx.x;

    float na[DSTATE];
#pragma unroll
    for (int s = 0; s < DSTATE; ++s)
        na[s] = -__expf(A_log[(size_t)d * DSTATE + s]);

    float h[DSTATE];
    {
        const size_t base = ((size_t)(b * NCHUNK + c) * DSTATE) * DINNER + d;
#pragma unroll
        for (int s = 0; s < DSTATE; ++s)
            h[s] = hini[base + (size_t)s * DINNER];
    }

    const float Dd = Dv[d];
    __shared__ float bc[32][32];

    const int lbeg = c * CHUNK;
    for (int l0 = lbeg; l0 < lbeg + CHUNK; l0 += 32) {
        __syncthreads();
        for (int t = threadIdx.x; t < 1024; t += 256) {
            int i = t >> 5, j = t & 31;
            bc[i][j] = xdbl[(size_t)(b * L_SEQ + l0 + i) * XPROJ_N + 64 + j];
        }
        __syncthreads();
#pragma unroll 4
        for (int i = 0; i < 32; ++i) {
            size_t row = (size_t)b * L_SEQ + l0 + i;
            float t  = delta[row * DINNER + d];
            float u  = uc[row * DINNER + d];
            float tu = t * u;
            float yv = 0.f;
#pragma unroll
            for (int s = 0; s < DSTATE; ++s) {
                float dA = __expf(t * na[s]);
                h[s] = fmaf(dA, h[s], tu * bc[i][s]);
                yv   = fmaf(h[s], bc[i][16 + s], yv);
            }
            float zv = xz[row * (2 * DINNER) + DINNER + d];
            float g  = zv / (1.f + __expf(-zv));
            y[row * DINNER + d] = (yv + u * Dd) * g;
        }
    }
}

// ---------------------------------------------------------------------------
extern "C" void kernel_launch(void* const* d_in, const int* in_sizes, int n_in,
                              void* d_out, int out_size)
{
    const float* x        = (const float*)d_in[0];
    const float* W_in     = (const float*)d_in[1];
    const float* conv_w   = (const float*)d_in[2];
    const float* conv_b   = (const float*)d_in[3];
    const float* W_xproj  = (const float*)d_in[4];
    const float* W_dtproj = (const float*)d_in[5];
    const float* dt_bias  = (const float*)d_in[6];
    const float* A_log    = (const float*)d_in[7];
    const float* Dv       = (const float*)d_in[8];
    const float* W_out    = (const float*)d_in[9];
    float* out = (float*)d_out;

    float *xz, *uc, *xpart, *xdbl, *delta, *y, *hfin, *hini, *sumd;
    cudaGetSymbolAddress((void**)&xz,    g_xz);
    cudaGetSymbolAddress((void**)&uc,    g_uc);
    cudaGetSymbolAddress((void**)&xpart, g_xpart);
    cudaGetSymbolAddress((void**)&xdbl,  g_xdbl);
    cudaGetSymbolAddress((void**)&delta, g_delta);
    cudaGetSymbolAddress((void**)&y,     g_y);
    cudaGetSymbolAddress((void**)&hfin,  g_hfin);
    cudaGetSymbolAddress((void**)&hini,  g_hini);
    cudaGetSymbolAddress((void**)&sumd,  g_sumd);

    dim3 blk(256);

    // 1. in_proj: xz[4096,4096] = x @ W_in^T  (K=1024)
    mma_tn<<<dim3(32, 32, 1), blk>>>(x, W_in, xz,
        NROWS, 2 * DINNER, DMODEL, DMODEL, DMODEL, 2 * DINNER,
        nullptr, 0, DMODEL);

    // 2. depthwise conv + silu
    conv_silu_k<<<(NROWS * DINNER) / 256, blk>>>(xz, conv_w, conv_b, uc);

    // 3. x_proj (split-K x8): x_dbl[4096,96] = u_c @ W_xproj^T (K=2048)
    mma_tn<<<dim3(1, 32, KSPLIT), blk>>>(uc, W_xproj, xpart,
        NROWS, XPROJ_N, DINNER, DINNER, DINNER, XPROJ_N,
        nullptr, 0, DINNER / KSPLIT);
    reduce_split<<<(NROWS * XPROJ_N + 255) / 256, blk>>>(
        xpart, xdbl, NROWS * XPROJ_N);

    // 4. dt_proj + softplus: delta[4096,2048] (K=64)
    mma_tn<<<dim3(16, 32, 1), blk>>>(xdbl, W_dtproj, delta,
        NROWS, DINNER, 64, XPROJ_N, 64, DINNER,
        dt_bias, 1, 64);

    // 5. chunked selective scan + skip + gate
    scan_p1<<<dim3(DINNER / 256, NCHUNK, NB), blk>>>(
        delta, xdbl, uc, A_log, hfin, sumd);
    scan_combine<<<dim3(DINNER / 256, NB), blk>>>(hfin, sumd, A_log, hini);
    scan_p3<<<dim3(DINNER / 256, NCHUNK, NB), blk>>>(
        delta, xdbl, uc, xz, A_log, Dv, hini, y);

    // 6. out_proj: out[4096,1024] = y @ W_out^T (K=2048)
    mma_tn<<<dim3(8, 32, 1), blk>>>(y, W_out, out,
        NROWS, DMODEL, DINNER, DINNER, DINNER, DMODEL,
        nullptr, 0, DINNER);
}

// round 7
// speedup vs baseline: 1.4642x; 1.1871x over previous
#include <cuda_runtime.h>
#include <cuda_fp16.h>
#include <math.h>

// ---------------------------------------------------------------------------
// Mamba block forward. fp16 mma.sync (m16n8k16, fp32 accum) GEMMs with
// register prefetch + occ=2, chunked parallel selective scan.
//   B=2, L=2048, d_model=1024, d_inner=2048, d_state=16, d_conv=4, dt_rank=64
// tcgen05 unavailable: harness PTX target is compute_103 (no 'a' suffix).
// ---------------------------------------------------------------------------

#define L_SEQ   2048
#define NB      2
#define DMODEL  1024
#define DINNER  2048
#define DSTATE  16
#define NROWS   (NB * L_SEQ)     // 4096
#define XPROJ_N 96
#define KSPLIT  8
#define CHUNK   128
#define NCHUNK  (L_SEQ / CHUNK)  // 16

__device__ float g_xz   [(size_t)NROWS * 2 * DINNER];
__device__ float g_uc   [(size_t)NROWS * DINNER];
__device__ float g_xpart[(size_t)KSPLIT * NROWS * XPROJ_N];
__device__ float g_xdbl [(size_t)NROWS * XPROJ_N];
__device__ float g_delta[(size_t)NROWS * DINNER];
__device__ float g_y    [(size_t)NROWS * DINNER];
__device__ float g_hfin [(size_t)NB * NCHUNK * DSTATE * DINNER];
__device__ float g_hini [(size_t)NB * NCHUNK * DSTATE * DINNER];
__device__ float g_sumd [(size_t)NB * NCHUNK * DINNER];

__device__ __forceinline__ float softplusf(float x) {
    return x > 20.f ? x : log1pf(__expf(x));
}
__device__ __forceinline__ unsigned smem_u32(const void* p) {
    return (unsigned)__cvta_generic_to_shared(p);
}

// ---------------------------------------------------------------------------
// C[M,N] = A[M,K] @ B[N,K]^T via mma.sync.m16n8k16.f32.f16.f16.f32.
// 128x128 tile, BK=32 (two k16 steps), 256 threads = 8 warps (4m x 2n),
// warp tile 32m x 64n. Single smem stage; next K-block prefetched into regs.
// ---------------------------------------------------------------------------
#define BK    32
#define BSTH  40   // halfs per row (32 + 8 pad): conflict-free ldmatrix

__global__ __launch_bounds__(256, 2)
void mma_tn(const float* __restrict__ A, const float* __restrict__ B,
            float* __restrict__ C, int M, int N, int K,
            int lda, int ldb, int ldc,
            const float* __restrict__ bias, int epi, int kPerSplit)
{
    __shared__ __align__(16) __half As[128 * BSTH];
    __shared__ __align__(16) __half Bs[128 * BSTH];

    const int tid  = threadIdx.x;
    const int lane = tid & 31;
    const int wid  = tid >> 5;
    const int wm0  = (wid >> 1) << 5;   // 0,32,64,96
    const int wn0  = (wid & 1) << 6;    // 0,64

    const int bm = blockIdx.y << 7;
    const int bn = blockIdx.x << 7;
    const int kbeg = blockIdx.z * kPerSplit;
    const int kend = kbeg + kPerSplit;
    C += (size_t)blockIdx.z * (size_t)M * (size_t)ldc;

    float acc[2][8][4];
#pragma unroll
    for (int mt = 0; mt < 2; ++mt)
#pragma unroll
        for (int nt = 0; nt < 8; ++nt)
#pragma unroll
            for (int r = 0; r < 4; ++r) acc[mt][nt][r] = 0.f;

    // ldmatrix x4 source offsets (halfs). Groups (by lane/8):
    //   A: m0-7 k0 | m8-15 k0 | m0-7 k8 | m8-15 k8  -> a0..a3 of m16n8k16
    //   B: n0-7 k0 | n8-15 k0 | n0-7 k8 | n8-15 k8  -> per-slice reg pairing
    int a_off[2], b_off[4];
#pragma unroll
    for (int mt = 0; mt < 2; ++mt) {
        int row = wm0 + mt * 16 + ((lane >> 3) & 1) * 8 + (lane & 7);
        int col = (lane >> 4) * 8;
        a_off[mt] = row * BSTH + col;
    }
#pragma unroll
    for (int bt = 0; bt < 4; ++bt) {
        int row = wn0 + bt * 16 + ((lane >> 3) & 1) * 8 + (lane & 7);
        int col = (lane >> 4) * 8;
        b_off[bt] = row * BSTH + col;
    }
    const unsigned as_base = smem_u32(As);
    const unsigned bs_base = smem_u32(Bs);

    const int lrow = tid >> 3;          // 0..31
    const int lc4  = (tid & 7) << 2;    // 0,4,...,28 (float / half index)

    float4 pa[4], pb[4];
    // prologue: K-block 0 -> registers
#pragma unroll
    for (int i = 0; i < 4; ++i) {
        int r = lrow + (i << 5);
        pa[i] = *reinterpret_cast<const float4*>(
            A + (size_t)(bm + r) * lda + kbeg + lc4);
        pb[i] = make_float4(0.f, 0.f, 0.f, 0.f);
        if (bn + r < N)
            pb[i] = *reinterpret_cast<const float4*>(
                B + (size_t)(bn + r) * ldb + kbeg + lc4);
    }

    const int nk = (kend - kbeg) >> 5;
    for (int t = 0; t < nk; ++t) {
        // stage current regs into smem as fp16
#pragma unroll
        for (int i = 0; i < 4; ++i) {
            int r = lrow + (i << 5);
            __half2* qa = reinterpret_cast<__half2*>(&As[r * BSTH + lc4]);
            qa[0] = __floats2half2_rn(pa[i].x, pa[i].y);
            qa[1] = __floats2half2_rn(pa[i].z, pa[i].w);
            __half2* qb = reinterpret_cast<__half2*>(&Bs[r * BSTH + lc4]);
            qb[0] = __floats2half2_rn(pb[i].x, pb[i].y);
            qb[1] = __floats2half2_rn(pb[i].z, pb[i].w);
        }
        __syncthreads();

        // prefetch next K-block (hides global latency under MMA)
        if (t + 1 < nk) {
            const int kn = kbeg + (t + 1) * BK;
#pragma unroll
            for (int i = 0; i < 4; ++i) {
                int r = lrow + (i << 5);
                pa[i] = *reinterpret_cast<const float4*>(
                    A + (size_t)(bm + r) * lda + kn + lc4);
                pb[i] = make_float4(0.f, 0.f, 0.f, 0.f);
                if (bn + r < N)
                    pb[i] = *reinterpret_cast<const float4*>(
                        B + (size_t)(bn + r) * ldb + kn + lc4);
            }
        }

        // compute: two k16 steps per 32-wide block
#pragma unroll
        for (int kk = 0; kk < BK; kk += 16) {
            unsigned a[2][4], b[4][4];
#pragma unroll
            for (int mt = 0; mt < 2; ++mt) {
                unsigned addr = as_base + (unsigned)((a_off[mt] + kk) << 1);
                asm volatile(
                    "ldmatrix.sync.aligned.m8n8.x4.shared.b16 {%0,%1,%2,%3}, [%4];"
                    : "=r"(a[mt][0]), "=r"(a[mt][1]), "=r"(a[mt][2]), "=r"(a[mt][3])
                    : "r"(addr));
            }
#pragma unroll
            for (int bt = 0; bt < 4; ++bt) {
                unsigned addr = bs_base + (unsigned)((b_off[bt] + kk) << 1);
                asm volatile(
                    "ldmatrix.sync.aligned.m8n8.x4.shared.b16 {%0,%1,%2,%3}, [%4];"
                    : "=r"(b[bt][0]), "=r"(b[bt][1]), "=r"(b[bt][2]), "=r"(b[bt][3])
                    : "r"(addr));
            }
#pragma unroll
            for (int mt = 0; mt < 2; ++mt)
#pragma unroll
                for (int nt = 0; nt < 8; ++nt) {
                    unsigned b0 = b[nt >> 1][(nt & 1)];       // k0-7 of n-slice
                    unsigned b1 = b[nt >> 1][2 + (nt & 1)];   // k8-15
                    asm volatile(
                        "mma.sync.aligned.m16n8k16.row.col.f32.f16.f16.f32 "
                        "{%0,%1,%2,%3}, {%4,%5,%6,%7}, {%8,%9}, {%0,%1,%2,%3};"
                        : "+f"(acc[mt][nt][0]), "+f"(acc[mt][nt][1]),
                          "+f"(acc[mt][nt][2]), "+f"(acc[mt][nt][3])
                        : "r"(a[mt][0]), "r"(a[mt][1]), "r"(a[mt][2]), "r"(a[mt][3]),
                          "r"(b0), "r"(b1));
                }
        }
        __syncthreads();
    }

    const int gid = lane >> 2;
    const int tig = lane & 3;
#pragma unroll
    for (int mt = 0; mt < 2; ++mt)
#pragma unroll
        for (int nt = 0; nt < 8; ++nt) {
            int m = bm + wm0 + mt * 16 + gid;
            int n = bn + wn0 + nt * 8 + tig * 2;
            if (n < N) {
                float v0 = acc[mt][nt][0], v1 = acc[mt][nt][1];
                float v2 = acc[mt][nt][2], v3 = acc[mt][nt][3];
                if (epi == 1) {
                    float b0v = bias[n], b1v = bias[n + 1];
                    v0 = softplusf(v0 + b0v); v1 = softplusf(v1 + b1v);
                    v2 = softplusf(v2 + b0v); v3 = softplusf(v3 + b1v);
                }
                *reinterpret_cast<float2*>(C + (size_t)m * ldc + n) =
                    make_float2(v0, v1);
                *reinterpret_cast<float2*>(C + (size_t)(m + 8) * ldc + n) =
                    make_float2(v2, v3);
            }
        }
}

// ---------------------------------------------------------------------------
__global__ __launch_bounds__(256)
void conv_silu_k(const float* __restrict__ xz, const float* __restrict__ w,
                 const float* __restrict__ cb, float* __restrict__ uc)
{
    int idx = blockIdx.x * blockDim.x + threadIdx.x;
    if (idx >= NROWS * DINNER) return;
    int d   = idx & (DINNER - 1);
    int row = idx >> 11;
    int l   = row & (L_SEQ - 1);
    int b   = row >> 11;

    const float4 wv = *reinterpret_cast<const float4*>(w + (size_t)d * 4);
    const float* up = xz + (size_t)b * L_SEQ * (2 * DINNER) + d;
    const size_t S = 2 * DINNER;

    float acc = cb[d] + wv.w * up[(size_t)l * S];
    if (l >= 1) acc += wv.z * up[(size_t)(l - 1) * S];
    if (l >= 2) acc += wv.y * up[(size_t)(l - 2) * S];
    if (l >= 3) acc += wv.x * up[(size_t)(l - 3) * S];

    uc[idx] = acc / (1.f + __expf(-acc));
}

__global__ void reduce_split(const float* __restrict__ part,
                             float* __restrict__ out, int n)
{
    int i = blockIdx.x * blockDim.x + threadIdx.x;
    if (i < n) {
        float s = 0.f;
#pragma unroll
        for (int z = 0; z < KSPLIT; ++z) s += part[(size_t)z * n + i];
        out[i] = s;
    }
}

// ---------------------------------------------------------------------------
// Chunked selective scan (3 phases).
// ---------------------------------------------------------------------------
__global__ __launch_bounds__(256)
void scan_p1(const float* __restrict__ delta, const float* __restrict__ xdbl,
             const float* __restrict__ uc, const float* __restrict__ A_log,
             float* __restrict__ hfin, float* __restrict__ sumd)
{
    const int b = blockIdx.z;
    const int c = blockIdx.y;
    const int d = blockIdx.x * 256 + threadIdx.x;

    float na[DSTATE];
#pragma unroll
    for (int s = 0; s < DSTATE; ++s)
        na[s] = -__expf(A_log[(size_t)d * DSTATE + s]);

    float h[DSTATE];
#pragma unroll
    for (int s = 0; s < DSTATE; ++s) h[s] = 0.f;
    float sd = 0.f;

    __shared__ float bs[32][DSTATE];

    const int lbeg = c * CHUNK;
    for (int l0 = lbeg; l0 < lbeg + CHUNK; l0 += 32) {
        __syncthreads();
        for (int t = threadIdx.x; t < 32 * DSTATE; t += 256) {
            int i = t >> 4, j = t & 15;
            bs[i][j] = xdbl[(size_t)(b * L_SEQ + l0 + i) * XPROJ_N + 64 + j];
        }
        __syncthreads();
#pragma unroll 4
        for (int i = 0; i < 32; ++i) {
            size_t row = (size_t)b * L_SEQ + l0 + i;
            float t  = delta[row * DINNER + d];
            float u  = uc[row * DINNER + d];
            float tu = t * u;
            sd += t;
#pragma unroll
            for (int s = 0; s < DSTATE; ++s) {
                float dA = __expf(t * na[s]);
                h[s] = fmaf(dA, h[s], tu * bs[i][s]);
            }
        }
    }

    const size_t base = ((size_t)(b * NCHUNK + c) * DSTATE) * DINNER + d;
#pragma unroll
    for (int s = 0; s < DSTATE; ++s)
        hfin[base + (size_t)s * DINNER] = h[s];
    sumd[(size_t)(b * NCHUNK + c) * DINNER + d] = sd;
}

__global__ __launch_bounds__(256)
void scan_combine(const float* __restrict__ hfin, const float* __restrict__ sumd,
                  const float* __restrict__ A_log, float* __restrict__ hini)
{
    const int b = blockIdx.y;
    const int d = blockIdx.x * 256 + threadIdx.x;

    float na[DSTATE];
#pragma unroll
    for (int s = 0; s < DSTATE; ++s)
        na[s] = -__expf(A_log[(size_t)d * DSTATE + s]);

    float h[DSTATE];
#pragma unroll
    for (int s = 0; s < DSTATE; ++s) h[s] = 0.f;

    for (int c = 0; c < NCHUNK; ++c) {
        const size_t base = ((size_t)(b * NCHUNK + c) * DSTATE) * DINNER + d;
#pragma unroll
        for (int s = 0; s < DSTATE; ++s)
            hini[base + (size_t)s * DINNER] = h[s];
        float sd = sumd[(size_t)(b * NCHUNK + c) * DINNER + d];
#pragma unroll
        for (int s = 0; s < DSTATE; ++s) {
            float pA = __expf(sd * na[s]);
            h[s] = fmaf(pA, h[s], hfin[base + (size_t)s * DINNER]);
        }
    }
}

__global__ __launch_bounds__(256)
void scan_p3(const float* __restrict__ delta, const float* __restrict__ xdbl,
             const float* __restrict__ uc, const float* __restrict__ xz,
             const float* __restrict__ A_log, const float* __restrict__ Dv,
             const float* __restrict__ hini, float* __restrict__ y)
{
    const int b = blockIdx.z;
    const int c = blockIdx.y;
    const int d = blockIdx.x * 256 + threadIdx.x;

    float na[DSTATE];
#pragma unroll
    for (int s = 0; s < DSTATE; ++s)
        na[s] = -__expf(A_log[(size_t)d * DSTATE + s]);

    float h[DSTATE];
    {
        const size_t base = ((size_t)(b * NCHUNK + c) * DSTATE) * DINNER + d;
#pragma unroll
        for (int s = 0; s < DSTATE; ++s)
            h[s] = hini[base + (size_t)s * DINNER];
    }

    const float Dd = Dv[d];
    __shared__ float bc[32][32];

    const int lbeg = c * CHUNK;
    for (int l0 = lbeg; l0 < lbeg + CHUNK; l0 += 32) {
        __syncthreads();
        for (int t = threadIdx.x; t < 1024; t += 256) {
            int i = t >> 5, j = t & 31;
            bc[i][j] = xdbl[(size_t)(b * L_SEQ + l0 + i) * XPROJ_N + 64 + j];
        }
        __syncthreads();
#pragma unroll 4
        for (int i = 0; i < 32; ++i) {
            size_t row = (size_t)b * L_SEQ + l0 + i;
            float t  = delta[row * DINNER + d];
            float u  = uc[row * DINNER + d];
            float tu = t * u;
            float yv = 0.f;
#pragma unroll
            for (int s = 0; s < DSTATE; ++s) {
                float dA = __expf(t * na[s]);
                h[s] = fmaf(dA, h[s], tu * bc[i][s]);
                yv   = fmaf(h[s], bc[i][16 + s], yv);
            }
            float zv = xz[row * (2 * DINNER) + DINNER + d];
            float g  = zv / (1.f + __expf(-zv));
            y[row * DINNER + d] = (yv + u * Dd) * g;
        }
    }
}

// ---------------------------------------------------------------------------
extern "C" void kernel_launch(void* const* d_in, const int* in_sizes, int n_in,
                              void* d_out, int out_size)
{
    const float* x        = (const float*)d_in[0];
    const float* W_in     = (const float*)d_in[1];
    const float* conv_w   = (const float*)d_in[2];
    const float* conv_b   = (const float*)d_in[3];
    const float* W_xproj  = (const float*)d_in[4];
    const float* W_dtproj = (const float*)d_in[5];
    const float* dt_bias  = (const float*)d_in[6];
    const float* A_log    = (const float*)d_in[7];
    const float* Dv       = (const float*)d_in[8];
    const float* W_out    = (const float*)d_in[9];
    float* out = (float*)d_out;

    float *xz, *uc, *xpart, *xdbl, *delta, *y, *hfin, *hini, *sumd;
    cudaGetSymbolAddress((void**)&xz,    g_xz);
    cudaGetSymbolAddress((void**)&uc,    g_uc);
    cudaGetSymbolAddress((void**)&xpart, g_xpart);
    cudaGetSymbolAddress((void**)&xdbl,  g_xdbl);
    cudaGetSymbolAddress((void**)&delta, g_delta);
    cudaGetSymbolAddress((void**)&y,     g_y);
    cudaGetSymbolAddress((void**)&hfin,  g_hfin);
    cudaGetSymbolAddress((void**)&hini,  g_hini);
    cudaGetSymbolAddress((void**)&sumd,  g_sumd);

    dim3 blk(256);

    // 1. in_proj: xz[4096,4096] = x @ W_in^T  (K=1024)
    mma_tn<<<dim3(32, 32, 1), blk>>>(x, W_in, xz,
        NROWS, 2 * DINNER, DMODEL, DMODEL, DMODEL, 2 * DINNER,
        nullptr, 0, DMODEL);

    // 2. depthwise conv + silu
    conv_silu_k<<<(NROWS * DINNER) / 256, blk>>>(xz, conv_w, conv_b, uc);

    // 3. x_proj (split-K x8): x_dbl[4096,96] = u_c @ W_xproj^T (K=2048)
    mma_tn<<<dim3(1, 32, KSPLIT), blk>>>(uc, W_xproj, xpart,
        NROWS, XPROJ_N, DINNER, DINNER, DINNER, XPROJ_N,
        nullptr, 0, DINNER / KSPLIT);
    reduce_split<<<(NROWS * XPROJ_N + 255) / 256, blk>>>(
        xpart, xdbl, NROWS * XPROJ_N);

    // 4. dt_proj + softplus: delta[4096,2048] (K=64)
    mma_tn<<<dim3(16, 32, 1), blk>>>(xdbl, W_dtproj, delta,
        NROWS, DINNER, 64, XPROJ_N, 64, DINNER,
        dt_bias, 1, 64);

    // 5. chunked selective scan + skip + gate
    scan_p1<<<dim3(DINNER / 256, NCHUNK, NB), blk>>>(
        delta, xdbl, uc, A_log, hfin, sumd);
    scan_combine<<<dim3(DINNER / 256, NB), blk>>>(hfin, sumd, A_log, hini);
    scan_p3<<<dim3(DINNER / 256, NCHUNK, NB), blk>>>(
        delta, xdbl, uc, xz, A_log, Dv, hini, y);

    // 6. out_proj: out[4096,1024] = y @ W_out^T (K=2048)
    mma_tn<<<dim3(8, 32, 1), blk>>>(y, W_out, out,
        NROWS, DMODEL, DINNER, DINNER, DINNER, DMODEL,
        nullptr, 0, DINNER);
}

// round 8
// speedup vs baseline: 1.4838x; 1.0134x over previous
#include <cuda_runtime.h>
#include <cuda_fp16.h>
#include <math.h>

// ---------------------------------------------------------------------------
// Mamba block forward. fp16-resident GEMM operands (pre-converted once,
// bit-identical to in-loop conversion), m16n8k16 fp16 MMA w/ fp32 accum,
// register prefetch, occ=2. Chunked parallel selective scan.
//   B=2, L=2048, d_model=1024, d_inner=2048, d_state=16, d_conv=4, dt_rank=64
// tcgen05 unavailable: harness PTX target is compute_103 (no 'a' suffix).
// ---------------------------------------------------------------------------

#define L_SEQ   2048
#define NB      2
#define DMODEL  1024
#define DINNER  2048
#define DSTATE  16
#define NROWS   (NB * L_SEQ)     // 4096
#define XPROJ_N 96
#define KSPLIT  8
#define CHUNK   128
#define NCHUNK  (L_SEQ / CHUNK)  // 16

// fp32 scratch
__device__ float g_xz   [(size_t)NROWS * 2 * DINNER];
__device__ float g_uc   [(size_t)NROWS * DINNER];
__device__ float g_xpart[(size_t)KSPLIT * NROWS * XPROJ_N];
__device__ float g_xdbl [(size_t)NROWS * XPROJ_N];
__device__ float g_delta[(size_t)NROWS * DINNER];
__device__ float g_hfin [(size_t)NB * NCHUNK * DSTATE * DINNER];
__device__ float g_hini [(size_t)NB * NCHUNK * DSTATE * DINNER];
__device__ float g_sumd [(size_t)NB * NCHUNK * DINNER];
// fp16 operands
__device__ __half g_xh   [(size_t)NROWS * DMODEL];
__device__ __half g_whin [(size_t)2 * DINNER * DMODEL];
__device__ __half g_whxp [(size_t)XPROJ_N * DINNER];
__device__ __half g_whdt [(size_t)DINNER * 64];
__device__ __half g_whout[(size_t)DMODEL * DINNER];
__device__ __half g_xdblh[(size_t)NROWS * XPROJ_N];
__device__ __half g_yh   [(size_t)NROWS * DINNER];

__device__ __forceinline__ float softplusf(float x) {
    return x > 20.f ? x : log1pf(__expf(x));
}
__device__ __forceinline__ unsigned smem_u32(const void* p) {
    return (unsigned)__cvta_generic_to_shared(p);
}

// ---------------------------------------------------------------------------
// Multi-tensor fp32 -> fp16 conversion (one launch, segment per blockIdx.y).
// All sizes divisible by 4.
// ---------------------------------------------------------------------------
__global__ __launch_bounds__(256)
void f2h_multi(const float* __restrict__ s0, __half* d0, int n0,
               const float* __restrict__ s1, __half* d1, int n1,
               const float* __restrict__ s2, __half* d2, int n2,
               const float* __restrict__ s3, __half* d3, int n3,
               const float* __restrict__ s4, __half* d4, int n4)
{
    const float* s; __half* d; int n;
    switch (blockIdx.y) {
        case 0: s = s0; d = d0; n = n0; break;
        case 1: s = s1; d = d1; n = n1; break;
        case 2: s = s2; d = d2; n = n2; break;
        case 3: s = s3; d = d3; n = n3; break;
        default: s = s4; d = d4; n = n4; break;
    }
    int nq = n >> 2;
    for (int i = blockIdx.x * blockDim.x + threadIdx.x; i < nq;
         i += gridDim.x * blockDim.x) {
        float4 v = *reinterpret_cast<const float4*>(s + (size_t)i * 4);
        __half2 h0 = __floats2half2_rn(v.x, v.y);
        __half2 h1 = __floats2half2_rn(v.z, v.w);
        *reinterpret_cast<uint2*>(d + (size_t)i * 4) =
            make_uint2(*(unsigned*)&h0, *(unsigned*)&h1);
    }
}

// ---------------------------------------------------------------------------
// C[M,N] (fp32) = A[M,K] @ B[N,K]^T, fp16 operands, mma.sync.m16n8k16.
// A is fp16 in gmem when AF32==false, fp32 (converted in loader) when true.
// B always fp16. 128x128 tile, BK=32, 8 warps (4m x 2n), register prefetch.
// ---------------------------------------------------------------------------
#define BK    32
#define BSTH  40   // halfs per row (32 + 8 pad): conflict-free ldmatrix

template<bool AF32>
__global__ __launch_bounds__(256, 2)
void mma_tn(const void* __restrict__ Ap, const __half* __restrict__ Bh,
            float* __restrict__ C, int M, int N, int K,
            int lda, int ldb, int ldc,
            const float* __restrict__ bias, int epi, int kPerSplit)
{
    __shared__ __align__(16) __half As[128 * BSTH];
    __shared__ __align__(16) __half Bs[128 * BSTH];

    const int tid  = threadIdx.x;
    const int lane = tid & 31;
    const int wid  = tid >> 5;
    const int wm0  = (wid >> 1) << 5;   // 0,32,64,96
    const int wn0  = (wid & 1) << 6;    // 0,64

    const int bm = blockIdx.y << 7;
    const int bn = blockIdx.x << 7;
    const int kbeg = blockIdx.z * kPerSplit;
    const int kend = kbeg + kPerSplit;
    C += (size_t)blockIdx.z * (size_t)M * (size_t)ldc;

    const __half* Ah = (const __half*)Ap;
    const float*  Af = (const float*)Ap;

    float acc[2][8][4];
#pragma unroll
    for (int mt = 0; mt < 2; ++mt)
#pragma unroll
        for (int nt = 0; nt < 8; ++nt)
#pragma unroll
            for (int r = 0; r < 4; ++r) acc[mt][nt][r] = 0.f;

    int a_off[2], b_off[4];
#pragma unroll
    for (int mt = 0; mt < 2; ++mt) {
        int row = wm0 + mt * 16 + ((lane >> 3) & 1) * 8 + (lane & 7);
        int col = (lane >> 4) * 8;
        a_off[mt] = row * BSTH + col;
    }
#pragma unroll
    for (int bt = 0; bt < 4; ++bt) {
        int row = wn0 + bt * 16 + ((lane >> 3) & 1) * 8 + (lane & 7);
        int col = (lane >> 4) * 8;
        b_off[bt] = row * BSTH + col;
    }
    const unsigned as_base = smem_u32(As);
    const unsigned bs_base = smem_u32(Bs);

    // loader: 4 threads per row, 8 halfs (16B) each; rows lrow, lrow+64
    const int lrow = tid >> 2;          // 0..63
    const int lc8  = (tid & 3) << 3;    // 0,8,16,24

    uint4  pa[2], pb[2];
    float4 fa[2][2];

    // prologue: K-block 0 -> registers
#pragma unroll
    for (int i = 0; i < 2; ++i) {
        int r = lrow + (i << 6);
        if (AF32) {
            fa[i][0] = *reinterpret_cast<const float4*>(
                Af + (size_t)(bm + r) * lda + kbeg + lc8);
            fa[i][1] = *reinterpret_cast<const float4*>(
                Af + (size_t)(bm + r) * lda + kbeg + lc8 + 4);
        } else {
            pa[i] = *reinterpret_cast<const uint4*>(
                Ah + (size_t)(bm + r) * lda + kbeg + lc8);
        }
        pb[i] = make_uint4(0u, 0u, 0u, 0u);
        if (bn + r < N)
            pb[i] = *reinterpret_cast<const uint4*>(
                Bh + (size_t)(bn + r) * ldb + kbeg + lc8);
    }

    const int nk = (kend - kbeg) >> 5;
    for (int t = 0; t < nk; ++t) {
        // stage regs -> smem
#pragma unroll
        for (int i = 0; i < 2; ++i) {
            int r = lrow + (i << 6);
            uint4 va;
            if (AF32) {
                __half2 h0 = __floats2half2_rn(fa[i][0].x, fa[i][0].y);
                __half2 h1 = __floats2half2_rn(fa[i][0].z, fa[i][0].w);
                __half2 h2 = __floats2half2_rn(fa[i][1].x, fa[i][1].y);
                __half2 h3 = __floats2half2_rn(fa[i][1].z, fa[i][1].w);
                va = make_uint4(*(unsigned*)&h0, *(unsigned*)&h1,
                                *(unsigned*)&h2, *(unsigned*)&h3);
            } else {
                va = pa[i];
            }
            *reinterpret_cast<uint4*>(&As[r * BSTH + lc8]) = va;
            *reinterpret_cast<uint4*>(&Bs[r * BSTH + lc8]) = pb[i];
        }
        __syncthreads();

        // prefetch next K-block
        if (t + 1 < nk) {
            const int kn = kbeg + (t + 1) * BK;
#pragma unroll
            for (int i = 0; i < 2; ++i) {
                int r = lrow + (i << 6);
                if (AF32) {
                    fa[i][0] = *reinterpret_cast<const float4*>(
                        Af + (size_t)(bm + r) * lda + kn + lc8);
                    fa[i][1] = *reinterpret_cast<const float4*>(
                        Af + (size_t)(bm + r) * lda + kn + lc8 + 4);
                } else {
                    pa[i] = *reinterpret_cast<const uint4*>(
                        Ah + (size_t)(bm + r) * lda + kn + lc8);
                }
                pb[i] = make_uint4(0u, 0u, 0u, 0u);
                if (bn + r < N)
                    pb[i] = *reinterpret_cast<const uint4*>(
                        Bh + (size_t)(bn + r) * ldb + kn + lc8);
            }
        }

        // compute: two k16 steps
#pragma unroll
        for (int kk = 0; kk < BK; kk += 16) {
            unsigned a[2][4], b[4][4];
#pragma unroll
            for (int mt = 0; mt < 2; ++mt) {
                unsigned addr = as_base + (unsigned)((a_off[mt] + kk) << 1);
                asm volatile(
                    "ldmatrix.sync.aligned.m8n8.x4.shared.b16 {%0,%1,%2,%3}, [%4];"
                    : "=r"(a[mt][0]), "=r"(a[mt][1]), "=r"(a[mt][2]), "=r"(a[mt][3])
                    : "r"(addr));
            }
#pragma unroll
            for (int bt = 0; bt < 4; ++bt) {
                unsigned addr = bs_base + (unsigned)((b_off[bt] + kk) << 1);
                asm volatile(
                    "ldmatrix.sync.aligned.m8n8.x4.shared.b16 {%0,%1,%2,%3}, [%4];"
                    : "=r"(b[bt][0]), "=r"(b[bt][1]), "=r"(b[bt][2]), "=r"(b[bt][3])
                    : "r"(addr));
            }
#pragma unroll
            for (int mt = 0; mt < 2; ++mt)
#pragma unroll
                for (int nt = 0; nt < 8; ++nt) {
                    unsigned b0 = b[nt >> 1][(nt & 1)];
                    unsigned b1 = b[nt >> 1][2 + (nt & 1)];
                    asm volatile(
                        "mma.sync.aligned.m16n8k16.row.col.f32.f16.f16.f32 "
                        "{%0,%1,%2,%3}, {%4,%5,%6,%7}, {%8,%9}, {%0,%1,%2,%3};"
                        : "+f"(acc[mt][nt][0]), "+f"(acc[mt][nt][1]),
                          "+f"(acc[mt][nt][2]), "+f"(acc[mt][nt][3])
                        : "r"(a[mt][0]), "r"(a[mt][1]), "r"(a[mt][2]), "r"(a[mt][3]),
                          "r"(b0), "r"(b1));
                }
        }
        __syncthreads();
    }

    const int gid = lane >> 2;
    const int tig = lane & 3;
#pragma unroll
    for (int mt = 0; mt < 2; ++mt)
#pragma unroll
        for (int nt = 0; nt < 8; ++nt) {
            int m = bm + wm0 + mt * 16 + gid;
            int n = bn + wn0 + nt * 8 + tig * 2;
            if (n < N) {
                float v0 = acc[mt][nt][0], v1 = acc[mt][nt][1];
                float v2 = acc[mt][nt][2], v3 = acc[mt][nt][3];
                if (epi == 1) {
                    float b0v = bias[n], b1v = bias[n + 1];
                    v0 = softplusf(v0 + b0v); v1 = softplusf(v1 + b1v);
                    v2 = softplusf(v2 + b0v); v3 = softplusf(v3 + b1v);
                }
                *reinterpret_cast<float2*>(C + (size_t)m * ldc + n) =
                    make_float2(v0, v1);
                *reinterpret_cast<float2*>(C + (size_t)(m + 8) * ldc + n) =
                    make_float2(v2, v3);
            }
        }
}

// ---------------------------------------------------------------------------
__global__ __launch_bounds__(256)
void conv_silu_k(const float* __restrict__ xz, const float* __restrict__ w,
                 const float* __restrict__ cb, float* __restrict__ uc)
{
    int idx = blockIdx.x * blockDim.x + threadIdx.x;
    if (idx >= NROWS * DINNER) return;
    int d   = idx & (DINNER - 1);
    int row = idx >> 11;
    int l   = row & (L_SEQ - 1);
    int b   = row >> 11;

    const float4 wv = *reinterpret_cast<const float4*>(w + (size_t)d * 4);
    const float* up = xz + (size_t)b * L_SEQ * (2 * DINNER) + d;
    const size_t S = 2 * DINNER;

    float acc = cb[d] + wv.w * up[(size_t)l * S];
    if (l >= 1) acc += wv.z * up[(size_t)(l - 1) * S];
    if (l >= 2) acc += wv.y * up[(size_t)(l - 2) * S];
    if (l >= 3) acc += wv.x * up[(size_t)(l - 3) * S];

    uc[idx] = acc / (1.f + __expf(-acc));
}

// reduce split-K partials; emit fp32 (for scan B/C) and fp16 (dt_proj A)
__global__ void reduce_split(const float* __restrict__ part,
                             float* __restrict__ out,
                             __half* __restrict__ outh, int n)
{
    int i = blockIdx.x * blockDim.x + threadIdx.x;
    if (i < n) {
        float s = 0.f;
#pragma unroll
        for (int z = 0; z < KSPLIT; ++z) s += part[(size_t)z * n + i];
        out[i]  = s;
        outh[i] = __float2half_rn(s);
    }
}

// ---------------------------------------------------------------------------
// Chunked selective scan (3 phases).
// ---------------------------------------------------------------------------
__global__ __launch_bounds__(256)
void scan_p1(const float* __restrict__ delta, const float* __restrict__ xdbl,
             const float* __restrict__ uc, const float* __restrict__ A_log,
             float* __restrict__ hfin, float* __restrict__ sumd)
{
    const int b = blockIdx.z;
    const int c = blockIdx.y;
    const int d = blockIdx.x * 256 + threadIdx.x;

    float na[DSTATE];
#pragma unroll
    for (int s = 0; s < DSTATE; ++s)
        na[s] = -__expf(A_log[(size_t)d * DSTATE + s]);

    float h[DSTATE];
#pragma unroll
    for (int s = 0; s < DSTATE; ++s) h[s] = 0.f;
    float sd = 0.f;

    __shared__ float bs[32][DSTATE];

    const int lbeg = c * CHUNK;
    for (int l0 = lbeg; l0 < lbeg + CHUNK; l0 += 32) {
        __syncthreads();
        for (int t = threadIdx.x; t < 32 * DSTATE; t += 256) {
            int i = t >> 4, j = t & 15;
            bs[i][j] = xdbl[(size_t)(b * L_SEQ + l0 + i) * XPROJ_N + 64 + j];
        }
        __syncthreads();
#pragma unroll 4
        for (int i = 0; i < 32; ++i) {
            size_t row = (size_t)b * L_SEQ + l0 + i;
            float t  = delta[row * DINNER + d];
            float u  = uc[row * DINNER + d];
            float tu = t * u;
            sd += t;
#pragma unroll
            for (int s = 0; s < DSTATE; ++s) {
                float dA = __expf(t * na[s]);
                h[s] = fmaf(dA, h[s], tu * bs[i][s]);
            }
        }
    }

    const size_t base = ((size_t)(b * NCHUNK + c) * DSTATE) * DINNER + d;
#pragma unroll
    for (int s = 0; s < DSTATE; ++s)
        hfin[base + (size_t)s * DINNER] = h[s];
    sumd[(size_t)(b * NCHUNK + c) * DINNER + d] = sd;
}

__global__ __launch_bounds__(256)
void scan_combine(const float* __restrict__ hfin, const float* __restrict__ sumd,
                  const float* __restrict__ A_log, float* __restrict__ hini)
{
    const int b = blockIdx.y;
    const int d = blockIdx.x * 256 + threadIdx.x;

    float na[DSTATE];
#pragma unroll
    for (int s = 0; s < DSTATE; ++s)
        na[s] = -__expf(A_log[(size_t)d * DSTATE + s]);

    float h[DSTATE];
#pragma unroll
    for (int s = 0; s < DSTATE; ++s) h[s] = 0.f;

    for (int c = 0; c < NCHUNK; ++c) {
        const size_t base = ((size_t)(b * NCHUNK + c) * DSTATE) * DINNER + d;
#pragma unroll
        for (int s = 0; s < DSTATE; ++s)
            hini[base + (size_t)s * DINNER] = h[s];
        float sd = sumd[(size_t)(b * NCHUNK + c) * DINNER + d];
#pragma unroll
        for (int s = 0; s < DSTATE; ++s) {
            float pA = __expf(sd * na[s]);
            h[s] = fmaf(pA, h[s], hfin[base + (size_t)s * DINNER]);
        }
    }
}

__global__ __launch_bounds__(256)
void scan_p3(const float* __restrict__ delta, const float* __restrict__ xdbl,
             const float* __restrict__ uc, const float* __restrict__ xz,
             const float* __restrict__ A_log, const float* __restrict__ Dv,
             const float* __restrict__ hini, __half* __restrict__ yh)
{
    const int b = blockIdx.z;
    const int c = blockIdx.y;
    const int d = blockIdx.x * 256 + threadIdx.x;

    float na[DSTATE];
#pragma unroll
    for (int s = 0; s < DSTATE; ++s)
        na[s] = -__expf(A_log[(size_t)d * DSTATE + s]);

    float h[DSTATE];
    {
        const size_t base = ((size_t)(b * NCHUNK + c) * DSTATE) * DINNER + d;
#pragma unroll
        for (int s = 0; s < DSTATE; ++s)
            h[s] = hini[base + (size_t)s * DINNER];
    }

    const float Dd = Dv[d];
    __shared__ float bc[32][32];

    const int lbeg = c * CHUNK;
    for (int l0 = lbeg; l0 < lbeg + CHUNK; l0 += 32) {
        __syncthreads();
        for (int t = threadIdx.x; t < 1024; t += 256) {
            int i = t >> 5, j = t & 31;
            bc[i][j] = xdbl[(size_t)(b * L_SEQ + l0 + i) * XPROJ_N + 64 + j];
        }
        __syncthreads();
#pragma unroll 4
        for (int i = 0; i < 32; ++i) {
            size_t row = (size_t)b * L_SEQ + l0 + i;
            float t  = delta[row * DINNER + d];
            float u  = uc[row * DINNER + d];
            float tu = t * u;
            float yv = 0.f;
#pragma unroll
            for (int s = 0; s < DSTATE; ++s) {
                float dA = __expf(t * na[s]);
                h[s] = fmaf(dA, h[s], tu * bc[i][s]);
                yv   = fmaf(h[s], bc[i][16 + s], yv);
            }
            float zv = xz[row * (2 * DINNER) + DINNER + d];
            float g  = zv / (1.f + __expf(-zv));
            yh[row * DINNER + d] = __float2half_rn((yv + u * Dd) * g);
        }
    }
}

// ---------------------------------------------------------------------------
extern "C" void kernel_launch(void* const* d_in, const int* in_sizes, int n_in,
                              void* d_out, int out_size)
{
    const float* x        = (const float*)d_in[0];
    const float* W_in     = (const float*)d_in[1];
    const float* conv_w   = (const float*)d_in[2];
    const float* conv_b   = (const float*)d_in[3];
    const float* W_xproj  = (const float*)d_in[4];
    const float* W_dtproj = (const float*)d_in[5];
    const float* dt_bias  = (const float*)d_in[6];
    const float* A_log    = (const float*)d_in[7];
    const float* Dv       = (const float*)d_in[8];
    const float* W_out    = (const float*)d_in[9];
    float* out = (float*)d_out;

    float *xz, *uc, *xpart, *xdbl, *delta, *hfin, *hini, *sumd;
    __half *xh, *whin, *whxp, *whdt, *whout, *xdblh, *yh;
    cudaGetSymbolAddress((void**)&xz,    g_xz);
    cudaGetSymbolAddress((void**)&uc,    g_uc);
    cudaGetSymbolAddress((void**)&xpart, g_xpart);
    cudaGetSymbolAddress((void**)&xdbl,  g_xdbl);
    cudaGetSymbolAddress((void**)&delta, g_delta);
    cudaGetSymbolAddress((void**)&hfin,  g_hfin);
    cudaGetSymbolAddress((void**)&hini,  g_hini);
    cudaGetSymbolAddress((void**)&sumd,  g_sumd);
    cudaGetSymbolAddress((void**)&xh,    g_xh);
    cudaGetSymbolAddress((void**)&whin,  g_whin);
    cudaGetSymbolAddress((void**)&whxp,  g_whxp);
    cudaGetSymbolAddress((void**)&whdt,  g_whdt);
    cudaGetSymbolAddress((void**)&whout, g_whout);
    cudaGetSymbolAddress((void**)&xdblh, g_xdblh);
    cudaGetSymbolAddress((void**)&yh,    g_yh);

    dim3 blk(256);

    // 0. convert x + all weights to fp16 (bit-identical to in-loop cvt)
    f2h_multi<<<dim3(2048, 5), blk>>>(
        x,        xh,    NROWS * DMODEL,
        W_in,     whin,  2 * DINNER * DMODEL,
        W_xproj,  whxp,  XPROJ_N * DINNER,
        W_dtproj, whdt,  DINNER * 64,
        W_out,    whout, DMODEL * DINNER);

    // 1. in_proj: xz[4096,4096] = x @ W_in^T  (K=1024)
    mma_tn<false><<<dim3(32, 32, 1), blk>>>(xh, whin, xz,
        NROWS, 2 * DINNER, DMODEL, DMODEL, DMODEL, 2 * DINNER,
        nullptr, 0, DMODEL);

    // 2. depthwise conv + silu
    conv_silu_k<<<(NROWS * DINNER) / 256, blk>>>(xz, conv_w, conv_b, uc);

    // 3. x_proj (split-K x8): x_dbl[4096,96] = u_c @ W_xproj^T (K=2048)
    mma_tn<true><<<dim3(1, 32, KSPLIT), blk>>>(uc, whxp, xpart,
        NROWS, XPROJ_N, DINNER, DINNER, DINNER, XPROJ_N,
        nullptr, 0, DINNER / KSPLIT);
    reduce_split<<<(NROWS * XPROJ_N + 255) / 256, blk>>>(
        xpart, xdbl, xdblh, NROWS * XPROJ_N);

    // 4. dt_proj + softplus: delta[4096,2048] (K=64)
    mma_tn<false><<<dim3(16, 32, 1), blk>>>(xdblh, whdt, delta,
        NROWS, DINNER, 64, XPROJ_N, 64, DINNER,
        dt_bias, 1, 64);

    // 5. chunked selective scan + skip + gate (y written as fp16)
    scan_p1<<<dim3(DINNER / 256, NCHUNK, NB), blk>>>(
        delta, xdbl, uc, A_log, hfin, sumd);
    scan_combine<<<dim3(DINNER / 256, NB), blk>>>(hfin, sumd, A_log, hini);
    scan_p3<<<dim3(DINNER / 256, NCHUNK, NB), blk>>>(
        delta, xdbl, uc, xz, A_log, Dv, hini, yh);

    // 6. out_proj: out[4096,1024] = y @ W_out^T (K=2048)
    mma_tn<false><<<dim3(8, 32, 1), blk>>>(yh, whout, out,
        NROWS, DMODEL, DINNER, DINNER, DINNER, DMODEL,
        nullptr, 0, DINNER);
}

// round 9
// speedup vs baseline: 1.5265x; 1.0288x over previous
#include <cuda_runtime.h>
#include <cuda_fp16.h>
#include <math.h>

// ---------------------------------------------------------------------------
// Mamba block forward. All GEMMs: fp16 operands (pre-converted, bit-identical),
// m16n8k16 mma.sync + cp.async 3-stage smem pipeline, fp32 accumulate.
// Chunked parallel selective scan.
//   B=2, L=2048, d_model=1024, d_inner=2048, d_state=16, d_conv=4, dt_rank=64
// tcgen05 unavailable: harness PTX target is compute_103 (no 'a' suffix).
// ---------------------------------------------------------------------------

#define L_SEQ   2048
#define NB      2
#define DMODEL  1024
#define DINNER  2048
#define DSTATE  16
#define NROWS   (NB * L_SEQ)     // 4096
#define XPROJ_N 96
#define KSPLIT  8
#define CHUNK   128
#define NCHUNK  (L_SEQ / CHUNK)  // 16

// fp32 scratch
__device__ float g_xz   [(size_t)NROWS * 2 * DINNER];
__device__ float g_uc   [(size_t)NROWS * DINNER];
__device__ float g_xpart[(size_t)KSPLIT * NROWS * XPROJ_N];
__device__ float g_xdbl [(size_t)NROWS * XPROJ_N];
__device__ float g_delta[(size_t)NROWS * DINNER];
__device__ float g_hfin [(size_t)NB * NCHUNK * DSTATE * DINNER];
__device__ float g_hini [(size_t)NB * NCHUNK * DSTATE * DINNER];
__device__ float g_sumd [(size_t)NB * NCHUNK * DINNER];
// fp16 operands
__device__ __half g_xh   [(size_t)NROWS * DMODEL];
__device__ __half g_whin [(size_t)2 * DINNER * DMODEL];
__device__ __half g_whxp [(size_t)XPROJ_N * DINNER];
__device__ __half g_whdt [(size_t)DINNER * 64];
__device__ __half g_whout[(size_t)DMODEL * DINNER];
__device__ __half g_uch  [(size_t)NROWS * DINNER];
__device__ __half g_xdblh[(size_t)NROWS * XPROJ_N];
__device__ __half g_yh   [(size_t)NROWS * DINNER];

__device__ __forceinline__ float softplusf(float x) {
    return x > 20.f ? x : log1pf(__expf(x));
}
__device__ __forceinline__ unsigned smem_u32(const void* p) {
    return (unsigned)__cvta_generic_to_shared(p);
}
__device__ __forceinline__ void cp_async16(unsigned saddr, const void* gptr, int sz) {
    asm volatile("cp.async.cg.shared.global [%0], [%1], 16, %2;"
                 :: "r"(saddr), "l"(gptr), "r"(sz));
}
__device__ __forceinline__ void cp_commit() {
    asm volatile("cp.async.commit_group;" ::: "memory");
}
template<int N>
__device__ __forceinline__ void cp_wait() {
    asm volatile("cp.async.wait_group %0;" :: "n"(N) : "memory");
}

// ---------------------------------------------------------------------------
// Multi-tensor fp32 -> fp16 conversion.
// ---------------------------------------------------------------------------
__global__ __launch_bounds__(256)
void f2h_multi(const float* __restrict__ s0, __half* d0, int n0,
               const float* __restrict__ s1, __half* d1, int n1,
               const float* __restrict__ s2, __half* d2, int n2,
               const float* __restrict__ s3, __half* d3, int n3,
               const float* __restrict__ s4, __half* d4, int n4)
{
    const float* s; __half* d; int n;
    switch (blockIdx.y) {
        case 0: s = s0; d = d0; n = n0; break;
        case 1: s = s1; d = d1; n = n1; break;
        case 2: s = s2; d = d2; n = n2; break;
        case 3: s = s3; d = d3; n = n3; break;
        default: s = s4; d = d4; n = n4; break;
    }
    int nq = n >> 2;
    for (int i = blockIdx.x * blockDim.x + threadIdx.x; i < nq;
         i += gridDim.x * blockDim.x) {
        float4 v = *reinterpret_cast<const float4*>(s + (size_t)i * 4);
        __half2 h0 = __floats2half2_rn(v.x, v.y);
        __half2 h1 = __floats2half2_rn(v.z, v.w);
        *reinterpret_cast<uint2*>(d + (size_t)i * 4) =
            make_uint2(*(unsigned*)&h0, *(unsigned*)&h1);
    }
}

// ---------------------------------------------------------------------------
// C[M,N] (fp32) = A[M,K] @ B[N,K]^T, fp16 operands via cp.async 3-stage
// pipeline. 128x128 tile, BK=32, 8 warps (4m x 2n), warp tile 32m x 64n.
// ---------------------------------------------------------------------------
#define BK      32
#define BSTH    40                      // halfs per row (32 + 8 pad)
#define STG_H   (128 * BSTH)            // halfs per array per stage
#define NSTAGE  3
#define MMA_SMEM_BYTES (NSTAGE * 2 * STG_H * 2)   // 61440

__global__ __launch_bounds__(256, 2)
void mma_tn(const __half* __restrict__ A, const __half* __restrict__ B,
            float* __restrict__ C, int M, int N, int K,
            int lda, int ldb, int ldc,
            const float* __restrict__ bias, int epi, int kPerSplit)
{
    extern __shared__ __align__(16) __half sh[];
    // stage s: A at sh + s*2*STG_H, B at +STG_H

    const int tid  = threadIdx.x;
    const int lane = tid & 31;
    const int wid  = tid >> 5;
    const int wm0  = (wid >> 1) << 5;   // 0,32,64,96
    const int wn0  = (wid & 1) << 6;    // 0,64

    const int bm = blockIdx.y << 7;
    const int bn = blockIdx.x << 7;
    const int kbeg = blockIdx.z * kPerSplit;
    C += (size_t)blockIdx.z * (size_t)M * (size_t)ldc;

    float acc[2][8][4];
#pragma unroll
    for (int mt = 0; mt < 2; ++mt)
#pragma unroll
        for (int nt = 0; nt < 8; ++nt)
#pragma unroll
            for (int r = 0; r < 4; ++r) acc[mt][nt][r] = 0.f;

    int a_off[2], b_off[4];
#pragma unroll
    for (int mt = 0; mt < 2; ++mt) {
        int row = wm0 + mt * 16 + ((lane >> 3) & 1) * 8 + (lane & 7);
        int col = (lane >> 4) * 8;
        a_off[mt] = row * BSTH + col;
    }
#pragma unroll
    for (int bt = 0; bt < 4; ++bt) {
        int row = wn0 + bt * 16 + ((lane >> 3) & 1) * 8 + (lane & 7);
        int col = (lane >> 4) * 8;
        b_off[bt] = row * BSTH + col;
    }
    const unsigned sh_base = smem_u32(sh);

    // loader: 4 threads per row, 8 halfs (16B) each; rows lrow, lrow+64
    const int lrow = tid >> 2;          // 0..63
    const int lc8  = (tid & 3) << 3;    // 0,8,16,24

    const __half* gA = A + (size_t)bm * lda + kbeg;
    const __half* gB = B + (size_t)bn * ldb + kbeg;
    // B row validity (x_proj N=96 tail): clamp address, zero-fill via src-size
    int bsz[2]; const __half* gBrow[2]; const __half* gArow[2];
#pragma unroll
    for (int i = 0; i < 2; ++i) {
        int r = lrow + (i << 6);
        gArow[i] = gA + (size_t)r * lda + lc8;
        int rb = (bn + r < N) ? r : 0;
        bsz[i] = (bn + r < N) ? 16 : 0;
        gBrow[i] = gB + (size_t)rb * ldb + lc8;
    }

    const int nk = kPerSplit >> 5;

    // issue loads for stage s covering K-block t
    auto issue = [&](int t, int s) {
        unsigned sa = sh_base + (unsigned)((s * 2 * STG_H) << 1);
        unsigned sb = sa + (unsigned)(STG_H << 1);
        int koff = t * BK;
#pragma unroll
        for (int i = 0; i < 2; ++i) {
            int r = lrow + (i << 6);
            cp_async16(sa + (unsigned)((r * BSTH + lc8) << 1), gArow[i] + koff, 16);
            cp_async16(sb + (unsigned)((r * BSTH + lc8) << 1), gBrow[i] + koff, bsz[i]);
        }
        cp_commit();
    };

    issue(0, 0);
    if (nk > 1) issue(1, 1);

    for (int t = 0; t < nk; ++t) {
        const int cur = t % NSTAGE;
        cp_wait<1>();          // stage t complete (≤1 group pending)
        __syncthreads();
        if (t + 2 < nk) issue(t + 2, (t + 2) % NSTAGE);

        const unsigned as_base = sh_base + (unsigned)((cur * 2 * STG_H) << 1);
        const unsigned bs_base = as_base + (unsigned)(STG_H << 1);

#pragma unroll
        for (int kk = 0; kk < BK; kk += 16) {
            unsigned a[2][4], b[4][4];
#pragma unroll
            for (int mt = 0; mt < 2; ++mt) {
                unsigned addr = as_base + (unsigned)((a_off[mt] + kk) << 1);
                asm volatile(
                    "ldmatrix.sync.aligned.m8n8.x4.shared.b16 {%0,%1,%2,%3}, [%4];"
                    : "=r"(a[mt][0]), "=r"(a[mt][1]), "=r"(a[mt][2]), "=r"(a[mt][3])
                    : "r"(addr));
            }
#pragma unroll
            for (int bt = 0; bt < 4; ++bt) {
                unsigned addr = bs_base + (unsigned)((b_off[bt] + kk) << 1);
                asm volatile(
                    "ldmatrix.sync.aligned.m8n8.x4.shared.b16 {%0,%1,%2,%3}, [%4];"
                    : "=r"(b[bt][0]), "=r"(b[bt][1]), "=r"(b[bt][2]), "=r"(b[bt][3])
                    : "r"(addr));
            }
#pragma unroll
            for (int mt = 0; mt < 2; ++mt)
#pragma unroll
                for (int nt = 0; nt < 8; ++nt) {
                    unsigned b0 = b[nt >> 1][(nt & 1)];
                    unsigned b1 = b[nt >> 1][2 + (nt & 1)];
                    asm volatile(
                        "mma.sync.aligned.m16n8k16.row.col.f32.f16.f16.f32 "
                        "{%0,%1,%2,%3}, {%4,%5,%6,%7}, {%8,%9}, {%0,%1,%2,%3};"
                        : "+f"(acc[mt][nt][0]), "+f"(acc[mt][nt][1]),
                          "+f"(acc[mt][nt][2]), "+f"(acc[mt][nt][3])
                        : "r"(a[mt][0]), "r"(a[mt][1]), "r"(a[mt][2]), "r"(a[mt][3]),
                          "r"(b0), "r"(b1));
                }
        }
        __syncthreads();   // all reads of stage done before it is refilled
    }

    const int gid = lane >> 2;
    const int tig = lane & 3;
#pragma unroll
    for (int mt = 0; mt < 2; ++mt)
#pragma unroll
        for (int nt = 0; nt < 8; ++nt) {
            int m = bm + wm0 + mt * 16 + gid;
            int n = bn + wn0 + nt * 8 + tig * 2;
            if (n < N) {
                float v0 = acc[mt][nt][0], v1 = acc[mt][nt][1];
                float v2 = acc[mt][nt][2], v3 = acc[mt][nt][3];
                if (epi == 1) {
                    float b0v = bias[n], b1v = bias[n + 1];
                    v0 = softplusf(v0 + b0v); v1 = softplusf(v1 + b1v);
                    v2 = softplusf(v2 + b0v); v3 = softplusf(v3 + b1v);
                }
                *reinterpret_cast<float2*>(C + (size_t)m * ldc + n) =
                    make_float2(v0, v1);
                *reinterpret_cast<float2*>(C + (size_t)(m + 8) * ldc + n) =
                    make_float2(v2, v3);
            }
        }
}

// ---------------------------------------------------------------------------
// conv + silu; emits fp32 (scan) and fp16 (x_proj A, bit-identical cvt).
// ---------------------------------------------------------------------------
__global__ __launch_bounds__(256)
void conv_silu_k(const float* __restrict__ xz, const float* __restrict__ w,
                 const float* __restrict__ cb, float* __restrict__ uc,
                 __half* __restrict__ uch)
{
    int idx = blockIdx.x * blockDim.x + threadIdx.x;
    if (idx >= NROWS * DINNER) return;
    int d   = idx & (DINNER - 1);
    int row = idx >> 11;
    int l   = row & (L_SEQ - 1);
    int b   = row >> 11;

    const float4 wv = *reinterpret_cast<const float4*>(w + (size_t)d * 4);
    const float* up = xz + (size_t)b * L_SEQ * (2 * DINNER) + d;
    const size_t S = 2 * DINNER;

    float acc = cb[d] + wv.w * up[(size_t)l * S];
    if (l >= 1) acc += wv.z * up[(size_t)(l - 1) * S];
    if (l >= 2) acc += wv.y * up[(size_t)(l - 2) * S];
    if (l >= 3) acc += wv.x * up[(size_t)(l - 3) * S];

    float v = acc / (1.f + __expf(-acc));
    uc[idx]  = v;
    uch[idx] = __float2half_rn(v);
}

// reduce split-K partials; fp32 (scan B/C) + fp16 (dt_proj A)
__global__ void reduce_split(const float* __restrict__ part,
                             float* __restrict__ out,
                             __half* __restrict__ outh, int n)
{
    int i = blockIdx.x * blockDim.x + threadIdx.x;
    if (i < n) {
        float s = 0.f;
#pragma unroll
        for (int z = 0; z < KSPLIT; ++z) s += part[(size_t)z * n + i];
        out[i]  = s;
        outh[i] = __float2half_rn(s);
    }
}

// ---------------------------------------------------------------------------
// Chunked selective scan (3 phases).
// ---------------------------------------------------------------------------
__global__ __launch_bounds__(256)
void scan_p1(const float* __restrict__ delta, const float* __restrict__ xdbl,
             const float* __restrict__ uc, const float* __restrict__ A_log,
             float* __restrict__ hfin, float* __restrict__ sumd)
{
    const int b = blockIdx.z;
    const int c = blockIdx.y;
    const int d = blockIdx.x * 256 + threadIdx.x;

    float na[DSTATE];
#pragma unroll
    for (int s = 0; s < DSTATE; ++s)
        na[s] = -__expf(A_log[(size_t)d * DSTATE + s]);

    float h[DSTATE];
#pragma unroll
    for (int s = 0; s < DSTATE; ++s) h[s] = 0.f;
    float sd = 0.f;

    __shared__ float bs[32][DSTATE];

    const int lbeg = c * CHUNK;
    for (int l0 = lbeg; l0 < lbeg + CHUNK; l0 += 32) {
        __syncthreads();
        for (int t = threadIdx.x; t < 32 * DSTATE; t += 256) {
            int i = t >> 4, j = t & 15;
            bs[i][j] = xdbl[(size_t)(b * L_SEQ + l0 + i) * XPROJ_N + 64 + j];
        }
        __syncthreads();
#pragma unroll 4
        for (int i = 0; i < 32; ++i) {
            size_t row = (size_t)b * L_SEQ + l0 + i;
            float t  = delta[row * DINNER + d];
            float u  = uc[row * DINNER + d];
            float tu = t * u;
            sd += t;
#pragma unroll
            for (int s = 0; s < DSTATE; ++s) {
                float dA = __expf(t * na[s]);
                h[s] = fmaf(dA, h[s], tu * bs[i][s]);
            }
        }
    }

    const size_t base = ((size_t)(b * NCHUNK + c) * DSTATE) * DINNER + d;
#pragma unroll
    for (int s = 0; s < DSTATE; ++s)
        hfin[base + (size_t)s * DINNER] = h[s];
    sumd[(size_t)(b * NCHUNK + c) * DINNER + d] = sd;
}

__global__ __launch_bounds__(256)
void scan_combine(const float* __restrict__ hfin, const float* __restrict__ sumd,
                  const float* __restrict__ A_log, float* __restrict__ hini)
{
    const int b = blockIdx.y;
    const int d = blockIdx.x * 256 + threadIdx.x;

    float na[DSTATE];
#pragma unroll
    for (int s = 0; s < DSTATE; ++s)
        na[s] = -__expf(A_log[(size_t)d * DSTATE + s]);

    float h[DSTATE];
#pragma unroll
    for (int s = 0; s < DSTATE; ++s) h[s] = 0.f;

    for (int c = 0; c < NCHUNK; ++c) {
        const size_t base = ((size_t)(b * NCHUNK + c) * DSTATE) * DINNER + d;
#pragma unroll
        for (int s = 0; s < DSTATE; ++s)
            hini[base + (size_t)s * DINNER] = h[s];
        float sd = sumd[(size_t)(b * NCHUNK + c) * DINNER + d];
#pragma unroll
        for (int s = 0; s < DSTATE; ++s) {
            float pA = __expf(sd * na[s]);
            h[s] = fmaf(pA, h[s], hfin[base + (size_t)s * DINNER]);
        }
    }
}

__global__ __launch_bounds__(256)
void scan_p3(const float* __restrict__ delta, const float* __restrict__ xdbl,
             const float* __restrict__ uc, const float* __restrict__ xz,
             const float* __restrict__ A_log, const float* __restrict__ Dv,
             const float* __restrict__ hini, __half* __restrict__ yh)
{
    const int b = blockIdx.z;
    const int c = blockIdx.y;
    const int d = blockIdx.x * 256 + threadIdx.x;

    float na[DSTATE];
#pragma unroll
    for (int s = 0; s < DSTATE; ++s)
        na[s] = -__expf(A_log[(size_t)d * DSTATE + s]);

    float h[DSTATE];
    {
        const size_t base = ((size_t)(b * NCHUNK + c) * DSTATE) * DINNER + d;
#pragma unroll
        for (int s = 0; s < DSTATE; ++s)
            h[s] = hini[base + (size_t)s * DINNER];
    }

    const float Dd = Dv[d];
    __shared__ float bc[32][32];

    const int lbeg = c * CHUNK;
    for (int l0 = lbeg; l0 < lbeg + CHUNK; l0 += 32) {
        __syncthreads();
        for (int t = threadIdx.x; t < 1024; t += 256) {
            int i = t >> 5, j = t & 31;
            bc[i][j] = xdbl[(size_t)(b * L_SEQ + l0 + i) * XPROJ_N + 64 + j];
        }
        __syncthreads();
#pragma unroll 4
        for (int i = 0; i < 32; ++i) {
            size_t row = (size_t)b * L_SEQ + l0 + i;
            float t  = delta[row * DINNER + d];
            float u  = uc[row * DINNER + d];
            float tu = t * u;
            float yv = 0.f;
#pragma unroll
            for (int s = 0; s < DSTATE; ++s) {
                float dA = __expf(t * na[s]);
                h[s] = fmaf(dA, h[s], tu * bc[i][s]);
                yv   = fmaf(h[s], bc[i][16 + s], yv);
            }
            float zv = xz[row * (2 * DINNER) + DINNER + d];
            float g  = zv / (1.f + __expf(-zv));
            yh[row * DINNER + d] = __float2half_rn((yv + u * Dd) * g);
        }
    }
}

// ---------------------------------------------------------------------------
extern "C" void kernel_launch(void* const* d_in, const int* in_sizes, int n_in,
                              void* d_out, int out_size)
{
    const float* x        = (const float*)d_in[0];
    const float* W_in     = (const float*)d_in[1];
    const float* conv_w   = (const float*)d_in[2];
    const float* conv_b   = (const float*)d_in[3];
    const float* W_xproj  = (const float*)d_in[4];
    const float* W_dtproj = (const float*)d_in[5];
    const float* dt_bias  = (const float*)d_in[6];
    const float* A_log    = (const float*)d_in[7];
    const float* Dv       = (const float*)d_in[8];
    const float* W_out    = (const float*)d_in[9];
    float* out = (float*)d_out;

    float *xz, *uc, *xpart, *xdbl, *delta, *hfin, *hini, *sumd;
    __half *xh, *whin, *whxp, *whdt, *whout, *uch, *xdblh, *yh;
    cudaGetSymbolAddress((void**)&xz,    g_xz);
    cudaGetSymbolAddress((void**)&uc,    g_uc);
    cudaGetSymbolAddress((void**)&xpart, g_xpart);
    cudaGetSymbolAddress((void**)&xdbl,  g_xdbl);
    cudaGetSymbolAddress((void**)&delta, g_delta);
    cudaGetSymbolAddress((void**)&hfin,  g_hfin);
    cudaGetSymbolAddress((void**)&hini,  g_hini);
    cudaGetSymbolAddress((void**)&sumd,  g_sumd);
    cudaGetSymbolAddress((void**)&xh,    g_xh);
    cudaGetSymbolAddress((void**)&whin,  g_whin);
    cudaGetSymbolAddress((void**)&whxp,  g_whxp);
    cudaGetSymbolAddress((void**)&whdt,  g_whdt);
    cudaGetSymbolAddress((void**)&whout, g_whout);
    cudaGetSymbolAddress((void**)&uch,   g_uch);
    cudaGetSymbolAddress((void**)&xdblh, g_xdblh);
    cudaGetSymbolAddress((void**)&yh,    g_yh);

    cudaFuncSetAttribute(mma_tn,
        cudaFuncAttributeMaxDynamicSharedMemorySize, MMA_SMEM_BYTES);

    dim3 blk(256);

    // 0. convert x + all weights to fp16 (bit-identical to in-loop cvt)
    f2h_multi<<<dim3(2048, 5), blk>>>(
        x,        xh,    NROWS * DMODEL,
        W_in,     whin,  2 * DINNER * DMODEL,
        W_xproj,  whxp,  XPROJ_N * DINNER,
        W_dtproj, whdt,  DINNER * 64,
        W_out,    whout, DMODEL * DINNER);

    // 1. in_proj: xz[4096,4096] = x @ W_in^T  (K=1024)
    mma_tn<<<dim3(32, 32, 1), blk, MMA_SMEM_BYTES>>>(xh, whin, xz,
        NROWS, 2 * DINNER, DMODEL, DMODEL, DMODEL, 2 * DINNER,
        nullptr, 0, DMODEL);

    // 2. depthwise conv + silu (emits fp32 + fp16)
    conv_silu_k<<<(NROWS * DINNER) / 256, blk>>>(xz, conv_w, conv_b, uc, uch);

    // 3. x_proj (split-K x8): x_dbl[4096,96] = u_c @ W_xproj^T (K=2048)
    mma_tn<<<dim3(1, 32, KSPLIT), blk, MMA_SMEM_BYTES>>>(uch, whxp, xpart,
        NROWS, XPROJ_N, DINNER, DINNER, DINNER, XPROJ_N,
        nullptr, 0, DINNER / KSPLIT);
    reduce_split<<<(NROWS * XPROJ_N + 255) / 256, blk>>>(
        xpart, xdbl, xdblh, NROWS * XPROJ_N);

    // 4. dt_proj + softplus: delta[4096,2048] (K=64)
    mma_tn<<<dim3(16, 32, 1), blk, MMA_SMEM_BYTES>>>(xdblh, whdt, delta,
        NROWS, DINNER, 64, XPROJ_N, 64, DINNER,
        dt_bias, 1, 64);

    // 5. chunked selective scan + skip + gate (y written as fp16)
    scan_p1<<<dim3(DINNER / 256, NCHUNK, NB), blk>>>(
        delta, xdbl, uc, A_log, hfin, sumd);
    scan_combine<<<dim3(DINNER / 256, NB), blk>>>(hfin, sumd, A_log, hini);
    scan_p3<<<dim3(DINNER / 256, NCHUNK, NB), blk>>>(
        delta, xdbl, uc, xz, A_log, Dv, hini, yh);

    // 6. out_proj: out[4096,1024] = y @ W_out^T (K=2048)
    mma_tn<<<dim3(8, 32, 1), blk, MMA_SMEM_BYTES>>>(yh, whout, out,
        NROWS, DMODEL, DINNER, DINNER, DINNER, DMODEL,
        nullptr, 0, DINNER);
}

// round 11
// speedup vs baseline: 1.6078x; 1.0533x over previous
#include <cuda_runtime.h>
#include <cuda_fp16.h>
#include <math.h>

// ---------------------------------------------------------------------------
// Mamba block forward. fp16 mma.sync GEMMs (cp.async 4-stage ring, padded
// commit-group accounting so wait_group<2> is valid for ALL nk) + chunked
// parallel selective scan with geometric-dA fast path.
//   B=2, L=2048, d_model=1024, d_inner=2048, d_state=16, d_conv=4, dt_rank=64
// tcgen05 unavailable: harness PTX target is compute_103 (no 'a' suffix).
// ---------------------------------------------------------------------------

#define L_SEQ   2048
#define NB      2
#define DMODEL  1024
#define DINNER  2048
#define DSTATE  16
#define NROWS   (NB * L_SEQ)     // 4096
#define XPROJ_N 96
#define KSPLIT  8
#define CHUNK   128
#define NCHUNK  (L_SEQ / CHUNK)  // 16

// fp32 scratch
__device__ float g_xz   [(size_t)NROWS * 2 * DINNER];
__device__ float g_uc   [(size_t)NROWS * DINNER];
__device__ float g_xpart[(size_t)KSPLIT * NROWS * XPROJ_N];
__device__ float g_xdbl [(size_t)NROWS * XPROJ_N];
__device__ float g_delta[(size_t)NROWS * DINNER];
__device__ float g_hfin [(size_t)NB * NCHUNK * DSTATE * DINNER];
__device__ float g_hini [(size_t)NB * NCHUNK * DSTATE * DINNER];
__device__ float g_sumd [(size_t)NB * NCHUNK * DINNER];
// fp16 operands
__device__ __half g_xh   [(size_t)NROWS * DMODEL];
__device__ __half g_whin [(size_t)2 * DINNER * DMODEL];
__device__ __half g_whxp [(size_t)XPROJ_N * DINNER];
__device__ __half g_whdt [(size_t)DINNER * 64];
__device__ __half g_whout[(size_t)DMODEL * DINNER];
__device__ __half g_uch  [(size_t)NROWS * DINNER];
__device__ __half g_xdblh[(size_t)NROWS * XPROJ_N];
__device__ __half g_yh   [(size_t)NROWS * DINNER];

__device__ __forceinline__ float softplusf(float x) {
    return x > 20.f ? x : log1pf(__expf(x));
}
__device__ __forceinline__ unsigned smem_u32(const void* p) {
    return (unsigned)__cvta_generic_to_shared(p);
}
__device__ __forceinline__ void cp_async16(unsigned saddr, const void* gptr, int sz) {
    asm volatile("cp.async.cg.shared.global [%0], [%1], 16, %2;"
                 :: "r"(saddr), "l"(gptr), "r"(sz));
}
__device__ __forceinline__ void cp_commit() {
    asm volatile("cp.async.commit_group;" ::: "memory");
}
template<int N>
__device__ __forceinline__ void cp_wait() {
    asm volatile("cp.async.wait_group %0;" :: "n"(N) : "memory");
}

// load na[] and detect geometric structure na[s] == (s+1)*na[0]
__device__ __forceinline__ bool load_na(const float* __restrict__ A_log,
                                        int d, float* na)
{
    bool geo = true;
#pragma unroll
    for (int s = 0; s < DSTATE; ++s) {
        na[s] = -__expf(A_log[(size_t)d * DSTATE + s]);
        geo = geo && (fabsf(na[s] - (float)(s + 1) * na[0])
                      <= 1e-5f * fabsf(na[s]));
    }
    return geo;
}

// ---------------------------------------------------------------------------
// Multi-tensor fp32 -> fp16 conversion.
// ---------------------------------------------------------------------------
__global__ __launch_bounds__(256)
void f2h_multi(const float* __restrict__ s0, __half* d0, int n0,
               const float* __restrict__ s1, __half* d1, int n1,
               const float* __restrict__ s2, __half* d2, int n2,
               const float* __restrict__ s3, __half* d3, int n3,
               const float* __restrict__ s4, __half* d4, int n4)
{
    const float* s; __half* d; int n;
    switch (blockIdx.y) {
        case 0: s = s0; d = d0; n = n0; break;
        case 1: s = s1; d = d1; n = n1; break;
        case 2: s = s2; d = d2; n = n2; break;
        case 3: s = s3; d = d3; n = n3; break;
        default: s = s4; d = d4; n = n4; break;
    }
    int nq = n >> 2;
    for (int i = blockIdx.x * blockDim.x + threadIdx.x; i < nq;
         i += gridDim.x * blockDim.x) {
        float4 v = *reinterpret_cast<const float4*>(s + (size_t)i * 4);
        __half2 h0 = __floats2half2_rn(v.x, v.y);
        __half2 h1 = __floats2half2_rn(v.z, v.w);
        *reinterpret_cast<uint2*>(d + (size_t)i * 4) =
            make_uint2(*(unsigned*)&h0, *(unsigned*)&h1);
    }
}

// ---------------------------------------------------------------------------
// C[M,N] (fp32) = A[M,K] @ B[N,K]^T, fp16 operands via cp.async 4-stage ring.
// Commit-group accounting: exactly (t+3) groups are committed before the wait
// at iteration t (empty groups pad the tail), so wait_group<2> always implies
// stage t is resident — valid for any nk >= 1.
// ---------------------------------------------------------------------------
#define BK      32
#define BSTH    40                      // halfs per row (32 + 8 pad)
#define STG_H   (128 * BSTH)            // halfs per array per stage
#define NSTAGE  4
#define MMA_SMEM_BYTES (NSTAGE * 2 * STG_H * 2)   // 81920

__global__ __launch_bounds__(256, 2)
void mma_tn(const __half* __restrict__ A, const __half* __restrict__ B,
            float* __restrict__ C, int M, int N, int K,
            int lda, int ldb, int ldc,
            const float* __restrict__ bias, int epi, int kPerSplit)
{
    extern __shared__ __align__(16) __half sh[];

    const int tid  = threadIdx.x;
    const int lane = tid & 31;
    const int wid  = tid >> 5;
    const int wm0  = (wid >> 1) << 5;
    const int wn0  = (wid & 1) << 6;

    const int bm = blockIdx.y << 7;
    const int bn = blockIdx.x << 7;
    const int kbeg = blockIdx.z * kPerSplit;
    C += (size_t)blockIdx.z * (size_t)M * (size_t)ldc;

    float acc[2][8][4];
#pragma unroll
    for (int mt = 0; mt < 2; ++mt)
#pragma unroll
        for (int nt = 0; nt < 8; ++nt)
#pragma unroll
            for (int r = 0; r < 4; ++r) acc[mt][nt][r] = 0.f;

    int a_off[2], b_off[4];
#pragma unroll
    for (int mt = 0; mt < 2; ++mt) {
        int row = wm0 + mt * 16 + ((lane >> 3) & 1) * 8 + (lane & 7);
        int col = (lane >> 4) * 8;
        a_off[mt] = row * BSTH + col;
    }
#pragma unroll
    for (int bt = 0; bt < 4; ++bt) {
        int row = wn0 + bt * 16 + ((lane >> 3) & 1) * 8 + (lane & 7);
        int col = (lane >> 4) * 8;
        b_off[bt] = row * BSTH + col;
    }
    const unsigned sh_base = smem_u32(sh);

    const int lrow = tid >> 2;          // 0..63
    const int lc8  = (tid & 3) << 3;    // 0,8,16,24

    const __half* gA = A + (size_t)bm * lda + kbeg;
    const __half* gB = B + (size_t)bn * ldb + kbeg;
    int bsz[2]; const __half* gBrow[2]; const __half* gArow[2];
#pragma unroll
    for (int i = 0; i < 2; ++i) {
        int r = lrow + (i << 6);
        gArow[i] = gA + (size_t)r * lda + lc8;
        int rb = (bn + r < N) ? r : 0;
        bsz[i] = (bn + r < N) ? 16 : 0;
        gBrow[i] = gB + (size_t)rb * ldb + lc8;
    }

    const int nk = kPerSplit >> 5;

    // commits a group ALWAYS (real loads if t < nk, empty group otherwise)
    auto issue = [&](int t) {
        if (t < nk) {
            int s = t % NSTAGE;
            unsigned sa = sh_base + (unsigned)((s * 2 * STG_H) << 1);
            unsigned sb = sa + (unsigned)(STG_H << 1);
            int koff = t * BK;
#pragma unroll
            for (int i = 0; i < 2; ++i) {
                int r = lrow + (i << 6);
                cp_async16(sa + (unsigned)((r * BSTH + lc8) << 1),
                           gArow[i] + koff, 16);
                cp_async16(sb + (unsigned)((r * BSTH + lc8) << 1),
                           gBrow[i] + koff, bsz[i]);
            }
        }
        cp_commit();
    };

    issue(0);   // groups 0,1,2 committed (empty if past nk)
    issue(1);
    issue(2);

    for (int t = 0; t < nk; ++t) {
        const int cur = t % NSTAGE;
        // committed == t+3 here; wait<2> => completed >= t+1 => stage t ready
        cp_wait<2>();
        __syncthreads();       // all reads of stage (t+3)%4 finished last iter
        issue(t + 3);

        const unsigned as_base = sh_base + (unsigned)((cur * 2 * STG_H) << 1);
        const unsigned bs_base = as_base + (unsigned)(STG_H << 1);

#pragma unroll
        for (int kk = 0; kk < BK; kk += 16) {
            unsigned a[2][4], b[4][4];
#pragma unroll
            for (int mt = 0; mt < 2; ++mt) {
                unsigned addr = as_base + (unsigned)((a_off[mt] + kk) << 1);
                asm volatile(
                    "ldmatrix.sync.aligned.m8n8.x4.shared.b16 {%0,%1,%2,%3}, [%4];"
                    : "=r"(a[mt][0]), "=r"(a[mt][1]), "=r"(a[mt][2]), "=r"(a[mt][3])
                    : "r"(addr));
            }
#pragma unroll
            for (int bt = 0; bt < 4; ++bt) {
                unsigned addr = bs_base + (unsigned)((b_off[bt] + kk) << 1);
                asm volatile(
                    "ldmatrix.sync.aligned.m8n8.x4.shared.b16 {%0,%1,%2,%3}, [%4];"
                    : "=r"(b[bt][0]), "=r"(b[bt][1]), "=r"(b[bt][2]), "=r"(b[bt][3])
                    : "r"(addr));
            }
#pragma unroll
            for (int mt = 0; mt < 2; ++mt)
#pragma unroll
                for (int nt = 0; nt < 8; ++nt) {
                    unsigned b0 = b[nt >> 1][(nt & 1)];
                    unsigned b1 = b[nt >> 1][2 + (nt & 1)];
                    asm volatile(
                        "mma.sync.aligned.m16n8k16.row.col.f32.f16.f16.f32 "
                        "{%0,%1,%2,%3}, {%4,%5,%6,%7}, {%8,%9}, {%0,%1,%2,%3};"
                        : "+f"(acc[mt][nt][0]), "+f"(acc[mt][nt][1]),
                          "+f"(acc[mt][nt][2]), "+f"(acc[mt][nt][3])
                        : "r"(a[mt][0]), "r"(a[mt][1]), "r"(a[mt][2]), "r"(a[mt][3]),
                          "r"(b0), "r"(b1));
                }
        }
    }

    const int gid = lane >> 2;
    const int tig = lane & 3;
#pragma unroll
    for (int mt = 0; mt < 2; ++mt)
#pragma unroll
        for (int nt = 0; nt < 8; ++nt) {
            int m = bm + wm0 + mt * 16 + gid;
            int n = bn + wn0 + nt * 8 + tig * 2;
            if (n < N) {
                float v0 = acc[mt][nt][0], v1 = acc[mt][nt][1];
                float v2 = acc[mt][nt][2], v3 = acc[mt][nt][3];
                if (epi == 1) {
                    float b0v = bias[n], b1v = bias[n + 1];
                    v0 = softplusf(v0 + b0v); v1 = softplusf(v1 + b1v);
                    v2 = softplusf(v2 + b0v); v3 = softplusf(v3 + b1v);
                }
                *reinterpret_cast<float2*>(C + (size_t)m * ldc + n) =
                    make_float2(v0, v1);
                *reinterpret_cast<float2*>(C + (size_t)(m + 8) * ldc + n) =
                    make_float2(v2, v3);
            }
        }
}

// ---------------------------------------------------------------------------
__global__ __launch_bounds__(256)
void conv_silu_k(const float* __restrict__ xz, const float* __restrict__ w,
                 const float* __restrict__ cb, float* __restrict__ uc,
                 __half* __restrict__ uch)
{
    int idx = blockIdx.x * blockDim.x + threadIdx.x;
    if (idx >= NROWS * DINNER) return;
    int d   = idx & (DINNER - 1);
    int row = idx >> 11;
    int l   = row & (L_SEQ - 1);
    int b   = row >> 11;

    const float4 wv = *reinterpret_cast<const float4*>(w + (size_t)d * 4);
    const float* up = xz + (size_t)b * L_SEQ * (2 * DINNER) + d;
    const size_t S = 2 * DINNER;

    float acc = cb[d] + wv.w * up[(size_t)l * S];
    if (l >= 1) acc += wv.z * up[(size_t)(l - 1) * S];
    if (l >= 2) acc += wv.y * up[(size_t)(l - 2) * S];
    if (l >= 3) acc += wv.x * up[(size_t)(l - 3) * S];

    float v = acc / (1.f + __expf(-acc));
    uc[idx]  = v;
    uch[idx] = __float2half_rn(v);
}

__global__ void reduce_split(const float* __restrict__ part,
                             float* __restrict__ out,
                             __half* __restrict__ outh, int n)
{
    int i = blockIdx.x * blockDim.x + threadIdx.x;
    if (i < n) {
        float s = 0.f;
#pragma unroll
        for (int z = 0; z < KSPLIT; ++z) s += part[(size_t)z * n + i];
        out[i]  = s;
        outh[i] = __float2half_rn(s);
    }
}

// ---------------------------------------------------------------------------
// Chunked selective scan (3 phases) with geometric-dA fast path.
// ---------------------------------------------------------------------------
__global__ __launch_bounds__(256)
void scan_p1(const float* __restrict__ delta, const float* __restrict__ xdbl,
             const float* __restrict__ uc, const float* __restrict__ A_log,
             float* __restrict__ hfin, float* __restrict__ sumd)
{
    const int b = blockIdx.z;
    const int c = blockIdx.y;
    const int d = blockIdx.x * 256 + threadIdx.x;

    float na[DSTATE];
    const bool geo = load_na(A_log, d, na);
    const float na0 = na[0];

    float h[DSTATE];
#pragma unroll
    for (int s = 0; s < DSTATE; ++s) h[s] = 0.f;
    float sd = 0.f;

    __shared__ float bs[32][DSTATE];

    const int lbeg = c * CHUNK;
    for (int l0 = lbeg; l0 < lbeg + CHUNK; l0 += 32) {
        __syncthreads();
        for (int t = threadIdx.x; t < 32 * DSTATE; t += 256) {
            int i = t >> 4, j = t & 15;
            bs[i][j] = xdbl[(size_t)(b * L_SEQ + l0 + i) * XPROJ_N + 64 + j];
        }
        __syncthreads();
        if (geo) {
#pragma unroll 2
            for (int i = 0; i < 32; ++i) {
                size_t row = (size_t)b * L_SEQ + l0 + i;
                float t  = delta[row * DINNER + d];
                float u  = uc[row * DINNER + d];
                float tu = t * u;
                sd += t;
                float p  = __expf(t * na0);
                float p2 = p * p;
                float ra = p, rb = p2;
                h[0] = fmaf(ra, h[0], tu * bs[i][0]);
                h[1] = fmaf(rb, h[1], tu * bs[i][1]);
#pragma unroll
                for (int s = 2; s < DSTATE; s += 2) {
                    ra *= p2; h[s]     = fmaf(ra, h[s],     tu * bs[i][s]);
                    rb *= p2; h[s + 1] = fmaf(rb, h[s + 1], tu * bs[i][s + 1]);
                }
            }
        } else {
#pragma unroll 2
            for (int i = 0; i < 32; ++i) {
                size_t row = (size_t)b * L_SEQ + l0 + i;
                float t  = delta[row * DINNER + d];
                float u  = uc[row * DINNER + d];
                float tu = t * u;
                sd += t;
#pragma unroll
                for (int s = 0; s < DSTATE; ++s) {
                    float dA = __expf(t * na[s]);
                    h[s] = fmaf(dA, h[s], tu * bs[i][s]);
                }
            }
        }
    }

    const size_t base = ((size_t)(b * NCHUNK + c) * DSTATE) * DINNER + d;
#pragma unroll
    for (int s = 0; s < DSTATE; ++s)
        hfin[base + (size_t)s * DINNER] = h[s];
    sumd[(size_t)(b * NCHUNK + c) * DINNER + d] = sd;
}

__global__ __launch_bounds__(256)
void scan_combine(const float* __restrict__ hfin, const float* __restrict__ sumd,
                  const float* __restrict__ A_log, float* __restrict__ hini)
{
    const int b = blockIdx.y;
    const int d = blockIdx.x * 256 + threadIdx.x;

    float na[DSTATE];
    load_na(A_log, d, na);

    float h[DSTATE];
#pragma unroll
    for (int s = 0; s < DSTATE; ++s) h[s] = 0.f;

    for (int c = 0; c < NCHUNK; ++c) {
        const size_t base = ((size_t)(b * NCHUNK + c) * DSTATE) * DINNER + d;
#pragma unroll
        for (int s = 0; s < DSTATE; ++s)
            hini[base + (size_t)s * DINNER] = h[s];
        float sd = sumd[(size_t)(b * NCHUNK + c) * DINNER + d];
#pragma unroll
        for (int s = 0; s < DSTATE; ++s) {
            float pA = __expf(sd * na[s]);
            h[s] = fmaf(pA, h[s], hfin[base + (size_t)s * DINNER]);
        }
    }
}

__global__ __launch_bounds__(256)
void scan_p3(const float* __restrict__ delta, const float* __restrict__ xdbl,
             const float* __restrict__ uc, const float* __restrict__ xz,
             const float* __restrict__ A_log, const float* __restrict__ Dv,
             const float* __restrict__ hini, __half* __restrict__ yh)
{
    const int b = blockIdx.z;
    const int c = blockIdx.y;
    const int d = blockIdx.x * 256 + threadIdx.x;

    float na[DSTATE];
    const bool geo = load_na(A_log, d, na);
    const float na0 = na[0];

    float h[DSTATE];
    {
        const size_t base = ((size_t)(b * NCHUNK + c) * DSTATE) * DINNER + d;
#pragma unroll
        for (int s = 0; s < DSTATE; ++s)
            h[s] = hini[base + (size_t)s * DINNER];
    }

    const float Dd = Dv[d];
    __shared__ float bc[32][32];

    const int lbeg = c * CHUNK;
    for (int l0 = lbeg; l0 < lbeg + CHUNK; l0 += 32) {
        __syncthreads();
        for (int t = threadIdx.x; t < 1024; t += 256) {
            int i = t >> 5, j = t & 31;
            bc[i][j] = xdbl[(size_t)(b * L_SEQ + l0 + i) * XPROJ_N + 64 + j];
        }
        __syncthreads();
        if (geo) {
#pragma unroll 2
            for (int i = 0; i < 32; ++i) {
                size_t row = (size_t)b * L_SEQ + l0 + i;
                float t  = delta[row * DINNER + d];
                float u  = uc[row * DINNER + d];
                float tu = t * u;
                float yv = 0.f;
                float p  = __expf(t * na0);
                float p2 = p * p;
                float ra = p, rb = p2;
                h[0] = fmaf(ra, h[0], tu * bc[i][0]);
                yv = fmaf(h[0], bc[i][16], yv);
                h[1] = fmaf(rb, h[1], tu * bc[i][1]);
                yv = fmaf(h[1], bc[i][17], yv);
#pragma unroll
                for (int s = 2; s < DSTATE; s += 2) {
                    ra *= p2;
                    h[s] = fmaf(ra, h[s], tu * bc[i][s]);
                    yv = fmaf(h[s], bc[i][16 + s], yv);
                    rb *= p2;
                    h[s + 1] = fmaf(rb, h[s + 1], tu * bc[i][s + 1]);
                    yv = fmaf(h[s + 1], bc[i][17 + s], yv);
                }
                float zv = xz[row * (2 * DINNER) + DINNER + d];
                float g  = zv / (1.f + __expf(-zv));
                yh[row * DINNER + d] = __float2half_rn((yv + u * Dd) * g);
            }
        } else {
#pragma unroll 2
            for (int i = 0; i < 32; ++i) {
                size_t row = (size_t)b * L_SEQ + l0 + i;
                float t  = delta[row * DINNER + d];
                float u  = uc[row * DINNER + d];
                float tu = t * u;
                float yv = 0.f;
#pragma unroll
                for (int s = 0; s < DSTATE; ++s) {
                    float dA = __expf(t * na[s]);
                    h[s] = fmaf(dA, h[s], tu * bc[i][s]);
                    yv   = fmaf(h[s], bc[i][16 + s], yv);
                }
                float zv = xz[row * (2 * DINNER) + DINNER + d];
                float g  = zv / (1.f + __expf(-zv));
                yh[row * DINNER + d] = __float2half_rn((yv + u * Dd) * g);
            }
        }
    }
}

// ---------------------------------------------------------------------------
extern "C" void kernel_launch(void* const* d_in, const int* in_sizes, int n_in,
                              void* d_out, int out_size)
{
    const float* x        = (const float*)d_in[0];
    const float* W_in     = (const float*)d_in[1];
    const float* conv_w   = (const float*)d_in[2];
    const float* conv_b   = (const float*)d_in[3];
    const float* W_xproj  = (const float*)d_in[4];
    const float* W_dtproj = (const float*)d_in[5];
    const float* dt_bias  = (const float*)d_in[6];
    const float* A_log    = (const float*)d_in[7];
    const float* Dv       = (const float*)d_in[8];
    const float* W_out    = (const float*)d_in[9];
    float* out = (float*)d_out;

    float *xz, *uc, *xpart, *xdbl, *delta, *hfin, *hini, *sumd;
    __half *xh, *whin, *whxp, *whdt, *whout, *uch, *xdblh, *yh;
    cudaGetSymbolAddress((void**)&xz,    g_xz);
    cudaGetSymbolAddress((void**)&uc,    g_uc);
    cudaGetSymbolAddress((void**)&xpart, g_xpart);
    cudaGetSymbolAddress((void**)&xdbl,  g_xdbl);
    cudaGetSymbolAddress((void**)&delta, g_delta);
    cudaGetSymbolAddress((void**)&hfin,  g_hfin);
    cudaGetSymbolAddress((void**)&hini,  g_hini);
    cudaGetSymbolAddress((void**)&sumd,  g_sumd);
    cudaGetSymbolAddress((void**)&xh,    g_xh);
    cudaGetSymbolAddress((void**)&whin,  g_whin);
    cudaGetSymbolAddress((void**)&whxp,  g_whxp);
    cudaGetSymbolAddress((void**)&whdt,  g_whdt);
    cudaGetSymbolAddress((void**)&whout, g_whout);
    cudaGetSymbolAddress((void**)&uch,   g_uch);
    cudaGetSymbolAddress((void**)&xdblh, g_xdblh);
    cudaGetSymbolAddress((void**)&yh,    g_yh);

    cudaFuncSetAttribute(mma_tn,
        cudaFuncAttributeMaxDynamicSharedMemorySize, MMA_SMEM_BYTES);

    dim3 blk(256);

    // 0. convert x + all weights to fp16
    f2h_multi<<<dim3(2048, 5), blk>>>(
        x,        xh,    NROWS * DMODEL,
        W_in,     whin,  2 * DINNER * DMODEL,
        W_xproj,  whxp,  XPROJ_N * DINNER,
        W_dtproj, whdt,  DINNER * 64,
        W_out,    whout, DMODEL * DINNER);

    // 1. in_proj: xz[4096,4096] = x @ W_in^T  (K=1024)
    mma_tn<<<dim3(32, 32, 1), blk, MMA_SMEM_BYTES>>>(xh, whin, xz,
        NROWS, 2 * DINNER, DMODEL, DMODEL, DMODEL, 2 * DINNER,
        nullptr, 0, DMODEL);

    // 2. depthwise conv + silu (emits fp32 + fp16)
    conv_silu_k<<<(NROWS * DINNER) / 256, blk>>>(xz, conv_w, conv_b, uc, uch);

    // 3. x_proj (split-K x8): x_dbl[4096,96] = u_c @ W_xproj^T (K=2048)
    mma_tn<<<dim3(1, 32, KSPLIT), blk, MMA_SMEM_BYTES>>>(uch, whxp, xpart,
        NROWS, XPROJ_N, DINNER, DINNER, DINNER, XPROJ_N,
        nullptr, 0, DINNER / KSPLIT);
    reduce_split<<<(NROWS * XPROJ_N + 255) / 256, blk>>>(
        xpart, xdbl, xdblh, NROWS * XPROJ_N);

    // 4. dt_proj + softplus: delta[4096,2048] (K=64)
    mma_tn<<<dim3(16, 32, 1), blk, MMA_SMEM_BYTES>>>(xdblh, whdt, delta,
        NROWS, DINNER, 64, XPROJ_N, 64, DINNER,
        dt_bias, 1, 64);

    // 5. chunked selective scan + skip + gate
    scan_p1<<<dim3(DINNER / 256, NCHUNK, NB), blk>>>(
        delta, xdbl, uc, A_log, hfin, sumd);
    scan_combine<<<dim3(DINNER / 256, NB), blk>>>(hfin, sumd, A_log, hini);
    scan_p3<<<dim3(DINNER / 256, NCHUNK, NB), blk>>>(
        delta, xdbl, uc, xz, A_log, Dv, hini, yh);

    // 6. out_proj: out[4096,1024] = y @ W_out^T (K=2048)
    mma_tn<<<dim3(8, 32, 1), blk, MMA_SMEM_BYTES>>>(yh, whout, out,
        NROWS, DMODEL, DINNER, DINNER, DINNER, DMODEL,
        nullptr, 0, DINNER);
}

// round 12
// speedup vs baseline: 1.6877x; 1.0496x over previous
#include <cuda_runtime.h>
#include <cuda_fp16.h>
#include <math.h>

// ---------------------------------------------------------------------------
// Mamba block forward. fp16 mma.sync GEMMs: 128x64 CTA tile, 8 warps (32x32
// warp tile), cp.async 3-stage ring, 3 CTAs/SM target (regs<=85). Chunked
// parallel selective scan (geometric-dA fast path), fp16 delta/u in scan.
//   B=2, L=2048, d_model=1024, d_inner=2048, d_state=16, d_conv=4, dt_rank=64
// tcgen05 unavailable: harness PTX target is compute_103 (no 'a' suffix).
// ---------------------------------------------------------------------------

#define L_SEQ   2048
#define NB      2
#define DMODEL  1024
#define DINNER  2048
#define DSTATE  16
#define NROWS   (NB * L_SEQ)     // 4096
#define XPROJ_N 96
#define KSPLIT  8
#define CHUNK   128
#define NCHUNK  (L_SEQ / CHUNK)  // 16

// fp32 scratch
__device__ float g_xz    [(size_t)NROWS * 2 * DINNER];
__device__ float g_xpart [(size_t)KSPLIT * NROWS * XPROJ_N];
__device__ float g_xdbl  [(size_t)NROWS * XPROJ_N];
__device__ float g_hfin  [(size_t)NB * NCHUNK * DSTATE * DINNER];
__device__ float g_hini  [(size_t)NB * NCHUNK * DSTATE * DINNER];
__device__ float g_sumd  [(size_t)NB * NCHUNK * DINNER];
// fp16 operands / activations
__device__ __half g_xh    [(size_t)NROWS * DMODEL];
__device__ __half g_whin  [(size_t)2 * DINNER * DMODEL];
__device__ __half g_whxp  [(size_t)XPROJ_N * DINNER];
__device__ __half g_whdt  [(size_t)DINNER * 64];
__device__ __half g_whout [(size_t)DMODEL * DINNER];
__device__ __half g_uch   [(size_t)NROWS * DINNER];
__device__ __half g_xdblh [(size_t)NROWS * XPROJ_N];
__device__ __half g_deltah[(size_t)NROWS * DINNER];
__device__ __half g_yh    [(size_t)NROWS * DINNER];

__device__ __forceinline__ float softplusf(float x) {
    return x > 20.f ? x : log1pf(__expf(x));
}
__device__ __forceinline__ unsigned smem_u32(const void* p) {
    return (unsigned)__cvta_generic_to_shared(p);
}
__device__ __forceinline__ void cp_async16(unsigned saddr, const void* gptr, int sz) {
    asm volatile("cp.async.cg.shared.global [%0], [%1], 16, %2;"
                 :: "r"(saddr), "l"(gptr), "r"(sz));
}
__device__ __forceinline__ void cp_commit() {
    asm volatile("cp.async.commit_group;" ::: "memory");
}
template<int N>
__device__ __forceinline__ void cp_wait() {
    asm volatile("cp.async.wait_group %0;" :: "n"(N) : "memory");
}

// load na[] and detect geometric structure na[s] == (s+1)*na[0]
__device__ __forceinline__ bool load_na(const float* __restrict__ A_log,
                                        int d, float* na)
{
    bool geo = true;
#pragma unroll
    for (int s = 0; s < DSTATE; ++s) {
        na[s] = -__expf(A_log[(size_t)d * DSTATE + s]);
        geo = geo && (fabsf(na[s] - (float)(s + 1) * na[0])
                      <= 1e-5f * fabsf(na[s]));
    }
    return geo;
}

// ---------------------------------------------------------------------------
__global__ __launch_bounds__(256)
void f2h_multi(const float* __restrict__ s0, __half* d0, int n0,
               const float* __restrict__ s1, __half* d1, int n1,
               const float* __restrict__ s2, __half* d2, int n2,
               const float* __restrict__ s3, __half* d3, int n3,
               const float* __restrict__ s4, __half* d4, int n4)
{
    const float* s; __half* d; int n;
    switch (blockIdx.y) {
        case 0: s = s0; d = d0; n = n0; break;
        case 1: s = s1; d = d1; n = n1; break;
        case 2: s = s2; d = d2; n = n2; break;
        case 3: s = s3; d = d3; n = n3; break;
        default: s = s4; d = d4; n = n4; break;
    }
    int nq = n >> 2;
    for (int i = blockIdx.x * blockDim.x + threadIdx.x; i < nq;
         i += gridDim.x * blockDim.x) {
        float4 v = *reinterpret_cast<const float4*>(s + (size_t)i * 4);
        __half2 h0 = __floats2half2_rn(v.x, v.y);
        __half2 h1 = __floats2half2_rn(v.z, v.w);
        *reinterpret_cast<uint2*>(d + (size_t)i * 4) =
            make_uint2(*(unsigned*)&h0, *(unsigned*)&h1);
    }
}

// ---------------------------------------------------------------------------
// C[M,N] = A[M,K] @ B[N,K]^T, fp16 operands, m16n8k16. 128x64 CTA tile,
// 8 warps = 4m x 2n (warp tile 32x32). cp.async 3-stage ring with padded
// commit groups (wait_group<1> valid for all nk). EPI=0: fp32 C.
// EPI=1: C = half(softplus(acc + bias[n])).
// ---------------------------------------------------------------------------
#define BK      32
#define BSTH    40                       // halfs per row (32 + 8 pad)
#define A_STG   (128 * BSTH)
#define B_STG   (64 * BSTH)
#define STG_H   (A_STG + B_STG)          // 7680 halfs
#define NSTAGE  3
#define MMA_SMEM_BYTES (NSTAGE * STG_H * 2)   // 46080

template<int EPI>
__global__ __launch_bounds__(256, 3)
void mma_tn(const __half* __restrict__ A, const __half* __restrict__ B,
            void* __restrict__ Cv, int M, int N, int K,
            int lda, int ldb, int ldc,
            const float* __restrict__ bias, int kPerSplit)
{
    extern __shared__ __align__(16) __half sh[];

    const int tid  = threadIdx.x;
    const int lane = tid & 31;
    const int wid  = tid >> 5;
    const int wm0  = (wid >> 1) << 5;   // 0,32,64,96
    const int wn0  = (wid & 1) << 5;    // 0,32

    const int bm = blockIdx.y << 7;
    const int bn = blockIdx.x << 6;
    const int kbeg = blockIdx.z * kPerSplit;

    float acc[2][4][4];
#pragma unroll
    for (int mt = 0; mt < 2; ++mt)
#pragma unroll
        for (int nt = 0; nt < 4; ++nt)
#pragma unroll
            for (int r = 0; r < 4; ++r) acc[mt][nt][r] = 0.f;

    int a_off[2], b_off[2];
#pragma unroll
    for (int mt = 0; mt < 2; ++mt) {
        int row = wm0 + mt * 16 + ((lane >> 3) & 1) * 8 + (lane & 7);
        int col = (lane >> 4) * 8;
        a_off[mt] = row * BSTH + col;
    }
#pragma unroll
    for (int bt = 0; bt < 2; ++bt) {
        int row = wn0 + bt * 16 + ((lane >> 3) & 1) * 8 + (lane & 7);
        int col = (lane >> 4) * 8;
        b_off[bt] = A_STG + row * BSTH + col;   // B region after A within stage
    }
    const unsigned sh_base = smem_u32(sh);

    const int lrow = tid >> 2;          // 0..63
    const int lc8  = (tid & 3) << 3;    // 0,8,16,24

    const __half* gA0 = A + (size_t)(bm + lrow) * lda + kbeg + lc8;
    const __half* gA1 = gA0 + (size_t)64 * lda;
    int rb  = (bn + lrow < N) ? lrow : 0;
    int bsz = (bn + lrow < N) ? 16 : 0;
    const __half* gB0 = B + (size_t)(bn + rb) * ldb + kbeg + lc8;

    const int nk = kPerSplit >> 5;
    const unsigned s_arow0 = (unsigned)((lrow * BSTH + lc8) << 1);
    const unsigned s_arow1 = (unsigned)(((lrow + 64) * BSTH + lc8) << 1);
    const unsigned s_brow  = (unsigned)((A_STG + lrow * BSTH + lc8) << 1);

    auto issue = [&](int t) {
        if (t < nk) {
            unsigned sb = sh_base + (unsigned)(((t % NSTAGE) * STG_H) << 1);
            int koff = t * BK;
            cp_async16(sb + s_arow0, gA0 + koff, 16);
            cp_async16(sb + s_arow1, gA1 + koff, 16);
            cp_async16(sb + s_brow,  gB0 + koff, bsz);
        }
        cp_commit();
    };

    issue(0);
    issue(1);

    for (int t = 0; t < nk; ++t) {
        // committed == t+2 here; wait<1> => completed >= t+1 => stage t ready
        cp_wait<1>();
        __syncthreads();   // all reads of stage (t+2)%3 finished (iter t-1)
        issue(t + 2);

        const unsigned st_base = sh_base + (unsigned)(((t % NSTAGE) * STG_H) << 1);

#pragma unroll
        for (int kk = 0; kk < BK; kk += 16) {
            unsigned a[2][4], b[2][4];
#pragma unroll
            for (int mt = 0; mt < 2; ++mt) {
                unsigned addr = st_base + (unsigned)((a_off[mt] + kk) << 1);
                asm volatile(
                    "ldmatrix.sync.aligned.m8n8.x4.shared.b16 {%0,%1,%2,%3}, [%4];"
                    : "=r"(a[mt][0]), "=r"(a[mt][1]), "=r"(a[mt][2]), "=r"(a[mt][3])
                    : "r"(addr));
            }
#pragma unroll
            for (int bt = 0; bt < 2; ++bt) {
                unsigned addr = st_base + (unsigned)((b_off[bt] + kk) << 1);
                asm volatile(
                    "ldmatrix.sync.aligned.m8n8.x4.shared.b16 {%0,%1,%2,%3}, [%4];"
                    : "=r"(b[bt][0]), "=r"(b[bt][1]), "=r"(b[bt][2]), "=r"(b[bt][3])
                    : "r"(addr));
            }
#pragma unroll
            for (int mt = 0; mt < 2; ++mt)
#pragma unroll
                for (int nt = 0; nt < 4; ++nt) {
                    unsigned b0 = b[nt >> 1][(nt & 1)];
                    unsigned b1 = b[nt >> 1][2 + (nt & 1)];
                    asm volatile(
                        "mma.sync.aligned.m16n8k16.row.col.f32.f16.f16.f32 "
                        "{%0,%1,%2,%3}, {%4,%5,%6,%7}, {%8,%9}, {%0,%1,%2,%3};"
                        : "+f"(acc[mt][nt][0]), "+f"(acc[mt][nt][1]),
                          "+f"(acc[mt][nt][2]), "+f"(acc[mt][nt][3])
                        : "r"(a[mt][0]), "r"(a[mt][1]), "r"(a[mt][2]), "r"(a[mt][3]),
                          "r"(b0), "r"(b1));
                }
        }
    }

    const int gid = lane >> 2;
    const int tig = lane & 3;
#pragma unroll
    for (int mt = 0; mt < 2; ++mt)
#pragma unroll
        for (int nt = 0; nt < 4; ++nt) {
            int m = bm + wm0 + mt * 16 + gid;
            int n = bn + wn0 + nt * 8 + tig * 2;
            if (n < N) {
                float v0 = acc[mt][nt][0], v1 = acc[mt][nt][1];
                float v2 = acc[mt][nt][2], v3 = acc[mt][nt][3];
                if (EPI == 1) {
                    float b0v = bias[n], b1v = bias[n + 1];
                    v0 = softplusf(v0 + b0v); v1 = softplusf(v1 + b1v);
                    v2 = softplusf(v2 + b0v); v3 = softplusf(v3 + b1v);
                    __half* C = (__half*)Cv;
                    *reinterpret_cast<__half2*>(C + (size_t)m * ldc + n) =
                        __floats2half2_rn(v0, v1);
                    *reinterpret_cast<__half2*>(C + (size_t)(m + 8) * ldc + n) =
                        __floats2half2_rn(v2, v3);
                } else {
                    float* C = (float*)Cv + (size_t)blockIdx.z * (size_t)M * (size_t)ldc;
                    *reinterpret_cast<float2*>(C + (size_t)m * ldc + n) =
                        make_float2(v0, v1);
                    *reinterpret_cast<float2*>(C + (size_t)(m + 8) * ldc + n) =
                        make_float2(v2, v3);
                }
            }
        }
}

// ---------------------------------------------------------------------------
// conv + silu; emits fp16 only (scan + x_proj both read fp16).
// ---------------------------------------------------------------------------
__global__ __launch_bounds__(256)
void conv_silu_k(const float* __restrict__ xz, const float* __restrict__ w,
                 const float* __restrict__ cb, __half* __restrict__ uch)
{
    int idx = blockIdx.x * blockDim.x + threadIdx.x;
    if (idx >= NROWS * DINNER) return;
    int d   = idx & (DINNER - 1);
    int row = idx >> 11;
    int l   = row & (L_SEQ - 1);
    int b   = row >> 11;

    const float4 wv = *reinterpret_cast<const float4*>(w + (size_t)d * 4);
    const float* up = xz + (size_t)b * L_SEQ * (2 * DINNER) + d;
    const size_t S = 2 * DINNER;

    float acc = cb[d] + wv.w * up[(size_t)l * S];
    if (l >= 1) acc += wv.z * up[(size_t)(l - 1) * S];
    if (l >= 2) acc += wv.y * up[(size_t)(l - 2) * S];
    if (l >= 3) acc += wv.x * up[(size_t)(l - 3) * S];

    uch[idx] = __float2half_rn(acc / (1.f + __expf(-acc)));
}

__global__ void reduce_split(const float* __restrict__ part,
                             float* __restrict__ out,
                             __half* __restrict__ outh, int n)
{
    int i = blockIdx.x * blockDim.x + threadIdx.x;
    if (i < n) {
        float s = 0.f;
#pragma unroll
        for (int z = 0; z < KSPLIT; ++z) s += part[(size_t)z * n + i];
        out[i]  = s;
        outh[i] = __float2half_rn(s);
    }
}

// ---------------------------------------------------------------------------
// Chunked selective scan (3 phases), geometric-dA fast path, fp16 delta/u.
// ---------------------------------------------------------------------------
__global__ __launch_bounds__(256)
void scan_p1(const __half* __restrict__ delta, const float* __restrict__ xdbl,
             const __half* __restrict__ uc, const float* __restrict__ A_log,
             float* __restrict__ hfin, float* __restrict__ sumd)
{
    const int b = blockIdx.z;
    const int c = blockIdx.y;
    const int d = blockIdx.x * 256 + threadIdx.x;

    float na[DSTATE];
    const bool geo = load_na(A_log, d, na);
    const float na0 = na[0];

    float h[DSTATE];
#pragma unroll
    for (int s = 0; s < DSTATE; ++s) h[s] = 0.f;
    float sd = 0.f;

    __shared__ float bs[32][DSTATE];

    const int lbeg = c * CHUNK;
    for (int l0 = lbeg; l0 < lbeg + CHUNK; l0 += 32) {
        __syncthreads();
        for (int t = threadIdx.x; t < 32 * DSTATE; t += 256) {
            int i = t >> 4, j = t & 15;
            bs[i][j] = xdbl[(size_t)(b * L_SEQ + l0 + i) * XPROJ_N + 64 + j];
        }
        __syncthreads();
        if (geo) {
#pragma unroll 2
            for (int i = 0; i < 32; ++i) {
                size_t row = (size_t)b * L_SEQ + l0 + i;
                float t  = __half2float(delta[row * DINNER + d]);
                float u  = __half2float(uc[row * DINNER + d]);
                float tu = t * u;
                sd += t;
                float p  = __expf(t * na0);
                float p2 = p * p;
                float ra = p, rb = p2;
                h[0] = fmaf(ra, h[0], tu * bs[i][0]);
                h[1] = fmaf(rb, h[1], tu * bs[i][1]);
#pragma unroll
                for (int s = 2; s < DSTATE; s += 2) {
                    ra *= p2; h[s]     = fmaf(ra, h[s],     tu * bs[i][s]);
                    rb *= p2; h[s + 1] = fmaf(rb, h[s + 1], tu * bs[i][s + 1]);
                }
            }
        } else {
#pragma unroll 2
            for (int i = 0; i < 32; ++i) {
                size_t row = (size_t)b * L_SEQ + l0 + i;
                float t  = __half2float(delta[row * DINNER + d]);
                float u  = __half2float(uc[row * DINNER + d]);
                float tu = t * u;
                sd += t;
#pragma unroll
                for (int s = 0; s < DSTATE; ++s) {
                    float dA = __expf(t * na[s]);
                    h[s] = fmaf(dA, h[s], tu * bs[i][s]);
                }
            }
        }
    }

    const size_t base = ((size_t)(b * NCHUNK + c) * DSTATE) * DINNER + d;
#pragma unroll
    for (int s = 0; s < DSTATE; ++s)
        hfin[base + (size_t)s * DINNER] = h[s];
    sumd[(size_t)(b * NCHUNK + c) * DINNER + d] = sd;
}

__global__ __launch_bounds__(256)
void scan_combine(const float* __restrict__ hfin, const float* __restrict__ sumd,
                  const float* __restrict__ A_log, float* __restrict__ hini)
{
    const int b = blockIdx.y;
    const int d = blockIdx.x * 256 + threadIdx.x;

    float na[DSTATE];
    load_na(A_log, d, na);

    float h[DSTATE];
#pragma unroll
    for (int s = 0; s < DSTATE; ++s) h[s] = 0.f;

    for (int c = 0; c < NCHUNK; ++c) {
        const size_t base = ((size_t)(b * NCHUNK + c) * DSTATE) * DINNER + d;
#pragma unroll
        for (int s = 0; s < DSTATE; ++s)
            hini[base + (size_t)s * DINNER] = h[s];
        float sd = sumd[(size_t)(b * NCHUNK + c) * DINNER + d];
#pragma unroll
        for (int s = 0; s < DSTATE; ++s) {
            float pA = __expf(sd * na[s]);
            h[s] = fmaf(pA, h[s], hfin[base + (size_t)s * DINNER]);
        }
    }
}

__global__ __launch_bounds__(256)
void scan_p3(const __half* __restrict__ delta, const float* __restrict__ xdbl,
             const __half* __restrict__ uc, const float* __restrict__ xz,
             const float* __restrict__ A_log, const float* __restrict__ Dv,
             const float* __restrict__ hini, __half* __restrict__ yh)
{
    const int b = blockIdx.z;
    const int c = blockIdx.y;
    const int d = blockIdx.x * 256 + threadIdx.x;

    float na[DSTATE];
    const bool geo = load_na(A_log, d, na);
    const float na0 = na[0];

    float h[DSTATE];
    {
        const size_t base = ((size_t)(b * NCHUNK + c) * DSTATE) * DINNER + d;
#pragma unroll
        for (int s = 0; s < DSTATE; ++s)
            h[s] = hini[base + (size_t)s * DINNER];
    }

    const float Dd = Dv[d];
    __shared__ float bc[32][32];

    const int lbeg = c * CHUNK;
    for (int l0 = lbeg; l0 < lbeg + CHUNK; l0 += 32) {
        __syncthreads();
        for (int t = threadIdx.x; t < 1024; t += 256) {
            int i = t >> 5, j = t & 31;
            bc[i][j] = xdbl[(size_t)(b * L_SEQ + l0 + i) * XPROJ_N + 64 + j];
        }
        __syncthreads();
        if (geo) {
#pragma unroll 2
            for (int i = 0; i < 32; ++i) {
                size_t row = (size_t)b * L_SEQ + l0 + i;
                float t  = __half2float(delta[row * DINNER + d]);
                float u  = __half2float(uc[row * DINNER + d]);
                float tu = t * u;
                float yv = 0.f;
                float p  = __expf(t * na0);
                float p2 = p * p;
                float ra = p, rb = p2;
                h[0] = fmaf(ra, h[0], tu * bc[i][0]);
                yv = fmaf(h[0], bc[i][16], yv);
                h[1] = fmaf(rb, h[1], tu * bc[i][1]);
                yv = fmaf(h[1], bc[i][17], yv);
#pragma unroll
                for (int s = 2; s < DSTATE; s += 2) {
                    ra *= p2;
                    h[s] = fmaf(ra, h[s], tu * bc[i][s]);
                    yv = fmaf(h[s], bc[i][16 + s], yv);
                    rb *= p2;
                    h[s + 1] = fmaf(rb, h[s + 1], tu * bc[i][s + 1]);
                    yv = fmaf(h[s + 1], bc[i][17 + s], yv);
                }
                float zv = xz[row * (2 * DINNER) + DINNER + d];
                float g  = zv / (1.f + __expf(-zv));
                yh[row * DINNER + d] = __float2half_rn((yv + u * Dd) * g);
            }
        } else {
#pragma unroll 2
            for (int i = 0; i < 32; ++i) {
                size_t row = (size_t)b * L_SEQ + l0 + i;
                float t  = __half2float(delta[row * DINNER + d]);
                float u  = __half2float(uc[row * DINNER + d]);
                float tu = t * u;
                float yv = 0.f;
#pragma unroll
                for (int s = 0; s < DSTATE; ++s) {
                    float dA = __expf(t * na[s]);
                    h[s] = fmaf(dA, h[s], tu * bc[i][s]);
                    yv   = fmaf(h[s], bc[i][16 + s], yv);
                }
                float zv = xz[row * (2 * DINNER) + DINNER + d];
                float g  = zv / (1.f + __expf(-zv));
                yh[row * DINNER + d] = __float2half_rn((yv + u * Dd) * g);
            }
        }
    }
}

// ---------------------------------------------------------------------------
extern "C" void kernel_launch(void* const* d_in, const int* in_sizes, int n_in,
                              void* d_out, int out_size)
{
    const float* x        = (const float*)d_in[0];
    const float* W_in     = (const float*)d_in[1];
    const float* conv_w   = (const float*)d_in[2];
    const float* conv_b   = (const float*)d_in[3];
    const float* W_xproj  = (const float*)d_in[4];
    const float* W_dtproj = (const float*)d_in[5];
    const float* dt_bias  = (const float*)d_in[6];
    const float* A_log    = (const float*)d_in[7];
    const float* Dv       = (const float*)d_in[8];
    const float* W_out    = (const float*)d_in[9];
    float* out = (float*)d_out;

    float *xz, *xpart, *xdbl, *hfin, *hini, *sumd;
    __half *xh, *whin, *whxp, *whdt, *whout, *uch, *xdblh, *deltah, *yh;
    cudaGetSymbolAddress((void**)&xz,     g_xz);
    cudaGetSymbolAddress((void**)&xpart,  g_xpart);
    cudaGetSymbolAddress((void**)&xdbl,   g_xdbl);
    cudaGetSymbolAddress((void**)&hfin,   g_hfin);
    cudaGetSymbolAddress((void**)&hini,   g_hini);
    cudaGetSymbolAddress((void**)&sumd,   g_sumd);
    cudaGetSymbolAddress((void**)&xh,     g_xh);
    cudaGetSymbolAddress((void**)&whin,   g_whin);
    cudaGetSymbolAddress((void**)&whxp,   g_whxp);
    cudaGetSymbolAddress((void**)&whdt,   g_whdt);
    cudaGetSymbolAddress((void**)&whout,  g_whout);
    cudaGetSymbolAddress((void**)&uch,    g_uch);
    cudaGetSymbolAddress((void**)&xdblh,  g_xdblh);
    cudaGetSymbolAddress((void**)&deltah, g_deltah);
    cudaGetSymbolAddress((void**)&yh,     g_yh);

    cudaFuncSetAttribute(mma_tn<0>,
        cudaFuncAttributeMaxDynamicSharedMemorySize, MMA_SMEM_BYTES);
    cudaFuncSetAttribute(mma_tn<1>,
        cudaFuncAttributeMaxDynamicSharedMemorySize, MMA_SMEM_BYTES);

    dim3 blk(256);

    // 0. convert x + all weights to fp16
    f2h_multi<<<dim3(2048, 5), blk>>>(
        x,        xh,    NROWS * DMODEL,
        W_in,     whin,  2 * DINNER * DMODEL,
        W_xproj,  whxp,  XPROJ_N * DINNER,
        W_dtproj, whdt,  DINNER * 64,
        W_out,    whout, DMODEL * DINNER);

    // 1. in_proj: xz[4096,4096] = x @ W_in^T  (K=1024)
    mma_tn<0><<<dim3(64, 32, 1), blk, MMA_SMEM_BYTES>>>(xh, whin, xz,
        NROWS, 2 * DINNER, DMODEL, DMODEL, DMODEL, 2 * DINNER,
        nullptr, DMODEL);

    // 2. depthwise conv + silu (fp16 out)
    conv_silu_k<<<(NROWS * DINNER) / 256, blk>>>(xz, conv_w, conv_b, uch);

    // 3. x_proj (split-K x8): x_dbl[4096,96] = u_c @ W_xproj^T (K=2048)
    mma_tn<0><<<dim3(2, 32, KSPLIT), blk, MMA_SMEM_BYTES>>>(uch, whxp, xpart,
        NROWS, XPROJ_N, DINNER, DINNER, DINNER, XPROJ_N,
        nullptr, DINNER / KSPLIT);
    reduce_split<<<(NROWS * XPROJ_N + 255) / 256, blk>>>(
        xpart, xdbl, xdblh, NROWS * XPROJ_N);

    // 4. dt_proj + softplus -> fp16 delta (K=64)
    mma_tn<1><<<dim3(32, 32, 1), blk, MMA_SMEM_BYTES>>>(xdblh, whdt, deltah,
        NROWS, DINNER, 64, XPROJ_N, 64, DINNER,
        dt_bias, 64);

    // 5. chunked selective scan + skip + gate
    scan_p1<<<dim3(DINNER / 256, NCHUNK, NB), blk>>>(
        deltah, xdbl, uch, A_log, hfin, sumd);
    scan_combine<<<dim3(DINNER / 256, NB), blk>>>(hfin, sumd, A_log, hini);
    scan_p3<<<dim3(DINNER / 256, NCHUNK, NB), blk>>>(
        deltah, xdbl, uch, xz, A_log, Dv, hini, yh);

    // 6. out_proj: out[4096,1024] = y @ W_out^T (K=2048)
    mma_tn<0><<<dim3(16, 32, 1), blk, MMA_SMEM_BYTES>>>(yh, whout, out,
        NROWS, DMODEL, DINNER, DINNER, DINNER, DMODEL,
        nullptr, DINNER);
}

// round 13
// speedup vs baseline: 1.7662x; 1.0465x over previous
#include <cuda_runtime.h>
#include <cuda_fp16.h>
#include <math.h>

// ---------------------------------------------------------------------------
// Mamba block forward. fp16 mma.sync GEMMs: 128x64 CTA tile, cp.async 3-stage
// ring, 4 CTAs/SM target (regs<=64). Chunked selective scan (geometric-dA),
// fp16 delta/u/gate.
//   B=2, L=2048, d_model=1024, d_inner=2048, d_state=16, d_conv=4, dt_rank=64
// tcgen05 unavailable: harness PTX target is compute_103 (no 'a' suffix).
// ---------------------------------------------------------------------------

#define L_SEQ   2048
#define NB      2
#define DMODEL  1024
#define DINNER  2048
#define DSTATE  16
#define NROWS   (NB * L_SEQ)     // 4096
#define XPROJ_N 96
#define KSPLIT  8
#define CHUNK   128
#define NCHUNK  (L_SEQ / CHUNK)  // 16

// fp32 scratch
__device__ float g_xz    [(size_t)NROWS * 2 * DINNER];
__device__ float g_xpart [(size_t)KSPLIT * NROWS * XPROJ_N];
__device__ float g_xdbl  [(size_t)NROWS * XPROJ_N];
__device__ float g_hfin  [(size_t)NB * NCHUNK * DSTATE * DINNER];
__device__ float g_hini  [(size_t)NB * NCHUNK * DSTATE * DINNER];
__device__ float g_sumd  [(size_t)NB * NCHUNK * DINNER];
// fp16 operands / activations
__device__ __half g_xh    [(size_t)NROWS * DMODEL];
__device__ __half g_whin  [(size_t)2 * DINNER * DMODEL];
__device__ __half g_whxp  [(size_t)XPROJ_N * DINNER];
__device__ __half g_whdt  [(size_t)DINNER * 64];
__device__ __half g_whout [(size_t)DMODEL * DINNER];
__device__ __half g_uch   [(size_t)NROWS * DINNER];
__device__ __half g_gateh [(size_t)NROWS * DINNER];
__device__ __half g_xdblh [(size_t)NROWS * XPROJ_N];
__device__ __half g_deltah[(size_t)NROWS * DINNER];
__device__ __half g_yh    [(size_t)NROWS * DINNER];

__device__ __forceinline__ float softplusf(float x) {
    return x > 20.f ? x : log1pf(__expf(x));
}
__device__ __forceinline__ unsigned smem_u32(const void* p) {
    return (unsigned)__cvta_generic_to_shared(p);
}
__device__ __forceinline__ void cp_async16(unsigned saddr, const void* gptr, int sz) {
    asm volatile("cp.async.cg.shared.global [%0], [%1], 16, %2;"
                 :: "r"(saddr), "l"(gptr), "r"(sz));
}
__device__ __forceinline__ void cp_commit() {
    asm volatile("cp.async.commit_group;" ::: "memory");
}
template<int N>
__device__ __forceinline__ void cp_wait() {
    asm volatile("cp.async.wait_group %0;" :: "n"(N) : "memory");
}

// load na[] and detect geometric structure na[s] == (s+1)*na[0]
__device__ __forceinline__ bool load_na(const float* __restrict__ A_log,
                                        int d, float* na)
{
    bool geo = true;
#pragma unroll
    for (int s = 0; s < DSTATE; ++s) {
        na[s] = -__expf(A_log[(size_t)d * DSTATE + s]);
        geo = geo && (fabsf(na[s] - (float)(s + 1) * na[0])
                      <= 1e-5f * fabsf(na[s]));
    }
    return geo;
}

// ---------------------------------------------------------------------------
__global__ __launch_bounds__(256)
void f2h_multi(const float* __restrict__ s0, __half* d0, int n0,
               const float* __restrict__ s1, __half* d1, int n1,
               const float* __restrict__ s2, __half* d2, int n2,
               const float* __restrict__ s3, __half* d3, int n3,
               const float* __restrict__ s4, __half* d4, int n4)
{
    const float* s; __half* d; int n;
    switch (blockIdx.y) {
        case 0: s = s0; d = d0; n = n0; break;
        case 1: s = s1; d = d1; n = n1; break;
        case 2: s = s2; d = d2; n = n2; break;
        case 3: s = s3; d = d3; n = n3; break;
        default: s = s4; d = d4; n = n4; break;
    }
    int nq = n >> 2;
    for (int i = blockIdx.x * blockDim.x + threadIdx.x; i < nq;
         i += gridDim.x * blockDim.x) {
        float4 v = *reinterpret_cast<const float4*>(s + (size_t)i * 4);
        __half2 h0 = __floats2half2_rn(v.x, v.y);
        __half2 h1 = __floats2half2_rn(v.z, v.w);
        *reinterpret_cast<uint2*>(d + (size_t)i * 4) =
            make_uint2(*(unsigned*)&h0, *(unsigned*)&h1);
    }
}

// ---------------------------------------------------------------------------
// C[M,N] = A[M,K] @ B[N,K]^T, fp16 operands, m16n8k16. 128x64 CTA tile,
// 8 warps = 4m x 2n (32x32 warp tile). cp.async 3-stage ring, padded commits.
// EPI=0: fp32 C (split-K slice via blockIdx.z). EPI=1: fp16 softplus(acc+bias).
// ---------------------------------------------------------------------------
#define BK      32
#define BSTH    40                       // halfs per row (32 + 8 pad)
#define A_STG   (128 * BSTH)
#define B_STG   (64 * BSTH)
#define STG_H   (A_STG + B_STG)          // 7680 halfs
#define NSTAGE  3
#define MMA_SMEM_BYTES (NSTAGE * STG_H * 2)   // 46080

template<int EPI>
__global__ __launch_bounds__(256, 4)
void mma_tn(const __half* __restrict__ A, const __half* __restrict__ B,
            void* __restrict__ Cv, int M, int N, int K,
            int lda, int ldb, int ldc,
            const float* __restrict__ bias, int kPerSplit)
{
    extern __shared__ __align__(16) __half sh[];

    const int tid  = threadIdx.x;
    const int lane = tid & 31;
    const int wid  = tid >> 5;
    const int wm0  = (wid >> 1) << 5;   // 0,32,64,96
    const int wn0  = (wid & 1) << 5;    // 0,32

    const int bm = blockIdx.y << 7;
    const int bn = blockIdx.x << 6;
    const int kbeg = blockIdx.z * kPerSplit;

    float acc[2][4][4];
#pragma unroll
    for (int mt = 0; mt < 2; ++mt)
#pragma unroll
        for (int nt = 0; nt < 4; ++nt)
#pragma unroll
            for (int r = 0; r < 4; ++r) acc[mt][nt][r] = 0.f;

    int a_off[2], b_off[2];
#pragma unroll
    for (int mt = 0; mt < 2; ++mt) {
        int row = wm0 + mt * 16 + ((lane >> 3) & 1) * 8 + (lane & 7);
        int col = (lane >> 4) * 8;
        a_off[mt] = row * BSTH + col;
    }
#pragma unroll
    for (int bt = 0; bt < 2; ++bt) {
        int row = wn0 + bt * 16 + ((lane >> 3) & 1) * 8 + (lane & 7);
        int col = (lane >> 4) * 8;
        b_off[bt] = A_STG + row * BSTH + col;
    }
    const unsigned sh_base = smem_u32(sh);

    const int lrow = tid >> 2;          // 0..63
    const int lc8  = (tid & 3) << 3;    // 0,8,16,24

    const __half* gA0 = A + (size_t)(bm + lrow) * lda + kbeg + lc8;
    const __half* gA1 = gA0 + (size_t)64 * lda;
    int rb  = (bn + lrow < N) ? lrow : 0;
    int bsz = (bn + lrow < N) ? 16 : 0;
    const __half* gB0 = B + (size_t)(bn + rb) * ldb + kbeg + lc8;

    const int nk = kPerSplit >> 5;
    const unsigned s_arow0 = (unsigned)((lrow * BSTH + lc8) << 1);
    const unsigned s_arow1 = (unsigned)(((lrow + 64) * BSTH + lc8) << 1);
    const unsigned s_brow  = (unsigned)((A_STG + lrow * BSTH + lc8) << 1);

    auto issue = [&](int t) {
        if (t < nk) {
            unsigned sb = sh_base + (unsigned)(((t % NSTAGE) * STG_H) << 1);
            int koff = t * BK;
            cp_async16(sb + s_arow0, gA0 + koff, 16);
            cp_async16(sb + s_arow1, gA1 + koff, 16);
            cp_async16(sb + s_brow,  gB0 + koff, bsz);
        }
        cp_commit();
    };

    issue(0);
    issue(1);

    for (int t = 0; t < nk; ++t) {
        cp_wait<1>();      // committed == t+2 => stage t resident
        __syncthreads();   // readers of stage (t+2)%3 done (iter t-1)
        issue(t + 2);

        const unsigned st_base = sh_base + (unsigned)(((t % NSTAGE) * STG_H) << 1);

#pragma unroll
        for (int kk = 0; kk < BK; kk += 16) {
            unsigned a[2][4], b[2][4];
#pragma unroll
            for (int mt = 0; mt < 2; ++mt) {
                unsigned addr = st_base + (unsigned)((a_off[mt] + kk) << 1);
                asm volatile(
                    "ldmatrix.sync.aligned.m8n8.x4.shared.b16 {%0,%1,%2,%3}, [%4];"
                    : "=r"(a[mt][0]), "=r"(a[mt][1]), "=r"(a[mt][2]), "=r"(a[mt][3])
                    : "r"(addr));
            }
#pragma unroll
            for (int bt = 0; bt < 2; ++bt) {
                unsigned addr = st_base + (unsigned)((b_off[bt] + kk) << 1);
                asm volatile(
                    "ldmatrix.sync.aligned.m8n8.x4.shared.b16 {%0,%1,%2,%3}, [%4];"
                    : "=r"(b[bt][0]), "=r"(b[bt][1]), "=r"(b[bt][2]), "=r"(b[bt][3])
                    : "r"(addr));
            }
#pragma unroll
            for (int mt = 0; mt < 2; ++mt)
#pragma unroll
                for (int nt = 0; nt < 4; ++nt) {
                    unsigned b0 = b[nt >> 1][(nt & 1)];
                    unsigned b1 = b[nt >> 1][2 + (nt & 1)];
                    asm volatile(
                        "mma.sync.aligned.m16n8k16.row.col.f32.f16.f16.f32 "
                        "{%0,%1,%2,%3}, {%4,%5,%6,%7}, {%8,%9}, {%0,%1,%2,%3};"
                        : "+f"(acc[mt][nt][0]), "+f"(acc[mt][nt][1]),
                          "+f"(acc[mt][nt][2]), "+f"(acc[mt][nt][3])
                        : "r"(a[mt][0]), "r"(a[mt][1]), "r"(a[mt][2]), "r"(a[mt][3]),
                          "r"(b0), "r"(b1));
                }
        }
    }

    const int gid = lane >> 2;
    const int tig = lane & 3;
#pragma unroll
    for (int mt = 0; mt < 2; ++mt)
#pragma unroll
        for (int nt = 0; nt < 4; ++nt) {
            int m = bm + wm0 + mt * 16 + gid;
            int n = bn + wn0 + nt * 8 + tig * 2;
            if (n < N) {
                float v0 = acc[mt][nt][0], v1 = acc[mt][nt][1];
                float v2 = acc[mt][nt][2], v3 = acc[mt][nt][3];
                if (EPI == 1) {
                    float b0v = bias[n], b1v = bias[n + 1];
                    v0 = softplusf(v0 + b0v); v1 = softplusf(v1 + b1v);
                    v2 = softplusf(v2 + b0v); v3 = softplusf(v3 + b1v);
                    __half* C = (__half*)Cv;
                    *reinterpret_cast<__half2*>(C + (size_t)m * ldc + n) =
                        __floats2half2_rn(v0, v1);
                    *reinterpret_cast<__half2*>(C + (size_t)(m + 8) * ldc + n) =
                        __floats2half2_rn(v2, v3);
                } else {
                    float* C = (float*)Cv + (size_t)blockIdx.z * (size_t)M * (size_t)ldc;
                    *reinterpret_cast<float2*>(C + (size_t)m * ldc + n) =
                        make_float2(v0, v1);
                    *reinterpret_cast<float2*>(C + (size_t)(m + 8) * ldc + n) =
                        make_float2(v2, v3);
                }
            }
        }
}

// ---------------------------------------------------------------------------
// conv + silu (fp16 u out) + gate precompute: gateh = fp16(silu(z)).
// ---------------------------------------------------------------------------
__global__ __launch_bounds__(256)
void conv_silu_k(const float* __restrict__ xz, const float* __restrict__ w,
                 const float* __restrict__ cb, __half* __restrict__ uch,
                 __half* __restrict__ gateh)
{
    int idx = blockIdx.x * blockDim.x + threadIdx.x;
    if (idx >= NROWS * DINNER) return;
    int d   = idx & (DINNER - 1);
    int row = idx >> 11;
    int l   = row & (L_SEQ - 1);
    int b   = row >> 11;

    const float4 wv = *reinterpret_cast<const float4*>(w + (size_t)d * 4);
    const float* up = xz + (size_t)b * L_SEQ * (2 * DINNER) + d;
    const size_t S = 2 * DINNER;

    float acc = cb[d] + wv.w * up[(size_t)l * S];
    if (l >= 1) acc += wv.z * up[(size_t)(l - 1) * S];
    if (l >= 2) acc += wv.y * up[(size_t)(l - 2) * S];
    if (l >= 3) acc += wv.x * up[(size_t)(l - 3) * S];

    uch[idx] = __float2half_rn(acc / (1.f + __expf(-acc)));

    float zv = up[(size_t)l * S + DINNER];
    gateh[idx] = __float2half_rn(zv / (1.f + __expf(-zv)));
}

__global__ void reduce_split(const float* __restrict__ part,
                             float* __restrict__ out,
                             __half* __restrict__ outh, int n)
{
    int i = blockIdx.x * blockDim.x + threadIdx.x;
    if (i < n) {
        float s = 0.f;
#pragma unroll
        for (int z = 0; z < KSPLIT; ++z) s += part[(size_t)z * n + i];
        out[i]  = s;
        outh[i] = __float2half_rn(s);
    }
}

// ---------------------------------------------------------------------------
// Chunked selective scan (3 phases), geometric-dA fast path, fp16 streams.
// ---------------------------------------------------------------------------
__global__ __launch_bounds__(256)
void scan_p1(const __half* __restrict__ delta, const float* __restrict__ xdbl,
             const __half* __restrict__ uc, const float* __restrict__ A_log,
             float* __restrict__ hfin, float* __restrict__ sumd)
{
    const int b = blockIdx.z;
    const int c = blockIdx.y;
    const int d = blockIdx.x * 256 + threadIdx.x;

    float na[DSTATE];
    const bool geo = load_na(A_log, d, na);
    const float na0 = na[0];

    float h[DSTATE];
#pragma unroll
    for (int s = 0; s < DSTATE; ++s) h[s] = 0.f;
    float sd = 0.f;

    __shared__ float bs[32][DSTATE];

    const int lbeg = c * CHUNK;
    for (int l0 = lbeg; l0 < lbeg + CHUNK; l0 += 32) {
        __syncthreads();
        for (int t = threadIdx.x; t < 32 * DSTATE; t += 256) {
            int i = t >> 4, j = t & 15;
            bs[i][j] = xdbl[(size_t)(b * L_SEQ + l0 + i) * XPROJ_N + 64 + j];
        }
        __syncthreads();
        if (geo) {
#pragma unroll 2
            for (int i = 0; i < 32; ++i) {
                size_t row = (size_t)b * L_SEQ + l0 + i;
                float t  = __half2float(delta[row * DINNER + d]);
                float u  = __half2float(uc[row * DINNER + d]);
                float tu = t * u;
                sd += t;
                float p  = __expf(t * na0);
                float p2 = p * p;
                float ra = p, rb = p2;
                h[0] = fmaf(ra, h[0], tu * bs[i][0]);
                h[1] = fmaf(rb, h[1], tu * bs[i][1]);
#pragma unroll
                for (int s = 2; s < DSTATE; s += 2) {
                    ra *= p2; h[s]     = fmaf(ra, h[s],     tu * bs[i][s]);
                    rb *= p2; h[s + 1] = fmaf(rb, h[s + 1], tu * bs[i][s + 1]);
                }
            }
        } else {
#pragma unroll 2
            for (int i = 0; i < 32; ++i) {
                size_t row = (size_t)b * L_SEQ + l0 + i;
                float t  = __half2float(delta[row * DINNER + d]);
                float u  = __half2float(uc[row * DINNER + d]);
                float tu = t * u;
                sd += t;
#pragma unroll
                for (int s = 0; s < DSTATE; ++s) {
                    float dA = __expf(t * na[s]);
                    h[s] = fmaf(dA, h[s], tu * bs[i][s]);
                }
            }
        }
    }

    const size_t base = ((size_t)(b * NCHUNK + c) * DSTATE) * DINNER + d;
#pragma unroll
    for (int s = 0; s < DSTATE; ++s)
        hfin[base + (size_t)s * DINNER] = h[s];
    sumd[(size_t)(b * NCHUNK + c) * DINNER + d] = sd;
}

__global__ __launch_bounds__(256)
void scan_combine(const float* __restrict__ hfin, const float* __restrict__ sumd,
                  const float* __restrict__ A_log, float* __restrict__ hini)
{
    const int b = blockIdx.y;
    const int d = blockIdx.x * 256 + threadIdx.x;

    float na[DSTATE];
    load_na(A_log, d, na);

    float h[DSTATE];
#pragma unroll
    for (int s = 0; s < DSTATE; ++s) h[s] = 0.f;

    for (int c = 0; c < NCHUNK; ++c) {
        const size_t base = ((size_t)(b * NCHUNK + c) * DSTATE) * DINNER + d;
#pragma unroll
        for (int s = 0; s < DSTATE; ++s)
            hini[base + (size_t)s * DINNER] = h[s];
        float sd = sumd[(size_t)(b * NCHUNK + c) * DINNER + d];
#pragma unroll
        for (int s = 0; s < DSTATE; ++s) {
            float pA = __expf(sd * na[s]);
            h[s] = fmaf(pA, h[s], hfin[base + (size_t)s * DINNER]);
        }
    }
}

__global__ __launch_bounds__(256)
void scan_p3(const __half* __restrict__ delta, const float* __restrict__ xdbl,
             const __half* __restrict__ uc, const __half* __restrict__ gateh,
             const float* __restrict__ A_log, const float* __restrict__ Dv,
             const float* __restrict__ hini, __half* __restrict__ yh)
{
    const int b = blockIdx.z;
    const int c = blockIdx.y;
    const int d = blockIdx.x * 256 + threadIdx.x;

    float na[DSTATE];
    const bool geo = load_na(A_log, d, na);
    const float na0 = na[0];

    float h[DSTATE];
    {
        const size_t base = ((size_t)(b * NCHUNK + c) * DSTATE) * DINNER + d;
#pragma unroll
        for (int s = 0; s < DSTATE; ++s)
            h[s] = hini[base + (size_t)s * DINNER];
    }

    const float Dd = Dv[d];
    __shared__ float bc[32][32];

    const int lbeg = c * CHUNK;
    for (int l0 = lbeg; l0 < lbeg + CHUNK; l0 += 32) {
        __syncthreads();
        for (int t = threadIdx.x; t < 1024; t += 256) {
            int i = t >> 5, j = t & 31;
            bc[i][j] = xdbl[(size_t)(b * L_SEQ + l0 + i) * XPROJ_N + 64 + j];
        }
        __syncthreads();
        if (geo) {
#pragma unroll 2
            for (int i = 0; i < 32; ++i) {
                size_t row = (size_t)b * L_SEQ + l0 + i;
                float t  = __half2float(delta[row * DINNER + d]);
                float u  = __half2float(uc[row * DINNER + d]);
                float tu = t * u;
                float yv = 0.f;
                float p  = __expf(t * na0);
                float p2 = p * p;
                float ra = p, rb = p2;
                h[0] = fmaf(ra, h[0], tu * bc[i][0]);
                yv = fmaf(h[0], bc[i][16], yv);
                h[1] = fmaf(rb, h[1], tu * bc[i][1]);
                yv = fmaf(h[1], bc[i][17], yv);
#pragma unroll
                for (int s = 2; s < DSTATE; s += 2) {
                    ra *= p2;
                    h[s] = fmaf(ra, h[s], tu * bc[i][s]);
                    yv = fmaf(h[s], bc[i][16 + s], yv);
                    rb *= p2;
                    h[s + 1] = fmaf(rb, h[s + 1], tu * bc[i][s + 1]);
                    yv = fmaf(h[s + 1], bc[i][17 + s], yv);
                }
                float g = __half2float(gateh[row * DINNER + d]);
                yh[row * DINNER + d] = __float2half_rn((yv + u * Dd) * g);
            }
        } else {
#pragma unroll 2
            for (int i = 0; i < 32; ++i) {
                size_t row = (size_t)b * L_SEQ + l0 + i;
                float t  = __half2float(delta[row * DINNER + d]);
                float u  = __half2float(uc[row * DINNER + d]);
                float tu = t * u;
                float yv = 0.f;
#pragma unroll
                for (int s = 0; s < DSTATE; ++s) {
                    float dA = __expf(t * na[s]);
                    h[s] = fmaf(dA, h[s], tu * bc[i][s]);
                    yv   = fmaf(h[s], bc[i][16 + s], yv);
                }
                float g = __half2float(gateh[row * DINNER + d]);
                yh[row * DINNER + d] = __float2half_rn((yv + u * Dd) * g);
            }
        }
    }
}

// ---------------------------------------------------------------------------
extern "C" void kernel_launch(void* const* d_in, const int* in_sizes, int n_in,
                              void* d_out, int out_size)
{
    const float* x        = (const float*)d_in[0];
    const float* W_in     = (const float*)d_in[1];
    const float* conv_w   = (const float*)d_in[2];
    const float* conv_b   = (const float*)d_in[3];
    const float* W_xproj  = (const float*)d_in[4];
    const float* W_dtproj = (const float*)d_in[5];
    const float* dt_bias  = (const float*)d_in[6];
    const float* A_log    = (const float*)d_in[7];
    const float* Dv       = (const float*)d_in[8];
    const float* W_out    = (const float*)d_in[9];
    float* out = (float*)d_out;

    float *xz, *xpart, *xdbl, *hfin, *hini, *sumd;
    __half *xh, *whin, *whxp, *whdt, *whout, *uch, *gateh, *xdblh, *deltah, *yh;
    cudaGetSymbolAddress((void**)&xz,     g_xz);
    cudaGetSymbolAddress((void**)&xpart,  g_xpart);
    cudaGetSymbolAddress((void**)&xdbl,   g_xdbl);
    cudaGetSymbolAddress((void**)&hfin,   g_hfin);
    cudaGetSymbolAddress((void**)&hini,   g_hini);
    cudaGetSymbolAddress((void**)&sumd,   g_sumd);
    cudaGetSymbolAddress((void**)&xh,     g_xh);
    cudaGetSymbolAddress((void**)&whin,   g_whin);
    cudaGetSymbolAddress((void**)&whxp,   g_whxp);
    cudaGetSymbolAddress((void**)&whdt,   g_whdt);
    cudaGetSymbolAddress((void**)&whout,  g_whout);
    cudaGetSymbolAddress((void**)&uch,    g_uch);
    cudaGetSymbolAddress((void**)&gateh,  g_gateh);
    cudaGetSymbolAddress((void**)&xdblh,  g_xdblh);
    cudaGetSymbolAddress((void**)&deltah, g_deltah);
    cudaGetSymbolAddress((void**)&yh,     g_yh);

    cudaFuncSetAttribute(mma_tn<0>,
        cudaFuncAttributeMaxDynamicSharedMemorySize, MMA_SMEM_BYTES);
    cudaFuncSetAttribute(mma_tn<1>,
        cudaFuncAttributeMaxDynamicSharedMemorySize, MMA_SMEM_BYTES);

    dim3 blk(256);

    // 0. convert x + all weights to fp16
    f2h_multi<<<dim3(2048, 5), blk>>>(
        x,        xh,    NROWS * DMODEL,
        W_in,     whin,  2 * DINNER * DMODEL,
        W_xproj,  whxp,  XPROJ_N * DINNER,
        W_dtproj, whdt,  DINNER * 64,
        W_out,    whout, DMODEL * DINNER);

    // 1. in_proj: xz[4096,4096] = x @ W_in^T  (K=1024)
    mma_tn<0><<<dim3(64, 32, 1), blk, MMA_SMEM_BYTES>>>(xh, whin, xz,
        NROWS, 2 * DINNER, DMODEL, DMODEL, DMODEL, 2 * DINNER,
        nullptr, DMODEL);

    // 2. depthwise conv + silu (fp16 u) + gate silu(z) (fp16)
    conv_silu_k<<<(NROWS * DINNER) / 256, blk>>>(xz, conv_w, conv_b, uch, gateh);

    // 3. x_proj (split-K x8): x_dbl[4096,96] = u_c @ W_xproj^T (K=2048)
    mma_tn<0><<<dim3(2, 32, KSPLIT), blk, MMA_SMEM_BYTES>>>(uch, whxp, xpart,
        NROWS, XPROJ_N, DINNER, DINNER, DINNER, XPROJ_N,
        nullptr, DINNER / KSPLIT);
    reduce_split<<<(NROWS * XPROJ_N + 255) / 256, blk>>>(
        xpart, xdbl, xdblh, NROWS * XPROJ_N);

    // 4. dt_proj + softplus -> fp16 delta (K=64)
    mma_tn<1><<<dim3(32, 32, 1), blk, MMA_SMEM_BYTES>>>(xdblh, whdt, deltah,
        NROWS, DINNER, 64, XPROJ_N, 64, DINNER,
        dt_bias, 64);

    // 5. chunked selective scan + skip + gate
    scan_p1<<<dim3(DINNER / 256, NCHUNK, NB), blk>>>(
        deltah, xdbl, uch, A_log, hfin, sumd);
    scan_combine<<<dim3(DINNER / 256, NB), blk>>>(hfin, sumd, A_log, hini);
    scan_p3<<<dim3(DINNER / 256, NCHUNK, NB), blk>>>(
        deltah, xdbl, uch, gateh, A_log, Dv, hini, yh);

    // 6. out_proj: out[4096,1024] = y @ W_out^T (K=2048)
    mma_tn<0><<<dim3(16, 32, 1), blk, MMA_SMEM_BYTES>>>(yh, whout, out,
        NROWS, DMODEL, DINNER, DINNER, DINNER, DMODEL,
        nullptr, DINNER);
}

// round 14
// speedup vs baseline: 1.8300x; 1.0361x over previous
#include <cuda_runtime.h>
#include <cuda_fp16.h>
#include <math.h>

// ---------------------------------------------------------------------------
// Mamba block forward. fp16 mma.sync GEMMs (128x64 tile, cp.async 3-stage,
// occ=4) + fp16 xz end-to-end (in_proj writes fp16, conv reads fp16) +
// chunked selective scan (geometric-dA), fp16 delta/u/gate.
//   B=2, L=2048, d_model=1024, d_inner=2048, d_state=16, d_conv=4, dt_rank=64
// tcgen05 unavailable: harness PTX target is compute_103 (no 'a' suffix).
// ---------------------------------------------------------------------------

#define L_SEQ   2048
#define NB      2
#define DMODEL  1024
#define DINNER  2048
#define DSTATE  16
#define NROWS   (NB * L_SEQ)     // 4096
#define XPROJ_N 96
#define KSPLIT  8
#define CHUNK   128
#define NCHUNK  (L_SEQ / CHUNK)  // 16

// fp32 scratch
__device__ float g_xpart [(size_t)KSPLIT * NROWS * XPROJ_N];
__device__ float g_xdbl  [(size_t)NROWS * XPROJ_N];
__device__ float g_hfin  [(size_t)NB * NCHUNK * DSTATE * DINNER];
__device__ float g_hini  [(size_t)NB * NCHUNK * DSTATE * DINNER];
__device__ float g_sumd  [(size_t)NB * NCHUNK * DINNER];
// fp16 operands / activations
__device__ __half g_xzh   [(size_t)NROWS * 2 * DINNER];
__device__ __half g_xh    [(size_t)NROWS * DMODEL];
__device__ __half g_whin  [(size_t)2 * DINNER * DMODEL];
__device__ __half g_whxp  [(size_t)XPROJ_N * DINNER];
__device__ __half g_whdt  [(size_t)DINNER * 64];
__device__ __half g_whout [(size_t)DMODEL * DINNER];
__device__ __half g_uch   [(size_t)NROWS * DINNER];
__device__ __half g_gateh [(size_t)NROWS * DINNER];
__device__ __half g_xdblh [(size_t)NROWS * XPROJ_N];
__device__ __half g_deltah[(size_t)NROWS * DINNER];
__device__ __half g_yh    [(size_t)NROWS * DINNER];

__device__ __forceinline__ float softplusf(float x) {
    return x > 20.f ? x : log1pf(__expf(x));
}
__device__ __forceinline__ unsigned smem_u32(const void* p) {
    return (unsigned)__cvta_generic_to_shared(p);
}
__device__ __forceinline__ void cp_async16(unsigned saddr, const void* gptr, int sz) {
    asm volatile("cp.async.cg.shared.global [%0], [%1], 16, %2;"
                 :: "r"(saddr), "l"(gptr), "r"(sz));
}
__device__ __forceinline__ void cp_commit() {
    asm volatile("cp.async.commit_group;" ::: "memory");
}
template<int N>
__device__ __forceinline__ void cp_wait() {
    asm volatile("cp.async.wait_group %0;" :: "n"(N) : "memory");
}

__device__ __forceinline__ bool load_na(const float* __restrict__ A_log,
                                        int d, float* na)
{
    bool geo = true;
#pragma unroll
    for (int s = 0; s < DSTATE; ++s) {
        na[s] = -__expf(A_log[(size_t)d * DSTATE + s]);
        geo = geo && (fabsf(na[s] - (float)(s + 1) * na[0])
                      <= 1e-5f * fabsf(na[s]));
    }
    return geo;
}

// ---------------------------------------------------------------------------
__global__ __launch_bounds__(256)
void f2h_multi(const float* __restrict__ s0, __half* d0, int n0,
               const float* __restrict__ s1, __half* d1, int n1,
               const float* __restrict__ s2, __half* d2, int n2,
               const float* __restrict__ s3, __half* d3, int n3,
               const float* __restrict__ s4, __half* d4, int n4)
{
    const float* s; __half* d; int n;
    switch (blockIdx.y) {
        case 0: s = s0; d = d0; n = n0; break;
        case 1: s = s1; d = d1; n = n1; break;
        case 2: s = s2; d = d2; n = n2; break;
        case 3: s = s3; d = d3; n = n3; break;
        default: s = s4; d = d4; n = n4; break;
    }
    int nq = n >> 2;
    for (int i = blockIdx.x * blockDim.x + threadIdx.x; i < nq;
         i += gridDim.x * blockDim.x) {
        float4 v = *reinterpret_cast<const float4*>(s + (size_t)i * 4);
        __half2 h0 = __floats2half2_rn(v.x, v.y);
        __half2 h1 = __floats2half2_rn(v.z, v.w);
        *reinterpret_cast<uint2*>(d + (size_t)i * 4) =
            make_uint2(*(unsigned*)&h0, *(unsigned*)&h1);
    }
}

// ---------------------------------------------------------------------------
// C[M,N] = A[M,K] @ B[N,K]^T, fp16 operands, m16n8k16. 128x64 CTA tile,
// 8 warps = 4m x 2n (32x32 warp tile). cp.async 3-stage ring, padded commits.
// EPI=0: fp32 C (split-K slice via blockIdx.z). EPI=1: fp16 softplus(acc+bias).
// EPI=2: fp16 C plain.
// ---------------------------------------------------------------------------
#define BK      32
#define BSTH    40
#define A_STG   (128 * BSTH)
#define B_STG   (64 * BSTH)
#define STG_H   (A_STG + B_STG)
#define NSTAGE  3
#define MMA_SMEM_BYTES (NSTAGE * STG_H * 2)   // 46080

template<int EPI>
__global__ __launch_bounds__(256, 4)
void mma_tn(const __half* __restrict__ A, const __half* __restrict__ B,
            void* __restrict__ Cv, int M, int N, int K,
            int lda, int ldb, int ldc,
            const float* __restrict__ bias, int kPerSplit)
{
    extern __shared__ __align__(16) __half sh[];

    const int tid  = threadIdx.x;
    const int lane = tid & 31;
    const int wid  = tid >> 5;
    const int wm0  = (wid >> 1) << 5;
    const int wn0  = (wid & 1) << 5;

    const int bm = blockIdx.y << 7;
    const int bn = blockIdx.x << 6;
    const int kbeg = blockIdx.z * kPerSplit;

    float acc[2][4][4];
#pragma unroll
    for (int mt = 0; mt < 2; ++mt)
#pragma unroll
        for (int nt = 0; nt < 4; ++nt)
#pragma unroll
            for (int r = 0; r < 4; ++r) acc[mt][nt][r] = 0.f;

    int a_off[2], b_off[2];
#pragma unroll
    for (int mt = 0; mt < 2; ++mt) {
        int row = wm0 + mt * 16 + ((lane >> 3) & 1) * 8 + (lane & 7);
        int col = (lane >> 4) * 8;
        a_off[mt] = row * BSTH + col;
    }
#pragma unroll
    for (int bt = 0; bt < 2; ++bt) {
        int row = wn0 + bt * 16 + ((lane >> 3) & 1) * 8 + (lane & 7);
        int col = (lane >> 4) * 8;
        b_off[bt] = A_STG + row * BSTH + col;
    }
    const unsigned sh_base = smem_u32(sh);

    const int lrow = tid >> 2;
    const int lc8  = (tid & 3) << 3;

    const __half* gA0 = A + (size_t)(bm + lrow) * lda + kbeg + lc8;
    const __half* gA1 = gA0 + (size_t)64 * lda;
    int rb  = (bn + lrow < N) ? lrow : 0;
    int bsz = (bn + lrow < N) ? 16 : 0;
    const __half* gB0 = B + (size_t)(bn + rb) * ldb + kbeg + lc8;

    const int nk = kPerSplit >> 5;
    const unsigned s_arow0 = (unsigned)((lrow * BSTH + lc8) << 1);
    const unsigned s_arow1 = (unsigned)(((lrow + 64) * BSTH + lc8) << 1);
    const unsigned s_brow  = (unsigned)((A_STG + lrow * BSTH + lc8) << 1);

    auto issue = [&](int t) {
        if (t < nk) {
            unsigned sb = sh_base + (unsigned)(((t % NSTAGE) * STG_H) << 1);
            int koff = t * BK;
            cp_async16(sb + s_arow0, gA0 + koff, 16);
            cp_async16(sb + s_arow1, gA1 + koff, 16);
            cp_async16(sb + s_brow,  gB0 + koff, bsz);
        }
        cp_commit();
    };

    issue(0);
    issue(1);

    for (int t = 0; t < nk; ++t) {
        cp_wait<1>();
        __syncthreads();
        issue(t + 2);

        const unsigned st_base = sh_base + (unsigned)(((t % NSTAGE) * STG_H) << 1);

#pragma unroll
        for (int kk = 0; kk < BK; kk += 16) {
            unsigned a[2][4], b[2][4];
#pragma unroll
            for (int mt = 0; mt < 2; ++mt) {
                unsigned addr = st_base + (unsigned)((a_off[mt] + kk) << 1);
                asm volatile(
                    "ldmatrix.sync.aligned.m8n8.x4.shared.b16 {%0,%1,%2,%3}, [%4];"
                    : "=r"(a[mt][0]), "=r"(a[mt][1]), "=r"(a[mt][2]), "=r"(a[mt][3])
                    : "r"(addr));
            }
#pragma unroll
            for (int bt = 0; bt < 2; ++bt) {
                unsigned addr = st_base + (unsigned)((b_off[bt] + kk) << 1);
                asm volatile(
                    "ldmatrix.sync.aligned.m8n8.x4.shared.b16 {%0,%1,%2,%3}, [%4];"
                    : "=r"(b[bt][0]), "=r"(b[bt][1]), "=r"(b[bt][2]), "=r"(b[bt][3])
                    : "r"(addr));
            }
#pragma unroll
            for (int mt = 0; mt < 2; ++mt)
#pragma unroll
                for (int nt = 0; nt < 4; ++nt) {
                    unsigned b0 = b[nt >> 1][(nt & 1)];
                    unsigned b1 = b[nt >> 1][2 + (nt & 1)];
                    asm volatile(
                        "mma.sync.aligned.m16n8k16.row.col.f32.f16.f16.f32 "
                        "{%0,%1,%2,%3}, {%4,%5,%6,%7}, {%8,%9}, {%0,%1,%2,%3};"
                        : "+f"(acc[mt][nt][0]), "+f"(acc[mt][nt][1]),
                          "+f"(acc[mt][nt][2]), "+f"(acc[mt][nt][3])
                        : "r"(a[mt][0]), "r"(a[mt][1]), "r"(a[mt][2]), "r"(a[mt][3]),
                          "r"(b0), "r"(b1));
                }
        }
    }

    const int gid = lane >> 2;
    const int tig = lane & 3;
#pragma unroll
    for (int mt = 0; mt < 2; ++mt)
#pragma unroll
        for (int nt = 0; nt < 4; ++nt) {
            int m = bm + wm0 + mt * 16 + gid;
            int n = bn + wn0 + nt * 8 + tig * 2;
            if (n < N) {
                float v0 = acc[mt][nt][0], v1 = acc[mt][nt][1];
                float v2 = acc[mt][nt][2], v3 = acc[mt][nt][3];
                if (EPI == 1) {
                    float b0v = bias[n], b1v = bias[n + 1];
                    v0 = softplusf(v0 + b0v); v1 = softplusf(v1 + b1v);
                    v2 = softplusf(v2 + b0v); v3 = softplusf(v3 + b1v);
                    __half* C = (__half*)Cv;
                    *reinterpret_cast<__half2*>(C + (size_t)m * ldc + n) =
                        __floats2half2_rn(v0, v1);
                    *reinterpret_cast<__half2*>(C + (size_t)(m + 8) * ldc + n) =
                        __floats2half2_rn(v2, v3);
                } else if (EPI == 2) {
                    __half* C = (__half*)Cv;
                    *reinterpret_cast<__half2*>(C + (size_t)m * ldc + n) =
                        __floats2half2_rn(v0, v1);
                    *reinterpret_cast<__half2*>(C + (size_t)(m + 8) * ldc + n) =
                        __floats2half2_rn(v2, v3);
                } else {
                    float* C = (float*)Cv + (size_t)blockIdx.z * (size_t)M * (size_t)ldc;
                    *reinterpret_cast<float2*>(C + (size_t)m * ldc + n) =
                        make_float2(v0, v1);
                    *reinterpret_cast<float2*>(C + (size_t)(m + 8) * ldc + n) =
                        make_float2(v2, v3);
                }
            }
        }
}

// ---------------------------------------------------------------------------
// conv + silu (fp16 in/out) + gate precompute: gateh = fp16(silu(z)).
// ---------------------------------------------------------------------------
__global__ __launch_bounds__(256)
void conv_silu_k(const __half* __restrict__ xz, const float* __restrict__ w,
                 const float* __restrict__ cb, __half* __restrict__ uch,
                 __half* __restrict__ gateh)
{
    int idx = blockIdx.x * blockDim.x + threadIdx.x;
    if (idx >= NROWS * DINNER) return;
    int d   = idx & (DINNER - 1);
    int row = idx >> 11;
    int l   = row & (L_SEQ - 1);
    int b   = row >> 11;

    const float4 wv = *reinterpret_cast<const float4*>(w + (size_t)d * 4);
    const __half* up = xz + (size_t)b * L_SEQ * (2 * DINNER) + d;
    const size_t S = 2 * DINNER;

    float acc = cb[d] + wv.w * __half2float(up[(size_t)l * S]);
    if (l >= 1) acc += wv.z * __half2float(up[(size_t)(l - 1) * S]);
    if (l >= 2) acc += wv.y * __half2float(up[(size_t)(l - 2) * S]);
    if (l >= 3) acc += wv.x * __half2float(up[(size_t)(l - 3) * S]);

    uch[idx] = __float2half_rn(acc / (1.f + __expf(-acc)));

    float zv = __half2float(up[(size_t)l * S + DINNER]);
    gateh[idx] = __float2half_rn(zv / (1.f + __expf(-zv)));
}

__global__ void reduce_split(const float* __restrict__ part,
                             float* __restrict__ out,
                             __half* __restrict__ outh, int n)
{
    int i = blockIdx.x * blockDim.x + threadIdx.x;
    if (i < n) {
        float s = 0.f;
#pragma unroll
        for (int z = 0; z < KSPLIT; ++z) s += part[(size_t)z * n + i];
        out[i]  = s;
        outh[i] = __float2half_rn(s);
    }
}

// ---------------------------------------------------------------------------
// Chunked selective scan (3 phases), geometric-dA fast path, fp16 streams.
// ---------------------------------------------------------------------------
__global__ __launch_bounds__(256)
void scan_p1(const __half* __restrict__ delta, const float* __restrict__ xdbl,
             const __half* __restrict__ uc, const float* __restrict__ A_log,
             float* __restrict__ hfin, float* __restrict__ sumd)
{
    const int b = blockIdx.z;
    const int c = blockIdx.y;
    const int d = blockIdx.x * 256 + threadIdx.x;

    float na[DSTATE];
    const bool geo = load_na(A_log, d, na);
    const float na0 = na[0];

    float h[DSTATE];
#pragma unroll
    for (int s = 0; s < DSTATE; ++s) h[s] = 0.f;
    float sd = 0.f;

    __shared__ float bs[32][DSTATE];

    const int lbeg = c * CHUNK;
    for (int l0 = lbeg; l0 < lbeg + CHUNK; l0 += 32) {
        __syncthreads();
        for (int t = threadIdx.x; t < 32 * DSTATE; t += 256) {
            int i = t >> 4, j = t & 15;
            bs[i][j] = xdbl[(size_t)(b * L_SEQ + l0 + i) * XPROJ_N + 64 + j];
        }
        __syncthreads();
        if (geo) {
#pragma unroll 2
            for (int i = 0; i < 32; ++i) {
                size_t row = (size_t)b * L_SEQ + l0 + i;
                float t  = __half2float(delta[row * DINNER + d]);
                float u  = __half2float(uc[row * DINNER + d]);
                float tu = t * u;
                sd += t;
                float p  = __expf(t * na0);
                float p2 = p * p;
                float ra = p, rb = p2;
                h[0] = fmaf(ra, h[0], tu * bs[i][0]);
                h[1] = fmaf(rb, h[1], tu * bs[i][1]);
#pragma unroll
                for (int s = 2; s < DSTATE; s += 2) {
                    ra *= p2; h[s]     = fmaf(ra, h[s],     tu * bs[i][s]);
                    rb *= p2; h[s + 1] = fmaf(rb, h[s + 1], tu * bs[i][s + 1]);
                }
            }
        } else {
#pragma unroll 2
            for (int i = 0; i < 32; ++i) {
                size_t row = (size_t)b * L_SEQ + l0 + i;
                float t  = __half2float(delta[row * DINNER + d]);
                float u  = __half2float(uc[row * DINNER + d]);
                float tu = t * u;
                sd += t;
#pragma unroll
                for (int s = 0; s < DSTATE; ++s) {
                    float dA = __expf(t * na[s]);
                    h[s] = fmaf(dA, h[s], tu * bs[i][s]);
                }
            }
        }
    }

    const size_t base = ((size_t)(b * NCHUNK + c) * DSTATE) * DINNER + d;
#pragma unroll
    for (int s = 0; s < DSTATE; ++s)
        hfin[base + (size_t)s * DINNER] = h[s];
    sumd[(size_t)(b * NCHUNK + c) * DINNER + d] = sd;
}

__global__ __launch_bounds__(256)
void scan_combine(const float* __restrict__ hfin, const float* __restrict__ sumd,
                  const float* __restrict__ A_log, float* __restrict__ hini)
{
    const int b = blockIdx.y;
    const int d = blockIdx.x * 256 + threadIdx.x;

    float na[DSTATE];
    load_na(A_log, d, na);

    float h[DSTATE];
#pragma unroll
    for (int s = 0; s < DSTATE; ++s) h[s] = 0.f;

    for (int c = 0; c < NCHUNK; ++c) {
        const size_t base = ((size_t)(b * NCHUNK + c) * DSTATE) * DINNER + d;
#pragma unroll
        for (int s = 0; s < DSTATE; ++s)
            hini[base + (size_t)s * DINNER] = h[s];
        float sd = sumd[(size_t)(b * NCHUNK + c) * DINNER + d];
#pragma unroll
        for (int s = 0; s < DSTATE; ++s) {
            float pA = __expf(sd * na[s]);
            h[s] = fmaf(pA, h[s], hfin[base + (size_t)s * DINNER]);
        }
    }
}

__global__ __launch_bounds__(256)
void scan_p3(const __half* __restrict__ delta, const float* __restrict__ xdbl,
             const __half* __restrict__ uc, const __half* __restrict__ gateh,
             const float* __restrict__ A_log, const float* __restrict__ Dv,
             const float* __restrict__ hini, __half* __restrict__ yh)
{
    const int b = blockIdx.z;
    const int c = blockIdx.y;
    const int d = blockIdx.x * 256 + threadIdx.x;

    float na[DSTATE];
    const bool geo = load_na(A_log, d, na);
    const float na0 = na[0];

    float h[DSTATE];
    {
        const size_t base = ((size_t)(b * NCHUNK + c) * DSTATE) * DINNER + d;
#pragma unroll
        for (int s = 0; s < DSTATE; ++s)
            h[s] = hini[base + (size_t)s * DINNER];
    }

    const float Dd = Dv[d];
    __shared__ float bc[32][32];

    const int lbeg = c * CHUNK;
    for (int l0 = lbeg; l0 < lbeg + CHUNK; l0 += 32) {
        __syncthreads();
        for (int t = threadIdx.x; t < 1024; t += 256) {
            int i = t >> 5, j = t & 31;
            bc[i][j] = xdbl[(size_t)(b * L_SEQ + l0 + i) * XPROJ_N + 64 + j];
        }
        __syncthreads();
        if (geo) {
#pragma unroll 2
            for (int i = 0; i < 32; ++i) {
                size_t row = (size_t)b * L_SEQ + l0 + i;
                float t  = __half2float(delta[row * DINNER + d]);
                float u  = __half2float(uc[row * DINNER + d]);
                float tu = t * u;
                float yv = 0.f;
                float p  = __expf(t * na0);
                float p2 = p * p;
                float ra = p, rb = p2;
                h[0] = fmaf(ra, h[0], tu * bc[i][0]);
                yv = fmaf(h[0], bc[i][16], yv);
                h[1] = fmaf(rb, h[1], tu * bc[i][1]);
                yv = fmaf(h[1], bc[i][17], yv);
#pragma unroll
                for (int s = 2; s < DSTATE; s += 2) {
                    ra *= p2;
                    h[s] = fmaf(ra, h[s], tu * bc[i][s]);
                    yv = fmaf(h[s], bc[i][16 + s], yv);
                    rb *= p2;
                    h[s + 1] = fmaf(rb, h[s + 1], tu * bc[i][s + 1]);
                    yv = fmaf(h[s + 1], bc[i][17 + s], yv);
                }
                float g = __half2float(gateh[row * DINNER + d]);
                yh[row * DINNER + d] = __float2half_rn((yv + u * Dd) * g);
            }
        } else {
#pragma unroll 2
            for (int i = 0; i < 32; ++i) {
                size_t row = (size_t)b * L_SEQ + l0 + i;
                float t  = __half2float(delta[row * DINNER + d]);
                float u  = __half2float(uc[row * DINNER + d]);
                float tu = t * u;
                float yv = 0.f;
#pragma unroll
                for (int s = 0; s < DSTATE; ++s) {
                    float dA = __expf(t * na[s]);
                    h[s] = fmaf(dA, h[s], tu * bc[i][s]);
                    yv   = fmaf(h[s], bc[i][16 + s], yv);
                }
                float g = __half2float(gateh[row * DINNER + d]);
                yh[row * DINNER + d] = __float2half_rn((yv + u * Dd) * g);
            }
        }
    }
}

// ---------------------------------------------------------------------------
extern "C" void kernel_launch(void* const* d_in, const int* in_sizes, int n_in,
                              void* d_out, int out_size)
{
    const float* x        = (const float*)d_in[0];
    const float* W_in     = (const float*)d_in[1];
    const float* conv_w   = (const float*)d_in[2];
    const float* conv_b   = (const float*)d_in[3];
    const float* W_xproj  = (const float*)d_in[4];
    const float* W_dtproj = (const float*)d_in[5];
    const float* dt_bias  = (const float*)d_in[6];
    const float* A_log    = (const float*)d_in[7];
    const float* Dv       = (const float*)d_in[8];
    const float* W_out    = (const float*)d_in[9];
    float* out = (float*)d_out;

    float *xpart, *xdbl, *hfin, *hini, *sumd;
    __half *xzh, *xh, *whin, *whxp, *whdt, *whout, *uch, *gateh, *xdblh, *deltah, *yh;
    cudaGetSymbolAddress((void**)&xpart,  g_xpart);
    cudaGetSymbolAddress((void**)&xdbl,   g_xdbl);
    cudaGetSymbolAddress((void**)&hfin,   g_hfin);
    cudaGetSymbolAddress((void**)&hini,   g_hini);
    cudaGetSymbolAddress((void**)&sumd,   g_sumd);
    cudaGetSymbolAddress((void**)&xzh,    g_xzh);
    cudaGetSymbolAddress((void**)&xh,     g_xh);
    cudaGetSymbolAddress((void**)&whin,   g_whin);
    cudaGetSymbolAddress((void**)&whxp,   g_whxp);
    cudaGetSymbolAddress((void**)&whdt,   g_whdt);
    cudaGetSymbolAddress((void**)&whout,  g_whout);
    cudaGetSymbolAddress((void**)&uch,    g_uch);
    cudaGetSymbolAddress((void**)&gateh,  g_gateh);
    cudaGetSymbolAddress((void**)&xdblh,  g_xdblh);
    cudaGetSymbolAddress((void**)&deltah, g_deltah);
    cudaGetSymbolAddress((void**)&yh,     g_yh);

    cudaFuncSetAttribute(mma_tn<0>,
        cudaFuncAttributeMaxDynamicSharedMemorySize, MMA_SMEM_BYTES);
    cudaFuncSetAttribute(mma_tn<1>,
        cudaFuncAttributeMaxDynamicSharedMemorySize, MMA_SMEM_BYTES);
    cudaFuncSetAttribute(mma_tn<2>,
        cudaFuncAttributeMaxDynamicSharedMemorySize, MMA_SMEM_BYTES);

    dim3 blk(256);

    // 0. convert x + all weights to fp16
    f2h_multi<<<dim3(2048, 5), blk>>>(
        x,        xh,    NROWS * DMODEL,
        W_in,     whin,  2 * DINNER * DMODEL,
        W_xproj,  whxp,  XPROJ_N * DINNER,
        W_dtproj, whdt,  DINNER * 64,
        W_out,    whout, DMODEL * DINNER);

    // 1. in_proj: xz[4096,4096] fp16 = x @ W_in^T  (K=1024)
    mma_tn<2><<<dim3(64, 32, 1), blk, MMA_SMEM_BYTES>>>(xh, whin, xzh,
        NROWS, 2 * DINNER, DMODEL, DMODEL, DMODEL, 2 * DINNER,
        nullptr, DMODEL);

    // 2. depthwise conv + silu (fp16 u) + gate silu(z) (fp16)
    conv_silu_k<<<(NROWS * DINNER) / 256, blk>>>(xzh, conv_w, conv_b, uch, gateh);

    // 3. x_proj (split-K x8): x_dbl[4096,96] = u_c @ W_xproj^T (K=2048)
    mma_tn<0><<<dim3(2, 32, KSPLIT), blk, MMA_SMEM_BYTES>>>(uch, whxp, xpart,
        NROWS, XPROJ_N, DINNER, DINNER, DINNER, XPROJ_N,
        nullptr, DINNER / KSPLIT);
    reduce_split<<<(NROWS * XPROJ_N + 255) / 256, blk>>>(
        xpart, xdbl, xdblh, NROWS * XPROJ_N);

    // 4. dt_proj + softplus -> fp16 delta (K=64)
    mma_tn<1><<<dim3(32, 32, 1), blk, MMA_SMEM_BYTES>>>(xdblh, whdt, deltah,
        NROWS, DINNER, 64, XPROJ_N, 64, DINNER,
        dt_bias, 64);

    // 5. chunked selective scan + skip + gate
    scan_p1<<<dim3(DINNER / 256, NCHUNK, NB), blk>>>(
        deltah, xdbl, uch, A_log, hfin, sumd);
    scan_combine<<<dim3(DINNER / 256, NB), blk>>>(hfin, sumd, A_log, hini);
    scan_p3<<<dim3(DINNER / 256, NCHUNK, NB), blk>>>(
        deltah, xdbl, uch, gateh, A_log, Dv, hini, yh);

    // 6. out_proj: out[4096,1024] = y @ W_out^T (K=2048)
    mma_tn<0><<<dim3(16, 32, 1), blk, MMA_SMEM_BYTES>>>(yh, whout, out,
        NROWS, DMODEL, DINNER, DINNER, DINNER, DMODEL,
        nullptr, DINNER);
}

// round 15
// speedup vs baseline: 1.9039x; 1.0404x over previous
#include <cuda_runtime.h>
#include <cuda_fp16.h>
#include <math.h>

// ---------------------------------------------------------------------------
// Mamba block forward. fp16 mma.sync GEMMs (128x64 tile, cp.async 3-stage,
// occ=4); fp16 xz/u/gate/delta/y streams, all __half2-vectorized; chunked
// selective scan (geometric-dA fast path), 2 channels per thread.
//   B=2, L=2048, d_model=1024, d_inner=2048, d_state=16, d_conv=4, dt_rank=64
// tcgen05 unavailable: harness PTX target is compute_103 (no 'a' suffix).
// ---------------------------------------------------------------------------

#define L_SEQ   2048
#define NB      2
#define DMODEL  1024
#define DINNER  2048
#define DSTATE  16
#define NROWS   (NB * L_SEQ)     // 4096
#define XPROJ_N 96
#define KSPLIT  8
#define CHUNK   128
#define NCHUNK  (L_SEQ / CHUNK)  // 16

// fp32 scratch
__device__ float g_xpart [(size_t)KSPLIT * NROWS * XPROJ_N];
__device__ float g_xdbl  [(size_t)NROWS * XPROJ_N];
__device__ float g_hfin  [(size_t)NB * NCHUNK * DSTATE * DINNER];
__device__ float g_hini  [(size_t)NB * NCHUNK * DSTATE * DINNER];
__device__ float g_sumd  [(size_t)NB * NCHUNK * DINNER];
// fp16 operands / activations
__device__ __half g_xzh   [(size_t)NROWS * 2 * DINNER];
__device__ __half g_xh    [(size_t)NROWS * DMODEL];
__device__ __half g_whin  [(size_t)2 * DINNER * DMODEL];
__device__ __half g_whxp  [(size_t)XPROJ_N * DINNER];
__device__ __half g_whdt  [(size_t)DINNER * 64];
__device__ __half g_whout [(size_t)DMODEL * DINNER];
__device__ __half g_uch   [(size_t)NROWS * DINNER];
__device__ __half g_gateh [(size_t)NROWS * DINNER];
__device__ __half g_xdblh [(size_t)NROWS * XPROJ_N];
__device__ __half g_deltah[(size_t)NROWS * DINNER];
__device__ __half g_yh    [(size_t)NROWS * DINNER];

__device__ __forceinline__ float softplusf(float x) {
    return x > 20.f ? x : log1pf(__expf(x));
}
__device__ __forceinline__ unsigned smem_u32(const void* p) {
    return (unsigned)__cvta_generic_to_shared(p);
}
__device__ __forceinline__ void cp_async16(unsigned saddr, const void* gptr, int sz) {
    asm volatile("cp.async.cg.shared.global [%0], [%1], 16, %2;"
                 :: "r"(saddr), "l"(gptr), "r"(sz));
}
__device__ __forceinline__ void cp_commit() {
    asm volatile("cp.async.commit_group;" ::: "memory");
}
template<int N>
__device__ __forceinline__ void cp_wait() {
    asm volatile("cp.async.wait_group %0;" :: "n"(N) : "memory");
}

__device__ __forceinline__ bool load_na(const float* __restrict__ A_log,
                                        int d, float* na)
{
    bool geo = true;
#pragma unroll
    for (int s = 0; s < DSTATE; ++s) {
        na[s] = -__expf(A_log[(size_t)d * DSTATE + s]);
        geo = geo && (fabsf(na[s] - (float)(s + 1) * na[0])
                      <= 1e-5f * fabsf(na[s]));
    }
    return geo;
}

// ---------------------------------------------------------------------------
__global__ __launch_bounds__(256)
void f2h_multi(const float* __restrict__ s0, __half* d0, int n0,
               const float* __restrict__ s1, __half* d1, int n1,
               const float* __restrict__ s2, __half* d2, int n2,
               const float* __restrict__ s3, __half* d3, int n3,
               const float* __restrict__ s4, __half* d4, int n4)
{
    const float* s; __half* d; int n;
    switch (blockIdx.y) {
        case 0: s = s0; d = d0; n = n0; break;
        case 1: s = s1; d = d1; n = n1; break;
        case 2: s = s2; d = d2; n = n2; break;
        case 3: s = s3; d = d3; n = n3; break;
        default: s = s4; d = d4; n = n4; break;
    }
    int nq = n >> 2;
    for (int i = blockIdx.x * blockDim.x + threadIdx.x; i < nq;
         i += gridDim.x * blockDim.x) {
        float4 v = *reinterpret_cast<const float4*>(s + (size_t)i * 4);
        __half2 h0 = __floats2half2_rn(v.x, v.y);
        __half2 h1 = __floats2half2_rn(v.z, v.w);
        *reinterpret_cast<uint2*>(d + (size_t)i * 4) =
            make_uint2(*(unsigned*)&h0, *(unsigned*)&h1);
    }
}

// ---------------------------------------------------------------------------
// fp16 GEMM, 128x64 CTA tile, m16n8k16, cp.async 3-stage ring, occ=4.
// EPI=0: fp32 C (split-K slice). EPI=1: fp16 softplus(acc+bias). EPI=2: fp16 C.
// ---------------------------------------------------------------------------
#define BK      32
#define BSTH    40
#define A_STG   (128 * BSTH)
#define B_STG   (64 * BSTH)
#define STG_H   (A_STG + B_STG)
#define NSTAGE  3
#define MMA_SMEM_BYTES (NSTAGE * STG_H * 2)   // 46080

template<int EPI>
__global__ __launch_bounds__(256, 4)
void mma_tn(const __half* __restrict__ A, const __half* __restrict__ B,
            void* __restrict__ Cv, int M, int N, int K,
            int lda, int ldb, int ldc,
            const float* __restrict__ bias, int kPerSplit)
{
    extern __shared__ __align__(16) __half sh[];

    const int tid  = threadIdx.x;
    const int lane = tid & 31;
    const int wid  = tid >> 5;
    const int wm0  = (wid >> 1) << 5;
    const int wn0  = (wid & 1) << 5;

    const int bm = blockIdx.y << 7;
    const int bn = blockIdx.x << 6;
    const int kbeg = blockIdx.z * kPerSplit;

    float acc[2][4][4];
#pragma unroll
    for (int mt = 0; mt < 2; ++mt)
#pragma unroll
        for (int nt = 0; nt < 4; ++nt)
#pragma unroll
            for (int r = 0; r < 4; ++r) acc[mt][nt][r] = 0.f;

    int a_off[2], b_off[2];
#pragma unroll
    for (int mt = 0; mt < 2; ++mt) {
        int row = wm0 + mt * 16 + ((lane >> 3) & 1) * 8 + (lane & 7);
        int col = (lane >> 4) * 8;
        a_off[mt] = row * BSTH + col;
    }
#pragma unroll
    for (int bt = 0; bt < 2; ++bt) {
        int row = wn0 + bt * 16 + ((lane >> 3) & 1) * 8 + (lane & 7);
        int col = (lane >> 4) * 8;
        b_off[bt] = A_STG + row * BSTH + col;
    }
    const unsigned sh_base = smem_u32(sh);

    const int lrow = tid >> 2;
    const int lc8  = (tid & 3) << 3;

    const __half* gA0 = A + (size_t)(bm + lrow) * lda + kbeg + lc8;
    const __half* gA1 = gA0 + (size_t)64 * lda;
    int rb  = (bn + lrow < N) ? lrow : 0;
    int bsz = (bn + lrow < N) ? 16 : 0;
    const __half* gB0 = B + (size_t)(bn + rb) * ldb + kbeg + lc8;

    const int nk = kPerSplit >> 5;
    const unsigned s_arow0 = (unsigned)((lrow * BSTH + lc8) << 1);
    const unsigned s_arow1 = (unsigned)(((lrow + 64) * BSTH + lc8) << 1);
    const unsigned s_brow  = (unsigned)((A_STG + lrow * BSTH + lc8) << 1);

    auto issue = [&](int t) {
        if (t < nk) {
            unsigned sb = sh_base + (unsigned)(((t % NSTAGE) * STG_H) << 1);
            int koff = t * BK;
            cp_async16(sb + s_arow0, gA0 + koff, 16);
            cp_async16(sb + s_arow1, gA1 + koff, 16);
            cp_async16(sb + s_brow,  gB0 + koff, bsz);
        }
        cp_commit();
    };

    issue(0);
    issue(1);

    for (int t = 0; t < nk; ++t) {
        cp_wait<1>();
        __syncthreads();
        issue(t + 2);

        const unsigned st_base = sh_base + (unsigned)(((t % NSTAGE) * STG_H) << 1);

#pragma unroll
        for (int kk = 0; kk < BK; kk += 16) {
            unsigned a[2][4], b[2][4];
#pragma unroll
            for (int mt = 0; mt < 2; ++mt) {
                unsigned addr = st_base + (unsigned)((a_off[mt] + kk) << 1);
                asm volatile(
                    "ldmatrix.sync.aligned.m8n8.x4.shared.b16 {%0,%1,%2,%3}, [%4];"
                    : "=r"(a[mt][0]), "=r"(a[mt][1]), "=r"(a[mt][2]), "=r"(a[mt][3])
                    : "r"(addr));
            }
#pragma unroll
            for (int bt = 0; bt < 2; ++bt) {
                unsigned addr = st_base + (unsigned)((b_off[bt] + kk) << 1);
                asm volatile(
                    "ldmatrix.sync.aligned.m8n8.x4.shared.b16 {%0,%1,%2,%3}, [%4];"
                    : "=r"(b[bt][0]), "=r"(b[bt][1]), "=r"(b[bt][2]), "=r"(b[bt][3])
                    : "r"(addr));
            }
#pragma unroll
            for (int mt = 0; mt < 2; ++mt)
#pragma unroll
                for (int nt = 0; nt < 4; ++nt) {
                    unsigned b0 = b[nt >> 1][(nt & 1)];
                    unsigned b1 = b[nt >> 1][2 + (nt & 1)];
                    asm volatile(
                        "mma.sync.aligned.m16n8k16.row.col.f32.f16.f16.f32 "
                        "{%0,%1,%2,%3}, {%4,%5,%6,%7}, {%8,%9}, {%0,%1,%2,%3};"
                        : "+f"(acc[mt][nt][0]), "+f"(acc[mt][nt][1]),
                          "+f"(acc[mt][nt][2]), "+f"(acc[mt][nt][3])
                        : "r"(a[mt][0]), "r"(a[mt][1]), "r"(a[mt][2]), "r"(a[mt][3]),
                          "r"(b0), "r"(b1));
                }
        }
    }

    const int gid = lane >> 2;
    const int tig = lane & 3;
#pragma unroll
    for (int mt = 0; mt < 2; ++mt)
#pragma unroll
        for (int nt = 0; nt < 4; ++nt) {
            int m = bm + wm0 + mt * 16 + gid;
            int n = bn + wn0 + nt * 8 + tig * 2;
            if (n < N) {
                float v0 = acc[mt][nt][0], v1 = acc[mt][nt][1];
                float v2 = acc[mt][nt][2], v3 = acc[mt][nt][3];
                if (EPI == 1) {
                    float b0v = bias[n], b1v = bias[n + 1];
                    v0 = softplusf(v0 + b0v); v1 = softplusf(v1 + b1v);
                    v2 = softplusf(v2 + b0v); v3 = softplusf(v3 + b1v);
                    __half* C = (__half*)Cv;
                    *reinterpret_cast<__half2*>(C + (size_t)m * ldc + n) =
                        __floats2half2_rn(v0, v1);
                    *reinterpret_cast<__half2*>(C + (size_t)(m + 8) * ldc + n) =
                        __floats2half2_rn(v2, v3);
                } else if (EPI == 2) {
                    __half* C = (__half*)Cv;
                    *reinterpret_cast<__half2*>(C + (size_t)m * ldc + n) =
                        __floats2half2_rn(v0, v1);
                    *reinterpret_cast<__half2*>(C + (size_t)(m + 8) * ldc + n) =
                        __floats2half2_rn(v2, v3);
                } else {
                    float* C = (float*)Cv + (size_t)blockIdx.z * (size_t)M * (size_t)ldc;
                    *reinterpret_cast<float2*>(C + (size_t)m * ldc + n) =
                        make_float2(v0, v1);
                    *reinterpret_cast<float2*>(C + (size_t)(m + 8) * ldc + n) =
                        make_float2(v2, v3);
                }
            }
        }
}

// ---------------------------------------------------------------------------
// conv + silu + gate, __half2-vectorized: each thread handles 2 channels.
// ---------------------------------------------------------------------------
__global__ __launch_bounds__(256)
void conv_silu_k(const __half* __restrict__ xz, const float* __restrict__ w,
                 const float* __restrict__ cb, __half* __restrict__ uch,
                 __half* __restrict__ gateh)
{
    int idx = blockIdx.x * blockDim.x + threadIdx.x;      // pair index
    if (idx >= NROWS * (DINNER / 2)) return;
    int dp  = idx & (DINNER / 2 - 1);
    int d2  = dp << 1;
    int row = idx >> 10;                 // / (DINNER/2)
    int l   = row & (L_SEQ - 1);
    int b   = row >> 11;

    const float4 w0 = *reinterpret_cast<const float4*>(w + (size_t)d2 * 4);
    const float4 w1 = *reinterpret_cast<const float4*>(w + (size_t)(d2 + 1) * 4);
    const float2 cbv = *reinterpret_cast<const float2*>(cb + d2);

    const __half* up = xz + (size_t)b * L_SEQ * (2 * DINNER) + d2;
    const size_t S = 2 * DINNER;

    float2 v;
    float a0 = cbv.x, a1 = cbv.y;
    v = __half22float2(*reinterpret_cast<const __half2*>(up + (size_t)l * S));
    a0 = fmaf(w0.w, v.x, a0); a1 = fmaf(w1.w, v.y, a1);
    if (l >= 1) {
        v = __half22float2(*reinterpret_cast<const __half2*>(up + (size_t)(l - 1) * S));
        a0 = fmaf(w0.z, v.x, a0); a1 = fmaf(w1.z, v.y, a1);
    }
    if (l >= 2) {
        v = __half22float2(*reinterpret_cast<const __half2*>(up + (size_t)(l - 2) * S));
        a0 = fmaf(w0.y, v.x, a0); a1 = fmaf(w1.y, v.y, a1);
    }
    if (l >= 3) {
        v = __half22float2(*reinterpret_cast<const __half2*>(up + (size_t)(l - 3) * S));
        a0 = fmaf(w0.x, v.x, a0); a1 = fmaf(w1.x, v.y, a1);
    }

    *reinterpret_cast<__half2*>(uch + (size_t)row * DINNER + d2) =
        __floats2half2_rn(a0 / (1.f + __expf(-a0)), a1 / (1.f + __expf(-a1)));

    float2 z = __half22float2(
        *reinterpret_cast<const __half2*>(up + (size_t)l * S + DINNER));
    *reinterpret_cast<__half2*>(gateh + (size_t)row * DINNER + d2) =
        __floats2half2_rn(z.x / (1.f + __expf(-z.x)), z.y / (1.f + __expf(-z.y)));
}

__global__ void reduce_split(const float* __restrict__ part,
                             float* __restrict__ out,
                             __half* __restrict__ outh, int n)
{
    int i = blockIdx.x * blockDim.x + threadIdx.x;
    if (i < n) {
        float s = 0.f;
#pragma unroll
        for (int z = 0; z < KSPLIT; ++z) s += part[(size_t)z * n + i];
        out[i]  = s;
        outh[i] = __float2half_rn(s);
    }
}

// ---------------------------------------------------------------------------
// Chunked selective scan, 2 channels/thread (128-thread blocks), __half2 IO.
// ---------------------------------------------------------------------------
__global__ __launch_bounds__(128)
void scan_p1(const __half* __restrict__ delta, const float* __restrict__ xdbl,
             const __half* __restrict__ uc, const float* __restrict__ A_log,
             float* __restrict__ hfin, float* __restrict__ sumd)
{
    const int b = blockIdx.z;
    const int c = blockIdx.y;
    const int d0 = blockIdx.x * 256 + threadIdx.x * 2;

    float na0[DSTATE], na1[DSTATE];
    const bool geo = load_na(A_log, d0, na0) & load_na(A_log, d0 + 1, na1);
    const float n00 = na0[0], n01 = na1[0];

    float h0[DSTATE], h1[DSTATE];
#pragma unroll
    for (int s = 0; s < DSTATE; ++s) { h0[s] = 0.f; h1[s] = 0.f; }
    float sd0 = 0.f, sd1 = 0.f;

    __shared__ float bs[32][DSTATE];

    const int lbeg = c * CHUNK;
    for (int l0 = lbeg; l0 < lbeg + CHUNK; l0 += 32) {
        __syncthreads();
        for (int t = threadIdx.x; t < 32 * DSTATE; t += 128) {
            int i = t >> 4, j = t & 15;
            bs[i][j] = xdbl[(size_t)(b * L_SEQ + l0 + i) * XPROJ_N + 64 + j];
        }
        __syncthreads();
        if (geo) {
#pragma unroll 2
            for (int i = 0; i < 32; ++i) {
                size_t row = (size_t)b * L_SEQ + l0 + i;
                float2 td = __half22float2(
                    *reinterpret_cast<const __half2*>(delta + row * DINNER + d0));
                float2 ud = __half22float2(
                    *reinterpret_cast<const __half2*>(uc + row * DINNER + d0));
                float tu0 = td.x * ud.x, tu1 = td.y * ud.y;
                sd0 += td.x; sd1 += td.y;
                float p0 = __expf(td.x * n00), p1 = __expf(td.y * n01);
                float q0 = p0 * p0, q1 = p1 * p1;
                float ra0 = p0, rb0 = q0, ra1 = p1, rb1 = q1;
                h0[0] = fmaf(ra0, h0[0], tu0 * bs[i][0]);
                h1[0] = fmaf(ra1, h1[0], tu1 * bs[i][0]);
                h0[1] = fmaf(rb0, h0[1], tu0 * bs[i][1]);
                h1[1] = fmaf(rb1, h1[1], tu1 * bs[i][1]);
#pragma unroll
                for (int s = 2; s < DSTATE; s += 2) {
                    ra0 *= q0; ra1 *= q1;
                    h0[s] = fmaf(ra0, h0[s], tu0 * bs[i][s]);
                    h1[s] = fmaf(ra1, h1[s], tu1 * bs[i][s]);
                    rb0 *= q0; rb1 *= q1;
                    h0[s+1] = fmaf(rb0, h0[s+1], tu0 * bs[i][s+1]);
                    h1[s+1] = fmaf(rb1, h1[s+1], tu1 * bs[i][s+1]);
                }
            }
        } else {
#pragma unroll 2
            for (int i = 0; i < 32; ++i) {
                size_t row = (size_t)b * L_SEQ + l0 + i;
                float2 td = __half22float2(
                    *reinterpret_cast<const __half2*>(delta + row * DINNER + d0));
                float2 ud = __half22float2(
                    *reinterpret_cast<const __half2*>(uc + row * DINNER + d0));
                float tu0 = td.x * ud.x, tu1 = td.y * ud.y;
                sd0 += td.x; sd1 += td.y;
#pragma unroll
                for (int s = 0; s < DSTATE; ++s) {
                    h0[s] = fmaf(__expf(td.x * na0[s]), h0[s], tu0 * bs[i][s]);
                    h1[s] = fmaf(__expf(td.y * na1[s]), h1[s], tu1 * bs[i][s]);
                }
            }
        }
    }

    const size_t base = ((size_t)(b * NCHUNK + c) * DSTATE) * DINNER + d0;
#pragma unroll
    for (int s = 0; s < DSTATE; ++s)
        *reinterpret_cast<float2*>(hfin + base + (size_t)s * DINNER) =
            make_float2(h0[s], h1[s]);
    *reinterpret_cast<float2*>(sumd + (size_t)(b * NCHUNK + c) * DINNER + d0) =
        make_float2(sd0, sd1);
}

__global__ __launch_bounds__(256)
void scan_combine(const float* __restrict__ hfin, const float* __restrict__ sumd,
                  const float* __restrict__ A_log, float* __restrict__ hini)
{
    const int b = blockIdx.y;
    const int d = blockIdx.x * 256 + threadIdx.x;

    float na[DSTATE];
    load_na(A_log, d, na);

    float h[DSTATE];
#pragma unroll
    for (int s = 0; s < DSTATE; ++s) h[s] = 0.f;

    for (int c = 0; c < NCHUNK; ++c) {
        const size_t base = ((size_t)(b * NCHUNK + c) * DSTATE) * DINNER + d;
#pragma unroll
        for (int s = 0; s < DSTATE; ++s)
            hini[base + (size_t)s * DINNER] = h[s];
        float sd = sumd[(size_t)(b * NCHUNK + c) * DINNER + d];
#pragma unroll
        for (int s = 0; s < DSTATE; ++s) {
            float pA = __expf(sd * na[s]);
            h[s] = fmaf(pA, h[s], hfin[base + (size_t)s * DINNER]);
        }
    }
}

__global__ __launch_bounds__(128)
void scan_p3(const __half* __restrict__ delta, const float* __restrict__ xdbl,
             const __half* __restrict__ uc, const __half* __restrict__ gateh,
             const float* __restrict__ A_log, const float* __restrict__ Dv,
             const float* __restrict__ hini, __half* __restrict__ yh)
{
    const int b = blockIdx.z;
    const int c = blockIdx.y;
    const int d0 = blockIdx.x * 256 + threadIdx.x * 2;

    float na0[DSTATE], na1[DSTATE];
    const bool geo = load_na(A_log, d0, na0) & load_na(A_log, d0 + 1, na1);
    const float n00 = na0[0], n01 = na1[0];

    float h0[DSTATE], h1[DSTATE];
    {
        const size_t base = ((size_t)(b * NCHUNK + c) * DSTATE) * DINNER + d0;
#pragma unroll
        for (int s = 0; s < DSTATE; ++s) {
            float2 hv = *reinterpret_cast<const float2*>(
                hini + base + (size_t)s * DINNER);
            h0[s] = hv.x; h1[s] = hv.y;
        }
    }

    const float2 Dd = *reinterpret_cast<const float2*>(Dv + d0);
    __shared__ float bc[32][32];

    const int lbeg = c * CHUNK;
    for (int l0 = lbeg; l0 < lbeg + CHUNK; l0 += 32) {
        __syncthreads();
        for (int t = threadIdx.x; t < 1024; t += 128) {
            int i = t >> 5, j = t & 31;
            bc[i][j] = xdbl[(size_t)(b * L_SEQ + l0 + i) * XPROJ_N + 64 + j];
        }
        __syncthreads();
        if (geo) {
#pragma unroll 2
            for (int i = 0; i < 32; ++i) {
                size_t row = (size_t)b * L_SEQ + l0 + i;
                float2 td = __half22float2(
                    *reinterpret_cast<const __half2*>(delta + row * DINNER + d0));
                float2 ud = __half22float2(
                    *reinterpret_cast<const __half2*>(uc + row * DINNER + d0));
                float tu0 = td.x * ud.x, tu1 = td.y * ud.y;
                float yv0 = 0.f, yv1 = 0.f;
                float p0 = __expf(td.x * n00), p1 = __expf(td.y * n01);
                float q0 = p0 * p0, q1 = p1 * p1;
                float ra0 = p0, rb0 = q0, ra1 = p1, rb1 = q1;
                h0[0] = fmaf(ra0, h0[0], tu0 * bc[i][0]);
                h1[0] = fmaf(ra1, h1[0], tu1 * bc[i][0]);
                yv0 = fmaf(h0[0], bc[i][16], yv0);
                yv1 = fmaf(h1[0], bc[i][16], yv1);
                h0[1] = fmaf(rb0, h0[1], tu0 * bc[i][1]);
                h1[1] = fmaf(rb1, h1[1], tu1 * bc[i][1]);
                yv0 = fmaf(h0[1], bc[i][17], yv0);
                yv1 = fmaf(h1[1], bc[i][17], yv1);
#pragma unroll
                for (int s = 2; s < DSTATE; s += 2) {
                    ra0 *= q0; ra1 *= q1;
                    h0[s] = fmaf(ra0, h0[s], tu0 * bc[i][s]);
                    h1[s] = fmaf(ra1, h1[s], tu1 * bc[i][s]);
                    yv0 = fmaf(h0[s], bc[i][16 + s], yv0);
                    yv1 = fmaf(h1[s], bc[i][16 + s], yv1);
                    rb0 *= q0; rb1 *= q1;
                    h0[s+1] = fmaf(rb0, h0[s+1], tu0 * bc[i][s+1]);
                    h1[s+1] = fmaf(rb1, h1[s+1], tu1 * bc[i][s+1]);
                    yv0 = fmaf(h0[s+1], bc[i][17 + s], yv0);
                    yv1 = fmaf(h1[s+1], bc[i][17 + s], yv1);
                }
                float2 g = __half22float2(
                    *reinterpret_cast<const __half2*>(gateh + row * DINNER + d0));
                *reinterpret_cast<__half2*>(yh + row * DINNER + d0) =
                    __floats2half2_rn((yv0 + ud.x * Dd.x) * g.x,
                                      (yv1 + ud.y * Dd.y) * g.y);
            }
        } else {
#pragma unroll 2
            for (int i = 0; i < 32; ++i) {
                size_t row = (size_t)b * L_SEQ + l0 + i;
                float2 td = __half22float2(
                    *reinterpret_cast<const __half2*>(delta + row * DINNER + d0));
                float2 ud = __half22float2(
                    *reinterpret_cast<const __half2*>(uc + row * DINNER + d0));
                float tu0 = td.x * ud.x, tu1 = td.y * ud.y;
                float yv0 = 0.f, yv1 = 0.f;
#pragma unroll
                for (int s = 0; s < DSTATE; ++s) {
                    h0[s] = fmaf(__expf(td.x * na0[s]), h0[s], tu0 * bc[i][s]);
                    h1[s] = fmaf(__expf(td.y * na1[s]), h1[s], tu1 * bc[i][s]);
                    yv0 = fmaf(h0[s], bc[i][16 + s], yv0);
                    yv1 = fmaf(h1[s], bc[i][16 + s], yv1);
                }
                float2 g = __half22float2(
                    *reinterpret_cast<const __half2*>(gateh + row * DINNER + d0));
                *reinterpret_cast<__half2*>(yh + row * DINNER + d0) =
                    __floats2half2_rn((yv0 + ud.x * Dd.x) * g.x,
                                      (yv1 + ud.y * Dd.y) * g.y);
            }
        }
    }
}

// ---------------------------------------------------------------------------
extern "C" void kernel_launch(void* const* d_in, const int* in_sizes, int n_in,
                              void* d_out, int out_size)
{
    const float* x        = (const float*)d_in[0];
    const float* W_in     = (const float*)d_in[1];
    const float* conv_w   = (const float*)d_in[2];
    const float* conv_b   = (const float*)d_in[3];
    const float* W_xproj  = (const float*)d_in[4];
    const float* W_dtproj = (const float*)d_in[5];
    const float* dt_bias  = (const float*)d_in[6];
    const float* A_log    = (const float*)d_in[7];
    const float* Dv       = (const float*)d_in[8];
    const float* W_out    = (const float*)d_in[9];
    float* out = (float*)d_out;

    float *xpart, *xdbl, *hfin, *hini, *sumd;
    __half *xzh, *xh, *whin, *whxp, *whdt, *whout, *uch, *gateh, *xdblh, *deltah, *yh;
    cudaGetSymbolAddress((void**)&xpart,  g_xpart);
    cudaGetSymbolAddress((void**)&xdbl,   g_xdbl);
    cudaGetSymbolAddress((void**)&hfin,   g_hfin);
    cudaGetSymbolAddress((void**)&hini,   g_hini);
    cudaGetSymbolAddress((void**)&sumd,   g_sumd);
    cudaGetSymbolAddress((void**)&xzh,    g_xzh);
    cudaGetSymbolAddress((void**)&xh,     g_xh);
    cudaGetSymbolAddress((void**)&whin,   g_whin);
    cudaGetSymbolAddress((void**)&whxp,   g_whxp);
    cudaGetSymbolAddress((void**)&whdt,   g_whdt);
    cudaGetSymbolAddress((void**)&whout,  g_whout);
    cudaGetSymbolAddress((void**)&uch,    g_uch);
    cudaGetSymbolAddress((void**)&gateh,  g_gateh);
    cudaGetSymbolAddress((void**)&xdblh,  g_xdblh);
    cudaGetSymbolAddress((void**)&deltah, g_deltah);
    cudaGetSymbolAddress((void**)&yh,     g_yh);

    cudaFuncSetAttribute(mma_tn<0>,
        cudaFuncAttributeMaxDynamicSharedMemorySize, MMA_SMEM_BYTES);
    cudaFuncSetAttribute(mma_tn<1>,
        cudaFuncAttributeMaxDynamicSharedMemorySize, MMA_SMEM_BYTES);
    cudaFuncSetAttribute(mma_tn<2>,
        cudaFuncAttributeMaxDynamicSharedMemorySize, MMA_SMEM_BYTES);

    dim3 blk(256);

    // 0. convert x + all weights to fp16
    f2h_multi<<<dim3(2048, 5), blk>>>(
        x,        xh,    NROWS * DMODEL,
        W_in,     whin,  2 * DINNER * DMODEL,
        W_xproj,  whxp,  XPROJ_N * DINNER,
        W_dtproj, whdt,  DINNER * 64,
        W_out,    whout, DMODEL * DINNER);

    // 1. in_proj: xz[4096,4096] fp16 = x @ W_in^T  (K=1024)
    mma_tn<2><<<dim3(64, 32, 1), blk, MMA_SMEM_BYTES>>>(xh, whin, xzh,
        NROWS, 2 * DINNER, DMODEL, DMODEL, DMODEL, 2 * DINNER,
        nullptr, DMODEL);

    // 2. depthwise conv + silu + gate (half2 vectorized)
    conv_silu_k<<<(NROWS * DINNER / 2) / 256, blk>>>(xzh, conv_w, conv_b,
                                                     uch, gateh);

    // 3. x_proj (split-K x8)
    mma_tn<0><<<dim3(2, 32, KSPLIT), blk, MMA_SMEM_BYTES>>>(uch, whxp, xpart,
        NROWS, XPROJ_N, DINNER, DINNER, DINNER, XPROJ_N,
        nullptr, DINNER / KSPLIT);
    reduce_split<<<(NROWS * XPROJ_N + 255) / 256, blk>>>(
        xpart, xdbl, xdblh, NROWS * XPROJ_N);

    // 4. dt_proj + softplus -> fp16 delta (K=64)
    mma_tn<1><<<dim3(32, 32, 1), blk, MMA_SMEM_BYTES>>>(xdblh, whdt, deltah,
        NROWS, DINNER, 64, XPROJ_N, 64, DINNER,
        dt_bias, 64);

    // 5. chunked selective scan (2 channels/thread)
    scan_p1<<<dim3(DINNER / 256, NCHUNK, NB), dim3(128)>>>(
        deltah, xdbl, uch, A_log, hfin, sumd);
    scan_combine<<<dim3(DINNER / 256, NB), blk>>>(hfin, sumd, A_log, hini);
    scan_p3<<<dim3(DINNER / 256, NCHUNK, NB), dim3(128)>>>(
        deltah, xdbl, uch, gateh, A_log, Dv, hini, yh);

    // 6. out_proj: out[4096,1024] = y @ W_out^T (K=2048)
    mma_tn<0><<<dim3(16, 32, 1), blk, MMA_SMEM_BYTES>>>(yh, whout, out,
        NROWS, DMODEL, DINNER, DINNER, DINNER, DMODEL,
        nullptr, DINNER);
}

// round 16
// speedup vs baseline: 1.9415x; 1.0198x over previous
#include <cuda_runtime.h>
#include <cuda_fp16.h>
#include <math.h>

// ---------------------------------------------------------------------------
// Mamba block forward. fp16 mma.sync GEMMs (128x64 tile, cp.async 3-stage,
// occ=4); fp16 streams, __half2-vectorized; chunked selective scan
// (geometric-dA fast path, CHUNK=64 for 2x scan occupancy), 2 ch/thread.
//   B=2, L=2048, d_model=1024, d_inner=2048, d_state=16, d_conv=4, dt_rank=64
// tcgen05 unavailable: harness PTX target is compute_103 (no 'a' suffix).
// ---------------------------------------------------------------------------

#define L_SEQ   2048
#define NB      2
#define DMODEL  1024
#define DINNER  2048
#define DSTATE  16
#define NROWS   (NB * L_SEQ)     // 4096
#define XPROJ_N 96
#define KSPLIT  8
#define CHUNK   64
#define NCHUNK  (L_SEQ / CHUNK)  // 32

// fp32 scratch
__device__ float g_xpart [(size_t)KSPLIT * NROWS * XPROJ_N];
__device__ float g_xdbl  [(size_t)NROWS * XPROJ_N];
__device__ float g_hfin  [(size_t)NB * NCHUNK * DSTATE * DINNER];
__device__ float g_hini  [(size_t)NB * NCHUNK * DSTATE * DINNER];
__device__ float g_sumd  [(size_t)NB * NCHUNK * DINNER];
// fp16 operands / activations
__device__ __half g_xzh   [(size_t)NROWS * 2 * DINNER];
__device__ __half g_xh    [(size_t)NROWS * DMODEL];
__device__ __half g_whin  [(size_t)2 * DINNER * DMODEL];
__device__ __half g_whxp  [(size_t)XPROJ_N * DINNER];
__device__ __half g_whdt  [(size_t)DINNER * 64];
__device__ __half g_whout [(size_t)DMODEL * DINNER];
__device__ __half g_uch   [(size_t)NROWS * DINNER];
__device__ __half g_gateh [(size_t)NROWS * DINNER];
__device__ __half g_xdblh [(size_t)NROWS * XPROJ_N];
__device__ __half g_deltah[(size_t)NROWS * DINNER];
__device__ __half g_yh    [(size_t)NROWS * DINNER];

__device__ __forceinline__ float softplusf(float x) {
    return x > 20.f ? x : log1pf(__expf(x));
}
__device__ __forceinline__ unsigned smem_u32(const void* p) {
    return (unsigned)__cvta_generic_to_shared(p);
}
__device__ __forceinline__ void cp_async16(unsigned saddr, const void* gptr, int sz) {
    asm volatile("cp.async.cg.shared.global [%0], [%1], 16, %2;"
                 :: "r"(saddr), "l"(gptr), "r"(sz));
}
__device__ __forceinline__ void cp_commit() {
    asm volatile("cp.async.commit_group;" ::: "memory");
}
template<int N>
__device__ __forceinline__ void cp_wait() {
    asm volatile("cp.async.wait_group %0;" :: "n"(N) : "memory");
}

__device__ __forceinline__ bool load_na(const float* __restrict__ A_log,
                                        int d, float* na)
{
    bool geo = true;
#pragma unroll
    for (int s = 0; s < DSTATE; ++s) {
        na[s] = -__expf(A_log[(size_t)d * DSTATE + s]);
        geo = geo && (fabsf(na[s] - (float)(s + 1) * na[0])
                      <= 1e-5f * fabsf(na[s]));
    }
    return geo;
}

// ---------------------------------------------------------------------------
__global__ __launch_bounds__(256)
void f2h_multi(const float* __restrict__ s0, __half* d0, int n0,
               const float* __restrict__ s1, __half* d1, int n1,
               const float* __restrict__ s2, __half* d2, int n2,
               const float* __restrict__ s3, __half* d3, int n3,
               const float* __restrict__ s4, __half* d4, int n4)
{
    const float* s; __half* d; int n;
    switch (blockIdx.y) {
        case 0: s = s0; d = d0; n = n0; break;
        case 1: s = s1; d = d1; n = n1; break;
        case 2: s = s2; d = d2; n = n2; break;
        case 3: s = s3; d = d3; n = n3; break;
        default: s = s4; d = d4; n = n4; break;
    }
    int nq = n >> 2;
    for (int i = blockIdx.x * blockDim.x + threadIdx.x; i < nq;
         i += gridDim.x * blockDim.x) {
        float4 v = *reinterpret_cast<const float4*>(s + (size_t)i * 4);
        __half2 h0 = __floats2half2_rn(v.x, v.y);
        __half2 h1 = __floats2half2_rn(v.z, v.w);
        *reinterpret_cast<uint2*>(d + (size_t)i * 4) =
            make_uint2(*(unsigned*)&h0, *(unsigned*)&h1);
    }
}

// ---------------------------------------------------------------------------
// fp16 GEMM, 128x64 CTA tile, m16n8k16, cp.async 3-stage ring, occ=4.
// EPI=0: fp32 C (split-K slice). EPI=1: fp16 softplus(acc+bias). EPI=2: fp16 C.
// ---------------------------------------------------------------------------
#define BK      32
#define BSTH    40
#define A_STG   (128 * BSTH)
#define B_STG   (64 * BSTH)
#define STG_H   (A_STG + B_STG)
#define NSTAGE  3
#define MMA_SMEM_BYTES (NSTAGE * STG_H * 2)   // 46080

template<int EPI>
__global__ __launch_bounds__(256, 4)
void mma_tn(const __half* __restrict__ A, const __half* __restrict__ B,
            void* __restrict__ Cv, int M, int N, int K,
            int lda, int ldb, int ldc,
            const float* __restrict__ bias, int kPerSplit)
{
    extern __shared__ __align__(16) __half sh[];

    const int tid  = threadIdx.x;
    const int lane = tid & 31;
    const int wid  = tid >> 5;
    const int wm0  = (wid >> 1) << 5;
    const int wn0  = (wid & 1) << 5;

    const int bm = blockIdx.y << 7;
    const int bn = blockIdx.x << 6;
    const int kbeg = blockIdx.z * kPerSplit;

    float acc[2][4][4];
#pragma unroll
    for (int mt = 0; mt < 2; ++mt)
#pragma unroll
        for (int nt = 0; nt < 4; ++nt)
#pragma unroll
            for (int r = 0; r < 4; ++r) acc[mt][nt][r] = 0.f;

    int a_off[2], b_off[2];
#pragma unroll
    for (int mt = 0; mt < 2; ++mt) {
        int row = wm0 + mt * 16 + ((lane >> 3) & 1) * 8 + (lane & 7);
        int col = (lane >> 4) * 8;
        a_off[mt] = row * BSTH + col;
    }
#pragma unroll
    for (int bt = 0; bt < 2; ++bt) {
        int row = wn0 + bt * 16 + ((lane >> 3) & 1) * 8 + (lane & 7);
        int col = (lane >> 4) * 8;
        b_off[bt] = A_STG + row * BSTH + col;
    }
    const unsigned sh_base = smem_u32(sh);

    const int lrow = tid >> 2;
    const int lc8  = (tid & 3) << 3;

    const __half* gA0 = A + (size_t)(bm + lrow) * lda + kbeg + lc8;
    const __half* gA1 = gA0 + (size_t)64 * lda;
    int rb  = (bn + lrow < N) ? lrow : 0;
    int bsz = (bn + lrow < N) ? 16 : 0;
    const __half* gB0 = B + (size_t)(bn + rb) * ldb + kbeg + lc8;

    const int nk = kPerSplit >> 5;
    const unsigned s_arow0 = (unsigned)((lrow * BSTH + lc8) << 1);
    const unsigned s_arow1 = (unsigned)(((lrow + 64) * BSTH + lc8) << 1);
    const unsigned s_brow  = (unsigned)((A_STG + lrow * BSTH + lc8) << 1);

    auto issue = [&](int t) {
        if (t < nk) {
            unsigned sb = sh_base + (unsigned)(((t % NSTAGE) * STG_H) << 1);
            int koff = t * BK;
            cp_async16(sb + s_arow0, gA0 + koff, 16);
            cp_async16(sb + s_arow1, gA1 + koff, 16);
            cp_async16(sb + s_brow,  gB0 + koff, bsz);
        }
        cp_commit();
    };

    issue(0);
    issue(1);

    for (int t = 0; t < nk; ++t) {
        cp_wait<1>();
        __syncthreads();
        issue(t + 2);

        const unsigned st_base = sh_base + (unsigned)(((t % NSTAGE) * STG_H) << 1);

#pragma unroll
        for (int kk = 0; kk < BK; kk += 16) {
            unsigned a[2][4], b[2][4];
#pragma unroll
            for (int mt = 0; mt < 2; ++mt) {
                unsigned addr = st_base + (unsigned)((a_off[mt] + kk) << 1);
                asm volatile(
                    "ldmatrix.sync.aligned.m8n8.x4.shared.b16 {%0,%1,%2,%3}, [%4];"
                    : "=r"(a[mt][0]), "=r"(a[mt][1]), "=r"(a[mt][2]), "=r"(a[mt][3])
                    : "r"(addr));
            }
#pragma unroll
            for (int bt = 0; bt < 2; ++bt) {
                unsigned addr = st_base + (unsigned)((b_off[bt] + kk) << 1);
                asm volatile(
                    "ldmatrix.sync.aligned.m8n8.x4.shared.b16 {%0,%1,%2,%3}, [%4];"
                    : "=r"(b[bt][0]), "=r"(b[bt][1]), "=r"(b[bt][2]), "=r"(b[bt][3])
                    : "r"(addr));
            }
#pragma unroll
            for (int mt = 0; mt < 2; ++mt)
#pragma unroll
                for (int nt = 0; nt < 4; ++nt) {
                    unsigned b0 = b[nt >> 1][(nt & 1)];
                    unsigned b1 = b[nt >> 1][2 + (nt & 1)];
                    asm volatile(
                        "mma.sync.aligned.m16n8k16.row.col.f32.f16.f16.f32 "
                        "{%0,%1,%2,%3}, {%4,%5,%6,%7}, {%8,%9}, {%0,%1,%2,%3};"
                        : "+f"(acc[mt][nt][0]), "+f"(acc[mt][nt][1]),
                          "+f"(acc[mt][nt][2]), "+f"(acc[mt][nt][3])
                        : "r"(a[mt][0]), "r"(a[mt][1]), "r"(a[mt][2]), "r"(a[mt][3]),
                          "r"(b0), "r"(b1));
                }
        }
    }

    const int gid = lane >> 2;
    const int tig = lane & 3;
#pragma unroll
    for (int mt = 0; mt < 2; ++mt)
#pragma unroll
        for (int nt = 0; nt < 4; ++nt) {
            int m = bm + wm0 + mt * 16 + gid;
            int n = bn + wn0 + nt * 8 + tig * 2;
            if (n < N) {
                float v0 = acc[mt][nt][0], v1 = acc[mt][nt][1];
                float v2 = acc[mt][nt][2], v3 = acc[mt][nt][3];
                if (EPI == 1) {
                    float b0v = bias[n], b1v = bias[n + 1];
                    v0 = softplusf(v0 + b0v); v1 = softplusf(v1 + b1v);
                    v2 = softplusf(v2 + b0v); v3 = softplusf(v3 + b1v);
                    __half* C = (__half*)Cv;
                    *reinterpret_cast<__half2*>(C + (size_t)m * ldc + n) =
                        __floats2half2_rn(v0, v1);
                    *reinterpret_cast<__half2*>(C + (size_t)(m + 8) * ldc + n) =
                        __floats2half2_rn(v2, v3);
                } else if (EPI == 2) {
                    __half* C = (__half*)Cv;
                    *reinterpret_cast<__half2*>(C + (size_t)m * ldc + n) =
                        __floats2half2_rn(v0, v1);
                    *reinterpret_cast<__half2*>(C + (size_t)(m + 8) * ldc + n) =
                        __floats2half2_rn(v2, v3);
                } else {
                    float* C = (float*)Cv + (size_t)blockIdx.z * (size_t)M * (size_t)ldc;
                    *reinterpret_cast<float2*>(C + (size_t)m * ldc + n) =
                        make_float2(v0, v1);
                    *reinterpret_cast<float2*>(C + (size_t)(m + 8) * ldc + n) =
                        make_float2(v2, v3);
                }
            }
        }
}

// ---------------------------------------------------------------------------
// conv + silu + gate, __half2-vectorized: each thread handles 2 channels.
// ---------------------------------------------------------------------------
__global__ __launch_bounds__(256)
void conv_silu_k(const __half* __restrict__ xz, const float* __restrict__ w,
                 const float* __restrict__ cb, __half* __restrict__ uch,
                 __half* __restrict__ gateh)
{
    int idx = blockIdx.x * blockDim.x + threadIdx.x;
    if (idx >= NROWS * (DINNER / 2)) return;
    int dp  = idx & (DINNER / 2 - 1);
    int d2  = dp << 1;
    int row = idx >> 10;
    int l   = row & (L_SEQ - 1);
    int b   = row >> 11;

    const float4 w0 = *reinterpret_cast<const float4*>(w + (size_t)d2 * 4);
    const float4 w1 = *reinterpret_cast<const float4*>(w + (size_t)(d2 + 1) * 4);
    const float2 cbv = *reinterpret_cast<const float2*>(cb + d2);

    const __half* up = xz + (size_t)b * L_SEQ * (2 * DINNER) + d2;
    const size_t S = 2 * DINNER;

    float2 v;
    float a0 = cbv.x, a1 = cbv.y;
    v = __half22float2(*reinterpret_cast<const __half2*>(up + (size_t)l * S));
    a0 = fmaf(w0.w, v.x, a0); a1 = fmaf(w1.w, v.y, a1);
    if (l >= 1) {
        v = __half22float2(*reinterpret_cast<const __half2*>(up + (size_t)(l - 1) * S));
        a0 = fmaf(w0.z, v.x, a0); a1 = fmaf(w1.z, v.y, a1);
    }
    if (l >= 2) {
        v = __half22float2(*reinterpret_cast<const __half2*>(up + (size_t)(l - 2) * S));
        a0 = fmaf(w0.y, v.x, a0); a1 = fmaf(w1.y, v.y, a1);
    }
    if (l >= 3) {
        v = __half22float2(*reinterpret_cast<const __half2*>(up + (size_t)(l - 3) * S));
        a0 = fmaf(w0.x, v.x, a0); a1 = fmaf(w1.x, v.y, a1);
    }

    *reinterpret_cast<__half2*>(uch + (size_t)row * DINNER + d2) =
        __floats2half2_rn(a0 / (1.f + __expf(-a0)), a1 / (1.f + __expf(-a1)));

    float2 z = __half22float2(
        *reinterpret_cast<const __half2*>(up + (size_t)l * S + DINNER));
    *reinterpret_cast<__half2*>(gateh + (size_t)row * DINNER + d2) =
        __floats2half2_rn(z.x / (1.f + __expf(-z.x)), z.y / (1.f + __expf(-z.y)));
}

__global__ void reduce_split(const float* __restrict__ part,
                             float* __restrict__ out,
                             __half* __restrict__ outh, int n)
{
    int i = blockIdx.x * blockDim.x + threadIdx.x;
    if (i < n) {
        float s = 0.f;
#pragma unroll
        for (int z = 0; z < KSPLIT; ++z) s += part[(size_t)z * n + i];
        out[i]  = s;
        outh[i] = __float2half_rn(s);
    }
}

// ---------------------------------------------------------------------------
// Chunked selective scan, CHUNK=64 (32 chunks -> 2x occupancy),
// 2 channels/thread (128-thread blocks), __half2 IO.
// ---------------------------------------------------------------------------
__global__ __launch_bounds__(128)
void scan_p1(const __half* __restrict__ delta, const float* __restrict__ xdbl,
             const __half* __restrict__ uc, const float* __restrict__ A_log,
             float* __restrict__ hfin, float* __restrict__ sumd)
{
    const int b = blockIdx.z;
    const int c = blockIdx.y;
    const int d0 = blockIdx.x * 256 + threadIdx.x * 2;

    float na0[DSTATE], na1[DSTATE];
    const bool geo = load_na(A_log, d0, na0) & load_na(A_log, d0 + 1, na1);
    const float n00 = na0[0], n01 = na1[0];

    float h0[DSTATE], h1[DSTATE];
#pragma unroll
    for (int s = 0; s < DSTATE; ++s) { h0[s] = 0.f; h1[s] = 0.f; }
    float sd0 = 0.f, sd1 = 0.f;

    __shared__ float bs[32][DSTATE];

    const int lbeg = c * CHUNK;
    for (int l0 = lbeg; l0 < lbeg + CHUNK; l0 += 32) {
        __syncthreads();
        for (int t = threadIdx.x; t < 32 * DSTATE; t += 128) {
            int i = t >> 4, j = t & 15;
            bs[i][j] = xdbl[(size_t)(b * L_SEQ + l0 + i) * XPROJ_N + 64 + j];
        }
        __syncthreads();
        if (geo) {
#pragma unroll 2
            for (int i = 0; i < 32; ++i) {
                size_t row = (size_t)b * L_SEQ + l0 + i;
                float2 td = __half22float2(
                    *reinterpret_cast<const __half2*>(delta + row * DINNER + d0));
                float2 ud = __half22float2(
                    *reinterpret_cast<const __half2*>(uc + row * DINNER + d0));
                float tu0 = td.x * ud.x, tu1 = td.y * ud.y;
                sd0 += td.x; sd1 += td.y;
                float p0 = __expf(td.x * n00), p1 = __expf(td.y * n01);
                float q0 = p0 * p0, q1 = p1 * p1;
                float ra0 = p0, rb0 = q0, ra1 = p1, rb1 = q1;
                h0[0] = fmaf(ra0, h0[0], tu0 * bs[i][0]);
                h1[0] = fmaf(ra1, h1[0], tu1 * bs[i][0]);
                h0[1] = fmaf(rb0, h0[1], tu0 * bs[i][1]);
                h1[1] = fmaf(rb1, h1[1], tu1 * bs[i][1]);
#pragma unroll
                for (int s = 2; s < DSTATE; s += 2) {
                    ra0 *= q0; ra1 *= q1;
                    h0[s] = fmaf(ra0, h0[s], tu0 * bs[i][s]);
                    h1[s] = fmaf(ra1, h1[s], tu1 * bs[i][s]);
                    rb0 *= q0; rb1 *= q1;
                    h0[s+1] = fmaf(rb0, h0[s+1], tu0 * bs[i][s+1]);
                    h1[s+1] = fmaf(rb1, h1[s+1], tu1 * bs[i][s+1]);
                }
            }
        } else {
#pragma unroll 2
            for (int i = 0; i < 32; ++i) {
                size_t row = (size_t)b * L_SEQ + l0 + i;
                float2 td = __half22float2(
                    *reinterpret_cast<const __half2*>(delta + row * DINNER + d0));
                float2 ud = __half22float2(
                    *reinterpret_cast<const __half2*>(uc + row * DINNER + d0));
                float tu0 = td.x * ud.x, tu1 = td.y * ud.y;
                sd0 += td.x; sd1 += td.y;
#pragma unroll
                for (int s = 0; s < DSTATE; ++s) {
                    h0[s] = fmaf(__expf(td.x * na0[s]), h0[s], tu0 * bs[i][s]);
                    h1[s] = fmaf(__expf(td.y * na1[s]), h1[s], tu1 * bs[i][s]);
                }
            }
        }
    }

    const size_t base = ((size_t)(b * NCHUNK + c) * DSTATE) * DINNER + d0;
#pragma unroll
    for (int s = 0; s < DSTATE; ++s)
        *reinterpret_cast<float2*>(hfin + base + (size_t)s * DINNER) =
            make_float2(h0[s], h1[s]);
    *reinterpret_cast<float2*>(sumd + (size_t)(b * NCHUNK + c) * DINNER + d0) =
        make_float2(sd0, sd1);
}

__global__ __launch_bounds__(256)
void scan_combine(const float* __restrict__ hfin, const float* __restrict__ sumd,
                  const float* __restrict__ A_log, float* __restrict__ hini)
{
    const int b = blockIdx.y;
    const int d = blockIdx.x * 256 + threadIdx.x;

    float na[DSTATE];
    load_na(A_log, d, na);

    float h[DSTATE];
#pragma unroll
    for (int s = 0; s < DSTATE; ++s) h[s] = 0.f;

    for (int c = 0; c < NCHUNK; ++c) {
        const size_t base = ((size_t)(b * NCHUNK + c) * DSTATE) * DINNER + d;
#pragma unroll
        for (int s = 0; s < DSTATE; ++s)
            hini[base + (size_t)s * DINNER] = h[s];
        float sd = sumd[(size_t)(b * NCHUNK + c) * DINNER + d];
#pragma unroll
        for (int s = 0; s < DSTATE; ++s) {
            float pA = __expf(sd * na[s]);
            h[s] = fmaf(pA, h[s], hfin[base + (size_t)s * DINNER]);
        }
    }
}

__global__ __launch_bounds__(128)
void scan_p3(const __half* __restrict__ delta, const float* __restrict__ xdbl,
             const __half* __restrict__ uc, const __half* __restrict__ gateh,
             const float* __restrict__ A_log, const float* __restrict__ Dv,
             const float* __restrict__ hini, __half* __restrict__ yh)
{
    const int b = blockIdx.z;
    const int c = blockIdx.y;
    const int d0 = blockIdx.x * 256 + threadIdx.x * 2;

    float na0[DSTATE], na1[DSTATE];
    const bool geo = load_na(A_log, d0, na0) & load_na(A_log, d0 + 1, na1);
    const float n00 = na0[0], n01 = na1[0];

    float h0[DSTATE], h1[DSTATE];
    {
        const size_t base = ((size_t)(b * NCHUNK + c) * DSTATE) * DINNER + d0;
#pragma unroll
        for (int s = 0; s < DSTATE; ++s) {
            float2 hv = *reinterpret_cast<const float2*>(
                hini + base + (size_t)s * DINNER);
            h0[s] = hv.x; h1[s] = hv.y;
        }
    }

    const float2 Dd = *reinterpret_cast<const float2*>(Dv + d0);
    __shared__ float bc[32][32];

    const int lbeg = c * CHUNK;
    for (int l0 = lbeg; l0 < lbeg + CHUNK; l0 += 32) {
        __syncthreads();
        for (int t = threadIdx.x; t < 1024; t += 128) {
            int i = t >> 5, j = t & 31;
            bc[i][j] = xdbl[(size_t)(b * L_SEQ + l0 + i) * XPROJ_N + 64 + j];
        }
        __syncthreads();
        if (geo) {
#pragma unroll 2
            for (int i = 0; i < 32; ++i) {
                size_t row = (size_t)b * L_SEQ + l0 + i;
                float2 td = __half22float2(
                    *reinterpret_cast<const __half2*>(delta + row * DINNER + d0));
                float2 ud = __half22float2(
                    *reinterpret_cast<const __half2*>(uc + row * DINNER + d0));
                float tu0 = td.x * ud.x, tu1 = td.y * ud.y;
                float yv0 = 0.f, yv1 = 0.f;
                float p0 = __expf(td.x * n00), p1 = __expf(td.y * n01);
                float q0 = p0 * p0, q1 = p1 * p1;
                float ra0 = p0, rb0 = q0, ra1 = p1, rb1 = q1;
                h0[0] = fmaf(ra0, h0[0], tu0 * bc[i][0]);
                h1[0] = fmaf(ra1, h1[0], tu1 * bc[i][0]);
                yv0 = fmaf(h0[0], bc[i][16], yv0);
                yv1 = fmaf(h1[0], bc[i][16], yv1);
                h0[1] = fmaf(rb0, h0[1], tu0 * bc[i][1]);
                h1[1] = fmaf(rb1, h1[1], tu1 * bc[i][1]);
                yv0 = fmaf(h0[1], bc[i][17], yv0);
                yv1 = fmaf(h1[1], bc[i][17], yv1);
#pragma unroll
                for (int s = 2; s < DSTATE; s += 2) {
                    ra0 *= q0; ra1 *= q1;
                    h0[s] = fmaf(ra0, h0[s], tu0 * bc[i][s]);
                    h1[s] = fmaf(ra1, h1[s], tu1 * bc[i][s]);
                    yv0 = fmaf(h0[s], bc[i][16 + s], yv0);
                    yv1 = fmaf(h1[s], bc[i][16 + s], yv1);
                    rb0 *= q0; rb1 *= q1;
                    h0[s+1] = fmaf(rb0, h0[s+1], tu0 * bc[i][s+1]);
                    h1[s+1] = fmaf(rb1, h1[s+1], tu1 * bc[i][s+1]);
                    yv0 = fmaf(h0[s+1], bc[i][17 + s], yv0);
                    yv1 = fmaf(h1[s+1], bc[i][17 + s], yv1);
                }
                float2 g = __half22float2(
                    *reinterpret_cast<const __half2*>(gateh + row * DINNER + d0));
                *reinterpret_cast<__half2*>(yh + row * DINNER + d0) =
                    __floats2half2_rn((yv0 + ud.x * Dd.x) * g.x,
                                      (yv1 + ud.y * Dd.y) * g.y);
            }
        } else {
#pragma unroll 2
            for (int i = 0; i < 32; ++i) {
                size_t row = (size_t)b * L_SEQ + l0 + i;
                float2 td = __half22float2(
                    *reinterpret_cast<const __half2*>(delta + row * DINNER + d0));
                float2 ud = __half22float2(
                    *reinterpret_cast<const __half2*>(uc + row * DINNER + d0));
                float tu0 = td.x * ud.x, tu1 = td.y * ud.y;
                float yv0 = 0.f, yv1 = 0.f;
#pragma unroll
                for (int s = 0; s < DSTATE; ++s) {
                    h0[s] = fmaf(__expf(td.x * na0[s]), h0[s], tu0 * bc[i][s]);
                    h1[s] = fmaf(__expf(td.y * na1[s]), h1[s], tu1 * bc[i][s]);
                    yv0 = fmaf(h0[s], bc[i][16 + s], yv0);
                    yv1 = fmaf(h1[s], bc[i][16 + s], yv1);
                }
                float2 g = __half22float2(
                    *reinterpret_cast<const __half2*>(gateh + row * DINNER + d0));
                *reinterpret_cast<__half2*>(yh + row * DINNER + d0) =
                    __floats2half2_rn((yv0 + ud.x * Dd.x) * g.x,
                                      (yv1 + ud.y * Dd.y) * g.y);
            }
        }
    }
}

// ---------------------------------------------------------------------------
extern "C" void kernel_launch(void* const* d_in, const int* in_sizes, int n_in,
                              void* d_out, int out_size)
{
    const float* x        = (const float*)d_in[0];
    const float* W_in     = (const float*)d_in[1];
    const float* conv_w   = (const float*)d_in[2];
    const float* conv_b   = (const float*)d_in[3];
    const float* W_xproj  = (const float*)d_in[4];
    const float* W_dtproj = (const float*)d_in[5];
    const float* dt_bias  = (const float*)d_in[6];
    const float* A_log    = (const float*)d_in[7];
    const float* Dv       = (const float*)d_in[8];
    const float* W_out    = (const float*)d_in[9];
    float* out = (float*)d_out;

    float *xpart, *xdbl, *hfin, *hini, *sumd;
    __half *xzh, *xh, *whin, *whxp, *whdt, *whout, *uch, *gateh, *xdblh, *deltah, *yh;
    cudaGetSymbolAddress((void**)&xpart,  g_xpart);
    cudaGetSymbolAddress((void**)&xdbl,   g_xdbl);
    cudaGetSymbolAddress((void**)&hfin,   g_hfin);
    cudaGetSymbolAddress((void**)&hini,   g_hini);
    cudaGetSymbolAddress((void**)&sumd,   g_sumd);
    cudaGetSymbolAddress((void**)&xzh,    g_xzh);
    cudaGetSymbolAddress((void**)&xh,     g_xh);
    cudaGetSymbolAddress((void**)&whin,   g_whin);
    cudaGetSymbolAddress((void**)&whxp,   g_whxp);
    cudaGetSymbolAddress((void**)&whdt,   g_whdt);
    cudaGetSymbolAddress((void**)&whout,  g_whout);
    cudaGetSymbolAddress((void**)&uch,    g_uch);
    cudaGetSymbolAddress((void**)&gateh,  g_gateh);
    cudaGetSymbolAddress((void**)&xdblh,  g_xdblh);
    cudaGetSymbolAddress((void**)&deltah, g_deltah);
    cudaGetSymbolAddress((void**)&yh,     g_yh);

    cudaFuncSetAttribute(mma_tn<0>,
        cudaFuncAttributeMaxDynamicSharedMemorySize, MMA_SMEM_BYTES);
    cudaFuncSetAttribute(mma_tn<1>,
        cudaFuncAttributeMaxDynamicSharedMemorySize, MMA_SMEM_BYTES);
    cudaFuncSetAttribute(mma_tn<2>,
        cudaFuncAttributeMaxDynamicSharedMemorySize, MMA_SMEM_BYTES);

    dim3 blk(256);

    // 0. convert x + all weights to fp16
    f2h_multi<<<dim3(2048, 5), blk>>>(
        x,        xh,    NROWS * DMODEL,
        W_in,     whin,  2 * DINNER * DMODEL,
        W_xproj,  whxp,  XPROJ_N * DINNER,
        W_dtproj, whdt,  DINNER * 64,
        W_out,    whout, DMODEL * DINNER);

    // 1. in_proj: xz[4096,4096] fp16 = x @ W_in^T  (K=1024)
    mma_tn<2><<<dim3(64, 32, 1), blk, MMA_SMEM_BYTES>>>(xh, whin, xzh,
        NROWS, 2 * DINNER, DMODEL, DMODEL, DMODEL, 2 * DINNER,
        nullptr, DMODEL);

    // 2. depthwise conv + silu + gate (half2 vectorized)
    conv_silu_k<<<(NROWS * DINNER / 2) / 256, blk>>>(xzh, conv_w, conv_b,
                                                     uch, gateh);

    // 3. x_proj (split-K x8)
    mma_tn<0><<<dim3(2, 32, KSPLIT), blk, MMA_SMEM_BYTES>>>(uch, whxp, xpart,
        NROWS, XPROJ_N, DINNER, DINNER, DINNER, XPROJ_N,
        nullptr, DINNER / KSPLIT);
    reduce_split<<<(NROWS * XPROJ_N + 255) / 256, blk>>>(
        xpart, xdbl, xdblh, NROWS * XPROJ_N);

    // 4. dt_proj + softplus -> fp16 delta (K=64)
    mma_tn<1><<<dim3(32, 32, 1), blk, MMA_SMEM_BYTES>>>(xdblh, whdt, deltah,
        NROWS, DINNER, 64, XPROJ_N, 64, DINNER,
        dt_bias, 64);

    // 5. chunked selective scan (CHUNK=64, 2 channels/thread)
    scan_p1<<<dim3(DINNER / 256, NCHUNK, NB), dim3(128)>>>(
        deltah, xdbl, uch, A_log, hfin, sumd);
    scan_combine<<<dim3(DINNER / 256, NB), blk>>>(hfin, sumd, A_log, hini);
    scan_p3<<<dim3(DINNER / 256, NCHUNK, NB), dim3(128)>>>(
        deltah, xdbl, uch, gateh, A_log, Dv, hini, yh);

    // 6. out_proj: out[4096,1024] = y @ W_out^T (K=2048)
    mma_tn<0><<<dim3(16, 32, 1), blk, MMA_SMEM_BYTES>>>(yh, whout, out,
        NROWS, DMODEL, DINNER, DINNER, DINNER, DMODEL,
        nullptr, DINNER);
}